// round 1
// baseline (speedup 1.0000x reference)
#include <cuda_runtime.h>
#include <cuda_bf16.h>
#include <math.h>

// Problem constants
#define B 8
#define T 1024
#define C 1024
#define H 16
#define D 64

// Scratch for Q/K/V projections: [B][H][T][D] each = 32 MB each
__device__ float g_q[(size_t)B * H * T * D];
__device__ float g_k[(size_t)B * H * T * D];
__device__ float g_v[(size_t)B * H * T * D];

// ---------------------------------------------------------------------------
// Kernel 1: QKV projection GEMMs.
// For each (head h, matrix w in {Q,K,V}): out[m, d] = sum_c x[m, c] * W[h][c][d]
// with m = b*T + t (x is [B*T, C] contiguous), M = 8192, K = 1024, N = 64.
// Tile: BM=128, BN=64, BK=16; 256 threads; 8x4 micro-tile per thread.
// ---------------------------------------------------------------------------
#define BM 128
#define BN 64
#define BK 16

__global__ __launch_bounds__(256) void qkv_gemm_kernel(
    const float* __restrict__ x,
    const float* __restrict__ Wq,
    const float* __restrict__ Wk,
    const float* __restrict__ Wv)
{
    const int tile_m = blockIdx.x;      // 0..63
    const int h      = blockIdx.y;      // 0..15
    const int which  = blockIdx.z;      // 0:Q 1:K 2:V

    const float* W = (which == 0) ? Wq : (which == 1) ? Wk : Wv;
    float* out     = (which == 0) ? g_q : (which == 1) ? g_k : g_v;
    W += (size_t)h * C * D;             // [C][D] slice for this head

    __shared__ float As[BK][BM];        // A tile, k-major (transposed on load)
    __shared__ float Bs[BK][BN];        // B tile

    const int tid = threadIdx.x;        // 0..255
    const int tx  = tid & 15;           // col group (4 cols each)
    const int ty  = tid >> 4;           // row group (8 rows each)

    float acc[8][4];
    #pragma unroll
    for (int i = 0; i < 8; i++)
        #pragma unroll
        for (int j = 0; j < 4; j++)
            acc[i][j] = 0.0f;

    const int m0 = tile_m * BM;

    for (int k0 = 0; k0 < C; k0 += BK) {
        // Load A tile: 128 rows x 16 cols = 512 float4, 2 per thread.
        #pragma unroll
        for (int i = 0; i < 2; i++) {
            int idx = tid * 2 + i;
            int r   = idx >> 2;             // 0..127
            int c4  = (idx & 3) * 4;        // 0,4,8,12
            float4 v = *(const float4*)(x + (size_t)(m0 + r) * C + k0 + c4);
            As[c4 + 0][r] = v.x;
            As[c4 + 1][r] = v.y;
            As[c4 + 2][r] = v.z;
            As[c4 + 3][r] = v.w;
        }
        // Load B tile: 16 rows x 64 cols = 256 float4, 1 per thread.
        {
            int r  = tid >> 4;              // 0..15
            int c4 = (tid & 15) * 4;        // 0..60
            float4 v = *(const float4*)(W + (size_t)(k0 + r) * D + c4);
            *(float4*)&Bs[r][c4] = v;
        }
        __syncthreads();

        #pragma unroll
        for (int kk = 0; kk < BK; kk++) {
            float4 a0 = *(const float4*)&As[kk][ty * 8];
            float4 a1 = *(const float4*)&As[kk][ty * 8 + 4];
            float4 bb = *(const float4*)&Bs[kk][tx * 4];
            float a[8] = {a0.x, a0.y, a0.z, a0.w, a1.x, a1.y, a1.z, a1.w};
            float b[4] = {bb.x, bb.y, bb.z, bb.w};
            #pragma unroll
            for (int i = 0; i < 8; i++)
                #pragma unroll
                for (int j = 0; j < 4; j++)
                    acc[i][j] = fmaf(a[i], b[j], acc[i][j]);
        }
        __syncthreads();
    }

    // Store to [B][H][T][D] layout. m = b*T + t.
    #pragma unroll
    for (int i = 0; i < 8; i++) {
        int m = m0 + ty * 8 + i;
        int bb = m >> 10;                   // / T
        int t  = m & 1023;                  // % T
        float* dst = out + (((size_t)(bb * H + h) * T + t) * D) + tx * 4;
        *(float4*)dst = make_float4(acc[i][0], acc[i][1], acc[i][2], acc[i][3]);
    }
}

// ---------------------------------------------------------------------------
// Kernel 2: causal FlashAttention, fp32.
// One CTA = 128 query rows of one (b, h). One thread = one query row.
// q[64] and acc[64] live in registers; K/V tiles (32 x 64) in SMEM,
// broadcast-read by all threads (conflict-free). Per-tile online softmax.
// ---------------------------------------------------------------------------
#define BR 128
#define BC 32

__global__ __launch_bounds__(128) void flash_attn_kernel(float* __restrict__ out)
{
    const int qt  = blockIdx.x;         // 0..7  (query tile)
    const int h   = blockIdx.y;         // 0..15
    const int b   = blockIdx.z;         // 0..7
    const int tid = threadIdx.x;        // 0..127
    const int t   = qt * BR + tid;      // this thread's query row

    const size_t head_base = ((size_t)(b * H + h) * T) * D;

    // Load q row into registers
    float q[D];
    {
        const float* qptr = g_q + head_base + (size_t)t * D;
        #pragma unroll
        for (int d = 0; d < D; d += 4) {
            float4 v = *(const float4*)(qptr + d);
            q[d] = v.x; q[d + 1] = v.y; q[d + 2] = v.z; q[d + 3] = v.w;
        }
    }

    __shared__ float Ks[BC][D];
    __shared__ float Vs[BC][D];

    float acc[D];
    #pragma unroll
    for (int d = 0; d < D; d++) acc[d] = 0.0f;
    float m = -1e30f;
    float l = 0.0f;

    const int kmax = qt * BR + BR;      // keys strictly below this are needed

    for (int k0 = 0; k0 < kmax; k0 += BC) {
        // Load K and V tiles: 32x64 floats = 512 float4 each; 4 per thread.
        const float* kbase = g_k + head_base + (size_t)k0 * D;
        const float* vbase = g_v + head_base + (size_t)k0 * D;
        #pragma unroll
        for (int i = 0; i < 4; i++) {
            int idx = i * 128 + tid;        // 0..511
            int r   = idx >> 4;             // 0..31
            int c   = (idx & 15) * 4;       // 0..60
            *(float4*)&Ks[r][c] = *(const float4*)(kbase + (size_t)r * D + c);
            *(float4*)&Vs[r][c] = *(const float4*)(vbase + (size_t)r * D + c);
        }
        __syncthreads();

        // Scores for this tile
        float s[BC];
        float mtile = -1e30f;
        #pragma unroll
        for (int j = 0; j < BC; j++) {
            float dot = 0.0f;
            #pragma unroll
            for (int d = 0; d < D; d += 4) {
                float4 kv = *(const float4*)&Ks[j][d];
                dot = fmaf(q[d], kv.x, dot);
                dot = fmaf(q[d + 1], kv.y, dot);
                dot = fmaf(q[d + 2], kv.z, dot);
                dot = fmaf(q[d + 3], kv.w, dot);
            }
            float sv = ((k0 + j) <= t) ? dot * 0.125f : -1e30f;
            s[j] = sv;
            mtile = fmaxf(mtile, sv);
        }

        // Online softmax update (one rescale per tile)
        float mnew = fmaxf(m, mtile);
        float corr = __expf(m - mnew);
        l *= corr;
        #pragma unroll
        for (int d = 0; d < D; d++) acc[d] *= corr;

        #pragma unroll
        for (int j = 0; j < BC; j++) {
            float p = __expf(s[j] - mnew);
            l += p;
            #pragma unroll
            for (int d = 0; d < D; d += 4) {
                float4 vv = *(const float4*)&Vs[j][d];
                acc[d]     = fmaf(p, vv.x, acc[d]);
                acc[d + 1] = fmaf(p, vv.y, acc[d + 1]);
                acc[d + 2] = fmaf(p, vv.z, acc[d + 2]);
                acc[d + 3] = fmaf(p, vv.w, acc[d + 3]);
            }
        }
        m = mnew;
        __syncthreads();
    }

    // Write output: out[b][t][h*D + d]
    const float inv = 1.0f / l;
    float* optr = out + ((size_t)(b * T + t) * (H * D)) + h * D;
    #pragma unroll
    for (int d = 0; d < D; d += 4) {
        *(float4*)(optr + d) =
            make_float4(acc[d] * inv, acc[d + 1] * inv, acc[d + 2] * inv, acc[d + 3] * inv);
    }
}

// ---------------------------------------------------------------------------
extern "C" void kernel_launch(void* const* d_in, const int* in_sizes, int n_in,
                              void* d_out, int out_size)
{
    const float* x  = (const float*)d_in[0];   // [B, T, C]
    const float* Wq = (const float*)d_in[1];   // [H, C, D]
    const float* Wk = (const float*)d_in[2];
    const float* Wv = (const float*)d_in[3];
    float* out = (float*)d_out;                 // [B, T, H*D]

    (void)in_sizes; (void)n_in; (void)out_size;

    dim3 gemm_grid(T * B / BM, H, 3);           // 64 x 16 x 3
    qkv_gemm_kernel<<<gemm_grid, 256>>>(x, Wq, Wk, Wv);

    dim3 attn_grid(T / BR, H, B);               // 8 x 16 x 8
    flash_attn_kernel<<<attn_grid, 128>>>(out);
}

// round 3
// speedup vs baseline: 1.1982x; 1.1982x over previous
#include <cuda_runtime.h>
#include <cuda_bf16.h>
#include <math.h>
#include <stdint.h>

// Problem constants
#define B 8
#define T 1024
#define C 1024
#define H 16
#define D 64

// Scratch for Q/K/V projections: [B][H][T][D] each
__device__ float g_q[(size_t)B * H * T * D];
__device__ float g_k[(size_t)B * H * T * D];
__device__ float g_v[(size_t)B * H * T * D];

// ===========================================================================
// Helpers
// ===========================================================================
__device__ __forceinline__ uint32_t smem_u32(const void* p) {
    uint32_t a;
    asm("{ .reg .u64 t; cvta.to.shared.u64 t, %1; cvt.u32.u64 %0, t; }"
        : "=r"(a) : "l"(p));
    return a;
}

#define LDMX4(r0, r1, r2, r3, addr)                                           \
    asm volatile("ldmatrix.sync.aligned.m8n8.x4.shared.b16 {%0,%1,%2,%3}, [%4];" \
                 : "=r"(r0), "=r"(r1), "=r"(r2), "=r"(r3) : "r"(addr))

#define MMA_BF16(c, a0, a1, a2, a3, b0, b1)                                   \
    asm volatile("mma.sync.aligned.m16n8k16.row.col.f32.bf16.bf16.f32 "       \
                 "{%0,%1,%2,%3}, {%4,%5,%6,%7}, {%8,%9}, {%0,%1,%2,%3};"      \
                 : "+f"((c)[0]), "+f"((c)[1]), "+f"((c)[2]), "+f"((c)[3])     \
                 : "r"(a0), "r"(a1), "r"(a2), "r"(a3), "r"(b0), "r"(b1))

__device__ __forceinline__ uint32_t pack_bf16(float a, float b) {
    __nv_bfloat16 ha = __float2bfloat16_rn(a);
    __nv_bfloat16 hb = __float2bfloat16_rn(b);
    return (uint32_t)__bfloat16_as_ushort(ha) |
           ((uint32_t)__bfloat16_as_ushort(hb) << 16);
}

__device__ __forceinline__ void bf16_split(float v, __nv_bfloat16& hi, __nv_bfloat16& lo) {
    hi = __float2bfloat16_rn(v);
    lo = __float2bfloat16_rn(v - __bfloat162float(hi));
}

// ===========================================================================
// Kernel 1: QKV projections, bf16x3 split on mma.sync (legacy HMMA path —
// tcgen05 is unavailable: harness PTX target is sm_103 without the 'a' feature).
// One CTA = 128-row M tile x one head, computing Q, K, V (acc in registers).
// SMEM tiles: A (x) 128x32 split hi/lo, B (W^T, [n][k]) 64x32 x 3 mats x hi/lo.
// Rows padded to 80B -> ldmatrix conflict-free. Double buffered.
// ===========================================================================
#define BK 32                     // K per chunk
#define NCHUNK (C / BK)           // 32
#define RSTRIDE 80                // bytes per 32-halfs row (padded)
#define ABYTES (128 * RSTRIDE)    // 10240 per term
#define BBYTES (64 * RSTRIDE)     // 5120 per term per mat
#define BUFBYTES (2 * ABYTES + 3 * 2 * BBYTES)   // 51200
#define QKV_SMEM (2 * BUFBYTES)                  // 102400

#define A_OFF(buf, term)       ((buf) * BUFBYTES + (term) * ABYTES)
#define B_OFF(buf, mat, term)  ((buf) * BUFBYTES + 2 * ABYTES + (mat) * 2 * BBYTES + (term) * BBYTES)

__global__ __launch_bounds__(256)
void qkv_bf16x3_kernel(const float* __restrict__ x,
                       const float* __restrict__ Wq,
                       const float* __restrict__ Wk,
                       const float* __restrict__ Wv)
{
    extern __shared__ char sm[];
    const uint32_t sbase = smem_u32(sm);

    const int tid  = threadIdx.x;
    const int warp = tid >> 5;
    const int lane = tid & 31;
    const int wm   = warp >> 1;           // 0..3 -> rows [wm*32, +32)
    const int wn   = warp & 1;            // 0..1 -> cols [wn*32, +32)

    const int m0 = blockIdx.x * 128;
    const int h  = blockIdx.y;

    const float* Ws0 = Wq + (size_t)h * C * D;
    const float* Ws1 = Wk + (size_t)h * C * D;
    const float* Ws2 = Wv + (size_t)h * C * D;

    float acc[3][2][4][4];
    #pragma unroll
    for (int m = 0; m < 3; m++)
        #pragma unroll
        for (int i = 0; i < 2; i++)
            #pragma unroll
            for (int j = 0; j < 4; j++)
                #pragma unroll
                for (int k = 0; k < 4; k++)
                    acc[m][i][j][k] = 0.0f;

    // Staging registers for the prefetched chunk
    float4 sA[4];
    float4 sB[3][2];

    // ---- chunk load (gmem -> regs) ----
    auto ldg_chunk = [&](int ci) {
        const int k0 = ci * BK;
        #pragma unroll
        for (int it = 0; it < 4; it++) {
            int idx = tid + it * 256;                 // 0..1023
            int r   = idx >> 3;                       // 0..127
            int c4  = (idx & 7) * 4;                  // 0..28
            sA[it] = *(const float4*)(x + (size_t)(m0 + r) * C + k0 + c4);
        }
        #pragma unroll
        for (int it = 0; it < 2; it++) {
            int idx = tid + it * 256;                 // 0..511
            int k   = idx >> 4;                       // 0..31
            int n4  = (idx & 15) * 4;                 // 0..60
            size_t off = (size_t)(k0 + k) * D + n4;
            sB[0][it] = *(const float4*)(Ws0 + off);
            sB[1][it] = *(const float4*)(Ws1 + off);
            sB[2][it] = *(const float4*)(Ws2 + off);
        }
    };

    // ---- chunk store (regs -> smem, bf16 split) ----
    auto sts_chunk = [&](int ci) {
        const int buf = ci & 1;
        #pragma unroll
        for (int it = 0; it < 4; it++) {
            int idx = tid + it * 256;
            int r   = idx >> 3;
            int c4  = (idx & 7) * 4;
            float4 v = sA[it];
            __nv_bfloat16 hx, lx, hy, ly, hz, lz, hw, lw;
            bf16_split(v.x, hx, lx); bf16_split(v.y, hy, ly);
            bf16_split(v.z, hz, lz); bf16_split(v.w, hw, lw);
            uint32_t off = r * RSTRIDE + c4 * 2;
            *(uint2*)(sm + A_OFF(buf, 0) + off) = make_uint2(
                (uint32_t)__bfloat16_as_ushort(hx) | ((uint32_t)__bfloat16_as_ushort(hy) << 16),
                (uint32_t)__bfloat16_as_ushort(hz) | ((uint32_t)__bfloat16_as_ushort(hw) << 16));
            *(uint2*)(sm + A_OFF(buf, 1) + off) = make_uint2(
                (uint32_t)__bfloat16_as_ushort(lx) | ((uint32_t)__bfloat16_as_ushort(ly) << 16),
                (uint32_t)__bfloat16_as_ushort(lz) | ((uint32_t)__bfloat16_as_ushort(lw) << 16));
        }
        #pragma unroll
        for (int mat = 0; mat < 3; mat++) {
            #pragma unroll
            for (int it = 0; it < 2; it++) {
                int idx = tid + it * 256;
                int k   = idx >> 4;
                int n4  = (idx & 15) * 4;
                float4 v = sB[mat][it];
                float vv[4] = { v.x, v.y, v.z, v.w };
                #pragma unroll
                for (int j = 0; j < 4; j++) {
                    __nv_bfloat16 hi, lo;
                    bf16_split(vv[j], hi, lo);
                    uint32_t off = (n4 + j) * RSTRIDE + k * 2;
                    *(__nv_bfloat16*)(sm + B_OFF(buf, mat, 0) + off) = hi;
                    *(__nv_bfloat16*)(sm + B_OFF(buf, mat, 1) + off) = lo;
                }
            }
        }
    };

    ldg_chunk(0);
    sts_chunk(0);
    __syncthreads();

    for (int ci = 0; ci < NCHUNK; ci++) {
        const int buf = ci & 1;

        if (ci + 1 < NCHUNK) ldg_chunk(ci + 1);

        // ---- load A fragments (both terms), all ksteps ----
        uint32_t ah[2][2][4], al[2][2][4];        // [mf][ks][4]
        {
            const uint32_t abh = sbase + A_OFF(buf, 0);
            const uint32_t abl = sbase + A_OFF(buf, 1);
            #pragma unroll
            for (int mf = 0; mf < 2; mf++) {
                #pragma unroll
                for (int ks = 0; ks < 2; ks++) {
                    int row = wm * 32 + mf * 16 + (lane & 15);
                    int col = ks * 32 + ((lane & 16) ? 16 : 0);
                    uint32_t ao = row * RSTRIDE + col;
                    LDMX4(ah[mf][ks][0], ah[mf][ks][1], ah[mf][ks][2], ah[mf][ks][3], abh + ao);
                    LDMX4(al[mf][ks][0], al[mf][ks][1], al[mf][ks][2], al[mf][ks][3], abl + ao);
                }
            }
        }

        // ---- per matrix: load B frags, issue mma ----
        #pragma unroll
        for (int mat = 0; mat < 3; mat++) {
            const uint32_t bbh = sbase + B_OFF(buf, mat, 0);
            const uint32_t bbl = sbase + B_OFF(buf, mat, 1);
            #pragma unroll
            for (int ks = 0; ks < 2; ks++) {
                uint32_t bh[2][4], bl[2][4];       // [nf16][4]
                #pragma unroll
                for (int nf16 = 0; nf16 < 2; nf16++) {
                    int row = wn * 32 + nf16 * 16 + (lane & 7) + ((lane & 16) ? 8 : 0);
                    int col = ks * 32 + ((lane & 8) ? 16 : 0);
                    uint32_t bo = row * RSTRIDE + col;
                    LDMX4(bh[nf16][0], bh[nf16][1], bh[nf16][2], bh[nf16][3], bbh + bo);
                    LDMX4(bl[nf16][0], bl[nf16][1], bl[nf16][2], bl[nf16][3], bbl + bo);
                }
                #pragma unroll
                for (int mf = 0; mf < 2; mf++) {
                    #pragma unroll
                    for (int nf16 = 0; nf16 < 2; nf16++) {
                        #pragma unroll
                        for (int hf = 0; hf < 2; hf++) {
                            float* c = acc[mat][mf][nf16 * 2 + hf];
                            MMA_BF16(c, ah[mf][ks][0], ah[mf][ks][1], ah[mf][ks][2], ah[mf][ks][3],
                                     bh[nf16][hf * 2], bh[nf16][hf * 2 + 1]);
                            MMA_BF16(c, al[mf][ks][0], al[mf][ks][1], al[mf][ks][2], al[mf][ks][3],
                                     bh[nf16][hf * 2], bh[nf16][hf * 2 + 1]);
                            MMA_BF16(c, ah[mf][ks][0], ah[mf][ks][1], ah[mf][ks][2], ah[mf][ks][3],
                                     bl[nf16][hf * 2], bl[nf16][hf * 2 + 1]);
                        }
                    }
                }
            }
        }

        if (ci + 1 < NCHUNK) sts_chunk(ci + 1);
        __syncthreads();
    }

    // ---- epilogue: accumulators -> g_q/g_k/g_v ([B][H][T][D]) ----
    const int bb = m0 >> 10;                 // batch (M tiles never straddle T)
    #pragma unroll
    for (int mat = 0; mat < 3; mat++) {
        float* g = (mat == 0) ? g_q : (mat == 1) ? g_k : g_v;
        #pragma unroll
        for (int mf = 0; mf < 2; mf++) {
            #pragma unroll
            for (int nf = 0; nf < 4; nf++) {
                const float* c = acc[mat][mf][nf];
                int row  = wm * 32 + mf * 16 + (lane >> 2);
                int colg = wn * 32 + nf * 8 + (lane & 3) * 2;
                int t    = (m0 + row) & 1023;
                float* dst = g + (((size_t)(bb * H + h) * T + t) * D) + colg;
                *(float2*)dst = make_float2(c[0], c[1]);
                *(float2*)(dst + 8 * D) = make_float2(c[2], c[3]);
            }
        }
    }
}

// ===========================================================================
// Kernel 2: causal FlashAttention, fp32 (unchanged — known passing, 974us)
// ===========================================================================
#define BR 128
#define BC 32

__global__ __launch_bounds__(128) void flash_attn_kernel(float* __restrict__ out)
{
    const int qt  = blockIdx.x;
    const int h   = blockIdx.y;
    const int b   = blockIdx.z;
    const int tid = threadIdx.x;
    const int t   = qt * BR + tid;

    const size_t head_base = ((size_t)(b * H + h) * T) * D;

    float q[D];
    {
        const float* qptr = g_q + head_base + (size_t)t * D;
        #pragma unroll
        for (int d = 0; d < D; d += 4) {
            float4 v = *(const float4*)(qptr + d);
            q[d] = v.x; q[d + 1] = v.y; q[d + 2] = v.z; q[d + 3] = v.w;
        }
    }

    __shared__ float Ks[BC][D];
    __shared__ float Vs[BC][D];

    float acc[D];
    #pragma unroll
    for (int d = 0; d < D; d++) acc[d] = 0.0f;
    float m = -1e30f;
    float l = 0.0f;

    const int kmax = qt * BR + BR;

    for (int k0 = 0; k0 < kmax; k0 += BC) {
        const float* kbase = g_k + head_base + (size_t)k0 * D;
        const float* vbase = g_v + head_base + (size_t)k0 * D;
        #pragma unroll
        for (int i = 0; i < 4; i++) {
            int idx = i * 128 + tid;
            int r   = idx >> 4;
            int c   = (idx & 15) * 4;
            *(float4*)&Ks[r][c] = *(const float4*)(kbase + (size_t)r * D + c);
            *(float4*)&Vs[r][c] = *(const float4*)(vbase + (size_t)r * D + c);
        }
        __syncthreads();

        float s[BC];
        float mtile = -1e30f;
        #pragma unroll
        for (int j = 0; j < BC; j++) {
            float dot = 0.0f;
            #pragma unroll
            for (int d = 0; d < D; d += 4) {
                float4 kv = *(const float4*)&Ks[j][d];
                dot = fmaf(q[d], kv.x, dot);
                dot = fmaf(q[d + 1], kv.y, dot);
                dot = fmaf(q[d + 2], kv.z, dot);
                dot = fmaf(q[d + 3], kv.w, dot);
            }
            float sv = ((k0 + j) <= t) ? dot * 0.125f : -1e30f;
            s[j] = sv;
            mtile = fmaxf(mtile, sv);
        }

        float mnew = fmaxf(m, mtile);
        float corr = __expf(m - mnew);
        l *= corr;
        #pragma unroll
        for (int d = 0; d < D; d++) acc[d] *= corr;

        #pragma unroll
        for (int j = 0; j < BC; j++) {
            float p = __expf(s[j] - mnew);
            l += p;
            #pragma unroll
            for (int d = 0; d < D; d += 4) {
                float4 vv = *(const float4*)&Vs[j][d];
                acc[d]     = fmaf(p, vv.x, acc[d]);
                acc[d + 1] = fmaf(p, vv.y, acc[d + 1]);
                acc[d + 2] = fmaf(p, vv.z, acc[d + 2]);
                acc[d + 3] = fmaf(p, vv.w, acc[d + 3]);
            }
        }
        m = mnew;
        __syncthreads();
    }

    const float inv = 1.0f / l;
    float* optr = out + ((size_t)(b * T + t) * (H * D)) + h * D;
    #pragma unroll
    for (int d = 0; d < D; d += 4) {
        *(float4*)(optr + d) =
            make_float4(acc[d] * inv, acc[d + 1] * inv, acc[d + 2] * inv, acc[d + 3] * inv);
    }
}

// ===========================================================================
extern "C" void kernel_launch(void* const* d_in, const int* in_sizes, int n_in,
                              void* d_out, int out_size)
{
    const float* x  = (const float*)d_in[0];   // [B, T, C]
    const float* Wq = (const float*)d_in[1];   // [H, C, D]
    const float* Wk = (const float*)d_in[2];
    const float* Wv = (const float*)d_in[3];
    float* out = (float*)d_out;                 // [B, T, H*D]

    (void)in_sizes; (void)n_in; (void)out_size;

    static int smem_set = 0;
    if (!smem_set) {
        cudaFuncSetAttribute(qkv_bf16x3_kernel,
                             cudaFuncAttributeMaxDynamicSharedMemorySize, QKV_SMEM);
        smem_set = 1;
    }

    dim3 gemm_grid(T * B / 128, H);             // 64 x 16
    qkv_bf16x3_kernel<<<gemm_grid, 256, QKV_SMEM>>>(x, Wq, Wk, Wv);

    dim3 attn_grid(T / BR, H, B);               // 8 x 16 x 8
    flash_attn_kernel<<<attn_grid, 128>>>(out);
}

// round 4
// speedup vs baseline: 2.0811x; 1.7369x over previous
#include <cuda_runtime.h>
#include <cuda_bf16.h>
#include <math.h>
#include <stdint.h>

// Problem constants
#define B 8
#define T 1024
#define C 1024
#define H 16
#define D 64

// Scratch for Q/K/V projections: [B][H][T][D] each
__device__ float g_q[(size_t)B * H * T * D];
__device__ float g_k[(size_t)B * H * T * D];
__device__ float g_v[(size_t)B * H * T * D];

// ===========================================================================
// Helpers
// ===========================================================================
__device__ __forceinline__ uint32_t smem_u32(const void* p) {
    uint32_t a;
    asm("{ .reg .u64 t; cvta.to.shared.u64 t, %1; cvt.u32.u64 %0, t; }"
        : "=r"(a) : "l"(p));
    return a;
}

#define LDMX4(r0, r1, r2, r3, addr)                                           \
    asm volatile("ldmatrix.sync.aligned.m8n8.x4.shared.b16 {%0,%1,%2,%3}, [%4];" \
                 : "=r"(r0), "=r"(r1), "=r"(r2), "=r"(r3) : "r"(addr))

#define LDMX4T(r0, r1, r2, r3, addr)                                          \
    asm volatile("ldmatrix.sync.aligned.m8n8.x4.trans.shared.b16 {%0,%1,%2,%3}, [%4];" \
                 : "=r"(r0), "=r"(r1), "=r"(r2), "=r"(r3) : "r"(addr))

#define MMA_BF16(c, a0, a1, a2, a3, b0, b1)                                   \
    asm volatile("mma.sync.aligned.m16n8k16.row.col.f32.bf16.bf16.f32 "       \
                 "{%0,%1,%2,%3}, {%4,%5,%6,%7}, {%8,%9}, {%0,%1,%2,%3};"      \
                 : "+f"((c)[0]), "+f"((c)[1]), "+f"((c)[2]), "+f"((c)[3])     \
                 : "r"(a0), "r"(a1), "r"(a2), "r"(a3), "r"(b0), "r"(b1))

__device__ __forceinline__ void bf16_split(float v, __nv_bfloat16& hi, __nv_bfloat16& lo) {
    hi = __float2bfloat16_rn(v);
    lo = __float2bfloat16_rn(v - __bfloat162float(hi));
}

__device__ __forceinline__ void split_pack2(float a, float b, uint32_t& hi, uint32_t& lo) {
    __nv_bfloat16 ha, la, hb, lb;
    bf16_split(a, ha, la);
    bf16_split(b, hb, lb);
    hi = (uint32_t)__bfloat16_as_ushort(ha) | ((uint32_t)__bfloat16_as_ushort(hb) << 16);
    lo = (uint32_t)__bfloat16_as_ushort(la) | ((uint32_t)__bfloat16_as_ushort(lb) << 16);
}

__device__ __forceinline__ void store_split4(char* dhi, char* dlo, float4 v) {
    __nv_bfloat16 hx, lx, hy, ly, hz, lz, hw, lw;
    bf16_split(v.x, hx, lx); bf16_split(v.y, hy, ly);
    bf16_split(v.z, hz, lz); bf16_split(v.w, hw, lw);
    *(uint2*)dhi = make_uint2(
        (uint32_t)__bfloat16_as_ushort(hx) | ((uint32_t)__bfloat16_as_ushort(hy) << 16),
        (uint32_t)__bfloat16_as_ushort(hz) | ((uint32_t)__bfloat16_as_ushort(hw) << 16));
    *(uint2*)dlo = make_uint2(
        (uint32_t)__bfloat16_as_ushort(lx) | ((uint32_t)__bfloat16_as_ushort(ly) << 16),
        (uint32_t)__bfloat16_as_ushort(lz) | ((uint32_t)__bfloat16_as_ushort(lw) << 16));
}

// ===========================================================================
// Kernel 1: QKV projections, bf16x3 split on mma.sync (unchanged from R3)
// ===========================================================================
#define BK 32
#define NCHUNK (C / BK)
#define RSTRIDE 80
#define ABYTES (128 * RSTRIDE)
#define BBYTES (64 * RSTRIDE)
#define BUFBYTES (2 * ABYTES + 3 * 2 * BBYTES)
#define QKV_SMEM (2 * BUFBYTES)

#define A_OFF(buf, term)       ((buf) * BUFBYTES + (term) * ABYTES)
#define B_OFF(buf, mat, term)  ((buf) * BUFBYTES + 2 * ABYTES + (mat) * 2 * BBYTES + (term) * BBYTES)

__global__ __launch_bounds__(256)
void qkv_bf16x3_kernel(const float* __restrict__ x,
                       const float* __restrict__ Wq,
                       const float* __restrict__ Wk,
                       const float* __restrict__ Wv)
{
    extern __shared__ char sm[];
    const uint32_t sbase = smem_u32(sm);

    const int tid  = threadIdx.x;
    const int warp = tid >> 5;
    const int lane = tid & 31;
    const int wm   = warp >> 1;
    const int wn   = warp & 1;

    const int m0 = blockIdx.x * 128;
    const int h  = blockIdx.y;

    const float* Ws0 = Wq + (size_t)h * C * D;
    const float* Ws1 = Wk + (size_t)h * C * D;
    const float* Ws2 = Wv + (size_t)h * C * D;

    float acc[3][2][4][4];
    #pragma unroll
    for (int m = 0; m < 3; m++)
        #pragma unroll
        for (int i = 0; i < 2; i++)
            #pragma unroll
            for (int j = 0; j < 4; j++)
                #pragma unroll
                for (int k = 0; k < 4; k++)
                    acc[m][i][j][k] = 0.0f;

    float4 sA[4];
    float4 sB[3][2];

    auto ldg_chunk = [&](int ci) {
        const int k0 = ci * BK;
        #pragma unroll
        for (int it = 0; it < 4; it++) {
            int idx = tid + it * 256;
            int r   = idx >> 3;
            int c4  = (idx & 7) * 4;
            sA[it] = *(const float4*)(x + (size_t)(m0 + r) * C + k0 + c4);
        }
        #pragma unroll
        for (int it = 0; it < 2; it++) {
            int idx = tid + it * 256;
            int k   = idx >> 4;
            int n4  = (idx & 15) * 4;
            size_t off = (size_t)(k0 + k) * D + n4;
            sB[0][it] = *(const float4*)(Ws0 + off);
            sB[1][it] = *(const float4*)(Ws1 + off);
            sB[2][it] = *(const float4*)(Ws2 + off);
        }
    };

    auto sts_chunk = [&](int ci) {
        const int buf = ci & 1;
        #pragma unroll
        for (int it = 0; it < 4; it++) {
            int idx = tid + it * 256;
            int r   = idx >> 3;
            int c4  = (idx & 7) * 4;
            uint32_t off = r * RSTRIDE + c4 * 2;
            store_split4(sm + A_OFF(buf, 0) + off, sm + A_OFF(buf, 1) + off, sA[it]);
        }
        #pragma unroll
        for (int mat = 0; mat < 3; mat++) {
            #pragma unroll
            for (int it = 0; it < 2; it++) {
                int idx = tid + it * 256;
                int k   = idx >> 4;
                int n4  = (idx & 15) * 4;
                float4 v = sB[mat][it];
                float vv[4] = { v.x, v.y, v.z, v.w };
                #pragma unroll
                for (int j = 0; j < 4; j++) {
                    __nv_bfloat16 hi, lo;
                    bf16_split(vv[j], hi, lo);
                    uint32_t off = (n4 + j) * RSTRIDE + k * 2;
                    *(__nv_bfloat16*)(sm + B_OFF(buf, mat, 0) + off) = hi;
                    *(__nv_bfloat16*)(sm + B_OFF(buf, mat, 1) + off) = lo;
                }
            }
        }
    };

    ldg_chunk(0);
    sts_chunk(0);
    __syncthreads();

    for (int ci = 0; ci < NCHUNK; ci++) {
        const int buf = ci & 1;

        if (ci + 1 < NCHUNK) ldg_chunk(ci + 1);

        uint32_t ah[2][2][4], al[2][2][4];
        {
            const uint32_t abh = sbase + A_OFF(buf, 0);
            const uint32_t abl = sbase + A_OFF(buf, 1);
            #pragma unroll
            for (int mf = 0; mf < 2; mf++) {
                #pragma unroll
                for (int ks = 0; ks < 2; ks++) {
                    int row = wm * 32 + mf * 16 + (lane & 15);
                    int col = ks * 32 + ((lane & 16) ? 16 : 0);
                    uint32_t ao = row * RSTRIDE + col;
                    LDMX4(ah[mf][ks][0], ah[mf][ks][1], ah[mf][ks][2], ah[mf][ks][3], abh + ao);
                    LDMX4(al[mf][ks][0], al[mf][ks][1], al[mf][ks][2], al[mf][ks][3], abl + ao);
                }
            }
        }

        #pragma unroll
        for (int mat = 0; mat < 3; mat++) {
            const uint32_t bbh = sbase + B_OFF(buf, mat, 0);
            const uint32_t bbl = sbase + B_OFF(buf, mat, 1);
            #pragma unroll
            for (int ks = 0; ks < 2; ks++) {
                uint32_t bh[2][4], bl[2][4];
                #pragma unroll
                for (int nf16 = 0; nf16 < 2; nf16++) {
                    int row = wn * 32 + nf16 * 16 + (lane & 7) + ((lane & 16) ? 8 : 0);
                    int col = ks * 32 + ((lane & 8) ? 16 : 0);
                    uint32_t bo = row * RSTRIDE + col;
                    LDMX4(bh[nf16][0], bh[nf16][1], bh[nf16][2], bh[nf16][3], bbh + bo);
                    LDMX4(bl[nf16][0], bl[nf16][1], bl[nf16][2], bl[nf16][3], bbl + bo);
                }
                #pragma unroll
                for (int mf = 0; mf < 2; mf++) {
                    #pragma unroll
                    for (int nf16 = 0; nf16 < 2; nf16++) {
                        #pragma unroll
                        for (int hf = 0; hf < 2; hf++) {
                            float* c = acc[mat][mf][nf16 * 2 + hf];
                            MMA_BF16(c, ah[mf][ks][0], ah[mf][ks][1], ah[mf][ks][2], ah[mf][ks][3],
                                     bh[nf16][hf * 2], bh[nf16][hf * 2 + 1]);
                            MMA_BF16(c, al[mf][ks][0], al[mf][ks][1], al[mf][ks][2], al[mf][ks][3],
                                     bh[nf16][hf * 2], bh[nf16][hf * 2 + 1]);
                            MMA_BF16(c, ah[mf][ks][0], ah[mf][ks][1], ah[mf][ks][2], ah[mf][ks][3],
                                     bl[nf16][hf * 2], bl[nf16][hf * 2 + 1]);
                        }
                    }
                }
            }
        }

        if (ci + 1 < NCHUNK) sts_chunk(ci + 1);
        __syncthreads();
    }

    const int bb = m0 >> 10;
    #pragma unroll
    for (int mat = 0; mat < 3; mat++) {
        float* g = (mat == 0) ? g_q : (mat == 1) ? g_k : g_v;
        #pragma unroll
        for (int mf = 0; mf < 2; mf++) {
            #pragma unroll
            for (int nf = 0; nf < 4; nf++) {
                const float* c = acc[mat][mf][nf];
                int row  = wm * 32 + mf * 16 + (lane >> 2);
                int colg = wn * 32 + nf * 8 + (lane & 3) * 2;
                int t    = (m0 + row) & 1023;
                float* dst = g + (((size_t)(bb * H + h) * T + t) * D) + colg;
                *(float2*)dst = make_float2(c[0], c[1]);
                *(float2*)(dst + 8 * D) = make_float2(c[2], c[3]);
            }
        }
    }
}

// ===========================================================================
// Kernel 2: causal FlashAttention on mma.sync (bf16x3 split for S and PV).
// CTA = 128 queries x one (b,h); 8 warps x 16 rows. Key tiles of 64,
// double-buffered SMEM. K tile stored [key][d] (B operand, non-trans
// ldmatrix — same proven pattern as the GEMM). V tile stored [key][d], read
// via ldmatrix.trans as the PV B operand. Online softmax in fp32 registers.
// ===========================================================================
#define BRA 128                   // queries per CTA
#define BCA 64                    // keys per tile
#define AST 144                   // smem row stride bytes (64 halfs + 8 pad)
#define KVT (64 * AST)            // 9216 per tile term
#define KHI_OFF(buf) ((buf) * 4 * KVT)
#define KLO_OFF(buf) ((buf) * 4 * KVT + KVT)
#define VHI_OFF(buf) ((buf) * 4 * KVT + 2 * KVT)
#define VLO_OFF(buf) ((buf) * 4 * KVT + 3 * KVT)
#define QLO_OFF (128 * AST)       // Q staging: hi at 0, lo at 18432
#define ATT_SMEM (2 * 4 * KVT)    // 73728

__global__ __launch_bounds__(256)
void flash_attn_mma_kernel(float* __restrict__ out)
{
    extern __shared__ char sm[];
    const uint32_t sbase = smem_u32(sm);

    const int tid  = threadIdx.x;
    const int warp = tid >> 5;
    const int lane = tid & 31;
    const int qt = blockIdx.x;
    const int h  = blockIdx.y;
    const int b  = blockIdx.z;
    const size_t head_base = ((size_t)(b * H + h) * T) * D;
    const int q0 = qt * BRA;

    // ---- Stage Q (pre-scaled by D^-0.5) into smem hi/lo ----
    {
        const float* qp = g_q + head_base + (size_t)q0 * D;
        #pragma unroll
        for (int it = 0; it < 8; it++) {
            int idx = tid + it * 256;               // 0..2047
            int r = idx >> 4, c4 = (idx & 15) * 4;
            float4 v = *(const float4*)(qp + (size_t)r * D + c4);
            v.x *= 0.125f; v.y *= 0.125f; v.z *= 0.125f; v.w *= 0.125f;
            uint32_t off = r * AST + c4 * 2;
            store_split4(sm + off, sm + QLO_OFF + off, v);
        }
    }
    __syncthreads();

    // ---- Q fragments (persistent): [ks][4] hi + lo ----
    uint32_t qh[4][4], ql[4][4];
    #pragma unroll
    for (int ks = 0; ks < 4; ks++) {
        int row = warp * 16 + (lane & 15);
        int col = ks * 32 + ((lane & 16) ? 16 : 0);
        uint32_t ao = row * AST + col;
        LDMX4(qh[ks][0], qh[ks][1], qh[ks][2], qh[ks][3], sbase + ao);
        LDMX4(ql[ks][0], ql[ks][1], ql[ks][2], ql[ks][3], sbase + QLO_OFF + ao);
    }
    __syncthreads();

    // ---- tile load/store machinery ----
    float4 stK[4], stV[4];
    auto ldg_tile = [&](int kt) {
        const float* kp = g_k + head_base + (size_t)kt * BCA * D;
        const float* vp = g_v + head_base + (size_t)kt * BCA * D;
        #pragma unroll
        for (int it = 0; it < 4; it++) {
            int idx = tid + it * 256;               // 0..1023
            int r = idx >> 4, c4 = (idx & 15) * 4;
            stK[it] = *(const float4*)(kp + (size_t)r * D + c4);
            stV[it] = *(const float4*)(vp + (size_t)r * D + c4);
        }
    };
    auto sts_tile = [&](int kt) {
        const int buf = kt & 1;
        #pragma unroll
        for (int it = 0; it < 4; it++) {
            int idx = tid + it * 256;
            int r = idx >> 4, c4 = (idx & 15) * 4;
            uint32_t off = r * AST + c4 * 2;
            store_split4(sm + KHI_OFF(buf) + off, sm + KLO_OFF(buf) + off, stK[it]);
            store_split4(sm + VHI_OFF(buf) + off, sm + VLO_OFF(buf) + off, stV[it]);
        }
    };

    // ---- state ----
    float o[8][4];
    #pragma unroll
    for (int nf = 0; nf < 8; nf++)
        #pragma unroll
        for (int e = 0; e < 4; e++) o[nf][e] = 0.0f;
    float m0 = -1e30f, m1 = -1e30f, l0 = 0.0f, l1 = 0.0f;

    const int ntiles = 2 * (qt + 1);
    const int rbase  = q0 + warp * 16 + (lane >> 2);

    ldg_tile(0);
    sts_tile(0);
    __syncthreads();

    for (int kt = 0; kt < ntiles; kt++) {
        const int buf = kt & 1;
        if (kt + 1 < ntiles) ldg_tile(kt + 1);

        // ---- S = Q K^T (3-term) ----
        float sc[8][4];
        #pragma unroll
        for (int nf = 0; nf < 8; nf++)
            #pragma unroll
            for (int e = 0; e < 4; e++) sc[nf][e] = 0.0f;

        const uint32_t khb = sbase + KHI_OFF(buf);
        const uint32_t klb = sbase + KLO_OFF(buf);
        #pragma unroll
        for (int ks = 0; ks < 4; ks++) {
            #pragma unroll
            for (int nf16 = 0; nf16 < 4; nf16++) {
                uint32_t kb0, kb1, kb2, kb3, kc0, kc1, kc2, kc3;
                int row = nf16 * 16 + (lane & 7) + ((lane & 16) ? 8 : 0);
                int col = ks * 32 + ((lane & 8) ? 16 : 0);
                uint32_t o32 = row * AST + col;
                LDMX4(kb0, kb1, kb2, kb3, khb + o32);
                LDMX4(kc0, kc1, kc2, kc3, klb + o32);
                float* c0p = sc[nf16 * 2];
                float* c1p = sc[nf16 * 2 + 1];
                MMA_BF16(c0p, qh[ks][0], qh[ks][1], qh[ks][2], qh[ks][3], kb0, kb1);
                MMA_BF16(c0p, ql[ks][0], ql[ks][1], ql[ks][2], ql[ks][3], kb0, kb1);
                MMA_BF16(c0p, qh[ks][0], qh[ks][1], qh[ks][2], qh[ks][3], kc0, kc1);
                MMA_BF16(c1p, qh[ks][0], qh[ks][1], qh[ks][2], qh[ks][3], kb2, kb3);
                MMA_BF16(c1p, ql[ks][0], ql[ks][1], ql[ks][2], ql[ks][3], kb2, kb3);
                MMA_BF16(c1p, qh[ks][0], qh[ks][1], qh[ks][2], qh[ks][3], kc2, kc3);
            }
        }

        // ---- causal mask on diagonal tiles ----
        if (kt * BCA + 63 > q0 + warp * 16) {
            #pragma unroll
            for (int nf = 0; nf < 8; nf++) {
                int col = kt * BCA + nf * 8 + 2 * (lane & 3);
                if (col     > rbase)     sc[nf][0] = -1e30f;
                if (col + 1 > rbase)     sc[nf][1] = -1e30f;
                if (col     > rbase + 8) sc[nf][2] = -1e30f;
                if (col + 1 > rbase + 8) sc[nf][3] = -1e30f;
            }
        }

        // ---- online softmax ----
        float mt0 = -1e30f, mt1 = -1e30f;
        #pragma unroll
        for (int nf = 0; nf < 8; nf++) {
            mt0 = fmaxf(mt0, fmaxf(sc[nf][0], sc[nf][1]));
            mt1 = fmaxf(mt1, fmaxf(sc[nf][2], sc[nf][3]));
        }
        mt0 = fmaxf(mt0, __shfl_xor_sync(0xFFFFFFFFu, mt0, 1));
        mt0 = fmaxf(mt0, __shfl_xor_sync(0xFFFFFFFFu, mt0, 2));
        mt1 = fmaxf(mt1, __shfl_xor_sync(0xFFFFFFFFu, mt1, 1));
        mt1 = fmaxf(mt1, __shfl_xor_sync(0xFFFFFFFFu, mt1, 2));

        float mn0 = fmaxf(m0, mt0), mn1 = fmaxf(m1, mt1);
        float cr0 = __expf(m0 - mn0), cr1 = __expf(m1 - mn1);
        l0 *= cr0; l1 *= cr1;
        #pragma unroll
        for (int nf = 0; nf < 8; nf++) {
            o[nf][0] *= cr0; o[nf][1] *= cr0;
            o[nf][2] *= cr1; o[nf][3] *= cr1;
            sc[nf][0] = __expf(sc[nf][0] - mn0);
            sc[nf][1] = __expf(sc[nf][1] - mn0);
            sc[nf][2] = __expf(sc[nf][2] - mn1);
            sc[nf][3] = __expf(sc[nf][3] - mn1);
            l0 += sc[nf][0] + sc[nf][1];
            l1 += sc[nf][2] + sc[nf][3];
        }
        m0 = mn0; m1 = mn1;

        // ---- O += P V (3-term) ----
        const uint32_t vhb = sbase + VHI_OFF(buf);
        const uint32_t vlb = sbase + VLO_OFF(buf);
        #pragma unroll
        for (int ks = 0; ks < 4; ks++) {
            uint32_t ph[4], pl[4];
            split_pack2(sc[2 * ks][0],     sc[2 * ks][1],     ph[0], pl[0]);
            split_pack2(sc[2 * ks][2],     sc[2 * ks][3],     ph[1], pl[1]);
            split_pack2(sc[2 * ks + 1][0], sc[2 * ks + 1][1], ph[2], pl[2]);
            split_pack2(sc[2 * ks + 1][2], sc[2 * ks + 1][3], ph[3], pl[3]);
            #pragma unroll
            for (int nf16 = 0; nf16 < 4; nf16++) {
                uint32_t vb0, vb1, vb2, vb3, vc0, vc1, vc2, vc3;
                int kk = ks * 16 + ((lane & 8) ? 8 : 0) + (lane & 7);
                int cb = (nf16 * 16 + ((lane & 16) ? 8 : 0)) * 2;
                uint32_t o32 = kk * AST + cb;
                LDMX4T(vb0, vb1, vb2, vb3, vhb + o32);
                LDMX4T(vc0, vc1, vc2, vc3, vlb + o32);
                float* c0p = o[nf16 * 2];
                float* c1p = o[nf16 * 2 + 1];
                MMA_BF16(c0p, ph[0], ph[1], ph[2], ph[3], vb0, vb1);
                MMA_BF16(c0p, pl[0], pl[1], pl[2], pl[3], vb0, vb1);
                MMA_BF16(c0p, ph[0], ph[1], ph[2], ph[3], vc0, vc1);
                MMA_BF16(c1p, ph[0], ph[1], ph[2], ph[3], vb2, vb3);
                MMA_BF16(c1p, pl[0], pl[1], pl[2], pl[3], vb2, vb3);
                MMA_BF16(c1p, ph[0], ph[1], ph[2], ph[3], vc2, vc3);
            }
        }

        if (kt + 1 < ntiles) sts_tile(kt + 1);
        __syncthreads();
    }

    // ---- finalize + write out[b][t][h*D + d] ----
    l0 += __shfl_xor_sync(0xFFFFFFFFu, l0, 1);
    l0 += __shfl_xor_sync(0xFFFFFFFFu, l0, 2);
    l1 += __shfl_xor_sync(0xFFFFFFFFu, l1, 1);
    l1 += __shfl_xor_sync(0xFFFFFFFFu, l1, 2);
    const float i0 = 1.0f / l0;
    const float i1 = 1.0f / l1;

    float* op = out + ((size_t)(b * T + rbase) * (H * D)) + h * D;
    #pragma unroll
    for (int nf = 0; nf < 8; nf++) {
        int col = nf * 8 + 2 * (lane & 3);
        *(float2*)(op + col) = make_float2(o[nf][0] * i0, o[nf][1] * i0);
        *(float2*)(op + (size_t)8 * (H * D) + col) = make_float2(o[nf][2] * i1, o[nf][3] * i1);
    }
}

// ===========================================================================
extern "C" void kernel_launch(void* const* d_in, const int* in_sizes, int n_in,
                              void* d_out, int out_size)
{
    const float* x  = (const float*)d_in[0];   // [B, T, C]
    const float* Wq = (const float*)d_in[1];   // [H, C, D]
    const float* Wk = (const float*)d_in[2];
    const float* Wv = (const float*)d_in[3];
    float* out = (float*)d_out;                 // [B, T, H*D]

    (void)in_sizes; (void)n_in; (void)out_size;

    static int smem_set = 0;
    if (!smem_set) {
        cudaFuncSetAttribute(qkv_bf16x3_kernel,
                             cudaFuncAttributeMaxDynamicSharedMemorySize, QKV_SMEM);
        cudaFuncSetAttribute(flash_attn_mma_kernel,
                             cudaFuncAttributeMaxDynamicSharedMemorySize, ATT_SMEM);
        smem_set = 1;
    }

    dim3 gemm_grid(T * B / 128, H);             // 64 x 16
    qkv_bf16x3_kernel<<<gemm_grid, 256, QKV_SMEM>>>(x, Wq, Wk, Wv);

    dim3 attn_grid(T / BRA, H, B);              // 8 x 16 x 8
    flash_attn_mma_kernel<<<attn_grid, 256, ATT_SMEM>>>(out);
}

// round 6
// speedup vs baseline: 3.6279x; 1.7433x over previous
#include <cuda_runtime.h>
#include <cuda_bf16.h>
#include <cuda_fp16.h>
#include <math.h>
#include <stdint.h>

// Problem constants
#define B 8
#define T 1024
#define C 1024
#define H 16
#define D 64

// Scratch: Q/K/V projections [B][H][T][D] fp32; x split fp16; W fp16
__device__ float  g_q[(size_t)B * H * T * D];
__device__ float  g_k[(size_t)B * H * T * D];
__device__ float  g_v[(size_t)B * H * T * D];
__device__ __half g_xh[(size_t)B * T * C];
__device__ __half g_xl[(size_t)B * T * C];
__device__ __half g_wh[(size_t)3 * H * C * D];

// ===========================================================================
// Helpers
// ===========================================================================
__device__ __forceinline__ uint32_t smem_u32(const void* p) {
    uint32_t a;
    asm("{ .reg .u64 t; cvta.to.shared.u64 t, %1; cvt.u32.u64 %0, t; }"
        : "=r"(a) : "l"(p));
    return a;
}

#define LDMX4(r0, r1, r2, r3, addr)                                           \
    asm volatile("ldmatrix.sync.aligned.m8n8.x4.shared.b16 {%0,%1,%2,%3}, [%4];" \
                 : "=r"(r0), "=r"(r1), "=r"(r2), "=r"(r3) : "r"(addr))

#define LDMX4T(r0, r1, r2, r3, addr)                                          \
    asm volatile("ldmatrix.sync.aligned.m8n8.x4.trans.shared.b16 {%0,%1,%2,%3}, [%4];" \
                 : "=r"(r0), "=r"(r1), "=r"(r2), "=r"(r3) : "r"(addr))

#define MMA_BF16(c, a0, a1, a2, a3, b0, b1)                                   \
    asm volatile("mma.sync.aligned.m16n8k16.row.col.f32.bf16.bf16.f32 "       \
                 "{%0,%1,%2,%3}, {%4,%5,%6,%7}, {%8,%9}, {%0,%1,%2,%3};"      \
                 : "+f"((c)[0]), "+f"((c)[1]), "+f"((c)[2]), "+f"((c)[3])     \
                 : "r"(a0), "r"(a1), "r"(a2), "r"(a3), "r"(b0), "r"(b1))

#define MMA_F16(c, a0, a1, a2, a3, b0, b1)                                    \
    asm volatile("mma.sync.aligned.m16n8k16.row.col.f32.f16.f16.f32 "         \
                 "{%0,%1,%2,%3}, {%4,%5,%6,%7}, {%8,%9}, {%0,%1,%2,%3};"      \
                 : "+f"((c)[0]), "+f"((c)[1]), "+f"((c)[2]), "+f"((c)[3])     \
                 : "r"(a0), "r"(a1), "r"(a2), "r"(a3), "r"(b0), "r"(b1))

#define CPA16(dst, src) \
    asm volatile("cp.async.cg.shared.global [%0], [%1], 16;" :: "r"(dst), "l"(src))
#define CPC()  asm volatile("cp.async.commit_group;" ::: "memory")
#define CPW0() asm volatile("cp.async.wait_group 0;" ::: "memory")
#define CPW1() asm volatile("cp.async.wait_group 1;" ::: "memory")

__device__ __forceinline__ void bf16_split(float v, __nv_bfloat16& hi, __nv_bfloat16& lo) {
    hi = __float2bfloat16_rn(v);
    lo = __float2bfloat16_rn(v - __bfloat162float(hi));
}

__device__ __forceinline__ void split_pack2(float a, float b, uint32_t& hi, uint32_t& lo) {
    __nv_bfloat16 ha, la, hb, lb;
    bf16_split(a, ha, la);
    bf16_split(b, hb, lb);
    hi = (uint32_t)__bfloat16_as_ushort(ha) | ((uint32_t)__bfloat16_as_ushort(hb) << 16);
    lo = (uint32_t)__bfloat16_as_ushort(la) | ((uint32_t)__bfloat16_as_ushort(lb) << 16);
}

__device__ __forceinline__ void store_split4(char* dhi, char* dlo, float4 v) {
    __nv_bfloat16 hx, lx, hy, ly, hz, lz, hw, lw;
    bf16_split(v.x, hx, lx); bf16_split(v.y, hy, ly);
    bf16_split(v.z, hz, lz); bf16_split(v.w, hw, lw);
    *(uint2*)dhi = make_uint2(
        (uint32_t)__bfloat16_as_ushort(hx) | ((uint32_t)__bfloat16_as_ushort(hy) << 16),
        (uint32_t)__bfloat16_as_ushort(hz) | ((uint32_t)__bfloat16_as_ushort(hw) << 16));
    *(uint2*)dlo = make_uint2(
        (uint32_t)__bfloat16_as_ushort(lx) | ((uint32_t)__bfloat16_as_ushort(ly) << 16),
        (uint32_t)__bfloat16_as_ushort(lz) | ((uint32_t)__bfloat16_as_ushort(lw) << 16));
}

__device__ __forceinline__ uint32_t pack_h2(__half a, __half b) {
    __half2 h = __halves2half2(a, b);
    return *(uint32_t*)&h;
}

// ===========================================================================
// Kernel 0a: split x into fp16 hi/lo (exact to ~2^-22)
// ===========================================================================
__global__ __launch_bounds__(256) void split_x_kernel(const float* __restrict__ x)
{
    size_t i = ((size_t)blockIdx.x * 256 + threadIdx.x) * 4;
    float4 v = *(const float4*)(x + i);
    __half hx = __float2half_rn(v.x), hy = __float2half_rn(v.y);
    __half hz = __float2half_rn(v.z), hw = __float2half_rn(v.w);
    __half lx = __float2half_rn(v.x - __half2float(hx));
    __half ly = __float2half_rn(v.y - __half2float(hy));
    __half lz = __float2half_rn(v.z - __half2float(hz));
    __half lw = __float2half_rn(v.w - __half2float(hw));
    *(uint2*)(g_xh + i) = make_uint2(pack_h2(hx, hy), pack_h2(hz, hw));
    *(uint2*)(g_xl + i) = make_uint2(pack_h2(lx, ly), pack_h2(lz, lw));
}

// ===========================================================================
// Kernel 0b: convert W to fp16 (single rounding — the only GEMM error source)
// ===========================================================================
__global__ __launch_bounds__(256) void conv_w_kernel(const float* __restrict__ Wq,
                                                     const float* __restrict__ Wk,
                                                     const float* __restrict__ Wv)
{
    const int mat = blockIdx.y;
    const float* W = (mat == 0) ? Wq : (mat == 1) ? Wk : Wv;
    size_t i = ((size_t)blockIdx.x * 256 + threadIdx.x) * 4;
    float4 v = *(const float4*)(W + i);
    *(uint2*)(g_wh + (size_t)mat * H * C * D + i) = make_uint2(
        pack_h2(__float2half_rn(v.x), __float2half_rn(v.y)),
        pack_h2(__float2half_rn(v.z), __float2half_rn(v.w)));
}

// ===========================================================================
// Kernel 1: QKV projections, fp16 2-term split, cp.async double-buffered.
// CTA = 128 M-rows x 1 head, all 3 matrices. A = x_hi/x_lo [m][k] (stride 80,
// non-trans ldmatrix); B = W fp16 [k][d] (stride 144, ldmatrix.trans —
// the pattern validated by the attention PV path).
// ===========================================================================
#define BK 32
#define NCHUNK (C / BK)
#define GBUF 34304
#define GAH(buf)       ((buf) * GBUF)
#define GAL(buf)       ((buf) * GBUF + 10240)
#define GBW(buf, mat)  ((buf) * GBUF + 20480 + (mat) * 4608)
#define G_SMEM (2 * GBUF)     // 68608

__global__ __launch_bounds__(256)
void qkv_fp16_kernel()
{
    extern __shared__ char sm[];
    const uint32_t sbase = smem_u32(sm);

    const int tid  = threadIdx.x;
    const int warp = tid >> 5;
    const int lane = tid & 31;
    const int wm   = warp >> 1;           // 0..3 -> rows [wm*32, +32)
    const int wn   = warp & 1;            // 0..1 -> cols [wn*32, +32)

    const int m0 = blockIdx.x * 128;
    const int h  = blockIdx.y;

    float acc[3][2][4][4];
    #pragma unroll
    for (int m = 0; m < 3; m++)
        #pragma unroll
        for (int i = 0; i < 2; i++)
            #pragma unroll
            for (int j = 0; j < 4; j++)
                #pragma unroll
                for (int k = 0; k < 4; k++)
                    acc[m][i][j][k] = 0.0f;

    auto load_chunk = [&](int ci) {
        const int buf = ci & 1;
        const int k0  = ci * BK;
        // A: x_hi / x_lo, 128 rows x 32 halves; 512 cp.async each
        #pragma unroll
        for (int i = 0; i < 2; i++) {
            int idx = tid * 2 + i;                 // 0..511
            int r   = idx >> 2;                    // 0..127
            int seg = idx & 3;                     // 16B segments
            uint32_t dofs = r * 80 + seg * 16;
            const __half* sh = g_xh + (size_t)(m0 + r) * C + k0 + seg * 8;
            const __half* sl = g_xl + (size_t)(m0 + r) * C + k0 + seg * 8;
            CPA16(sbase + GAH(buf) + dofs, sh);
            CPA16(sbase + GAL(buf) + dofs, sl);
        }
        // B: 3 mats x 32 k-rows x 64 halves; 256 cp.async per mat
        {
            int r   = tid >> 3;                    // 0..31
            int seg = tid & 7;                     // 0..7
            uint32_t dofs = r * 144 + seg * 16;
            #pragma unroll
            for (int mat = 0; mat < 3; mat++) {
                const __half* s = g_wh + ((size_t)(mat * H + h)) * C * D
                                 + (size_t)(k0 + r) * D + seg * 8;
                CPA16(sbase + GBW(buf, mat) + dofs, s);
            }
        }
    };

    load_chunk(0); CPC();
    load_chunk(1); CPC();

    for (int ci = 0; ci < NCHUNK; ci++) {
        const int buf = ci & 1;
        if (ci < NCHUNK - 1) { CPW1(); } else { CPW0(); }
        __syncthreads();

        // ---- A fragments (hi + lo), all ksteps ----
        uint32_t ah[2][2][4], al[2][2][4];        // [mf][ks][4]
        {
            const uint32_t abh = sbase + GAH(buf);
            const uint32_t abl = sbase + GAL(buf);
            #pragma unroll
            for (int mf = 0; mf < 2; mf++) {
                #pragma unroll
                for (int ks = 0; ks < 2; ks++) {
                    int row = wm * 32 + mf * 16 + (lane & 15);
                    int col = ks * 32 + ((lane & 16) ? 16 : 0);
                    uint32_t ao = row * 80 + col;
                    LDMX4(ah[mf][ks][0], ah[mf][ks][1], ah[mf][ks][2], ah[mf][ks][3], abh + ao);
                    LDMX4(al[mf][ks][0], al[mf][ks][1], al[mf][ks][2], al[mf][ks][3], abl + ao);
                }
            }
        }

        // ---- per matrix: B frags via ldmatrix.trans, 2-term MMA ----
        #pragma unroll
        for (int mat = 0; mat < 3; mat++) {
            const uint32_t bb = sbase + GBW(buf, mat);
            #pragma unroll
            for (int ks = 0; ks < 2; ks++) {
                #pragma unroll
                for (int nf16 = 0; nf16 < 2; nf16++) {
                    uint32_t b0, b1, b2, b3;
                    int kk = ks * 16 + (lane & 15);
                    int cb = (wn * 32 + nf16 * 16 + ((lane & 16) ? 8 : 0)) * 2;
                    LDMX4T(b0, b1, b2, b3, bb + kk * 144 + cb);
                    #pragma unroll
                    for (int mf = 0; mf < 2; mf++) {
                        float* c0 = acc[mat][mf][nf16 * 2];
                        float* c1 = acc[mat][mf][nf16 * 2 + 1];
                        MMA_F16(c0, ah[mf][ks][0], ah[mf][ks][1], ah[mf][ks][2], ah[mf][ks][3], b0, b1);
                        MMA_F16(c0, al[mf][ks][0], al[mf][ks][1], al[mf][ks][2], al[mf][ks][3], b0, b1);
                        MMA_F16(c1, ah[mf][ks][0], ah[mf][ks][1], ah[mf][ks][2], ah[mf][ks][3], b2, b3);
                        MMA_F16(c1, al[mf][ks][0], al[mf][ks][1], al[mf][ks][2], al[mf][ks][3], b2, b3);
                    }
                }
            }
        }

        __syncthreads();
        if (ci + 2 < NCHUNK) { load_chunk(ci + 2); CPC(); }
    }

    // ---- epilogue: accumulators -> g_q/g_k/g_v ([B][H][T][D]) ----
    const int bb = m0 >> 10;
    #pragma unroll
    for (int mat = 0; mat < 3; mat++) {
        float* g = (mat == 0) ? g_q : (mat == 1) ? g_k : g_v;
        #pragma unroll
        for (int mf = 0; mf < 2; mf++) {
            #pragma unroll
            for (int nf = 0; nf < 4; nf++) {
                const float* c = acc[mat][mf][nf];
                int row  = wm * 32 + mf * 16 + (lane >> 2);
                int colg = wn * 32 + nf * 8 + (lane & 3) * 2;
                int t    = (m0 + row) & 1023;
                float* dst = g + (((size_t)(bb * H + h) * T + t) * D) + colg;
                *(float2*)dst = make_float2(c[0], c[1]);
                *(float2*)(dst + 8 * D) = make_float2(c[2], c[3]);
            }
        }
    }
}

// ===========================================================================
// Kernel 2: causal FlashAttention on mma.sync (unchanged from R4 — 225us)
// ===========================================================================
#define BRA 128
#define BCA 64
#define AST 144
#define KVT (64 * AST)
#define KHI_OFF(buf) ((buf) * 4 * KVT)
#define KLO_OFF(buf) ((buf) * 4 * KVT + KVT)
#define VHI_OFF(buf) ((buf) * 4 * KVT + 2 * KVT)
#define VLO_OFF(buf) ((buf) * 4 * KVT + 3 * KVT)
#define QLO_OFF (128 * AST)
#define ATT_SMEM (2 * 4 * KVT)

__global__ __launch_bounds__(256)
void flash_attn_mma_kernel(float* __restrict__ out)
{
    extern __shared__ char sm[];
    const uint32_t sbase = smem_u32(sm);

    const int tid  = threadIdx.x;
    const int warp = tid >> 5;
    const int lane = tid & 31;
    const int qt = blockIdx.x;
    const int h  = blockIdx.y;
    const int b  = blockIdx.z;
    const size_t head_base = ((size_t)(b * H + h) * T) * D;
    const int q0 = qt * BRA;

    {
        const float* qp = g_q + head_base + (size_t)q0 * D;
        #pragma unroll
        for (int it = 0; it < 8; it++) {
            int idx = tid + it * 256;
            int r = idx >> 4, c4 = (idx & 15) * 4;
            float4 v = *(const float4*)(qp + (size_t)r * D + c4);
            v.x *= 0.125f; v.y *= 0.125f; v.z *= 0.125f; v.w *= 0.125f;
            uint32_t off = r * AST + c4 * 2;
            store_split4(sm + off, sm + QLO_OFF + off, v);
        }
    }
    __syncthreads();

    uint32_t qh[4][4], ql[4][4];
    #pragma unroll
    for (int ks = 0; ks < 4; ks++) {
        int row = warp * 16 + (lane & 15);
        int col = ks * 32 + ((lane & 16) ? 16 : 0);
        uint32_t ao = row * AST + col;
        LDMX4(qh[ks][0], qh[ks][1], qh[ks][2], qh[ks][3], sbase + ao);
        LDMX4(ql[ks][0], ql[ks][1], ql[ks][2], ql[ks][3], sbase + QLO_OFF + ao);
    }
    __syncthreads();

    float4 stK[4], stV[4];
    auto ldg_tile = [&](int kt) {
        const float* kp = g_k + head_base + (size_t)kt * BCA * D;
        const float* vp = g_v + head_base + (size_t)kt * BCA * D;
        #pragma unroll
        for (int it = 0; it < 4; it++) {
            int idx = tid + it * 256;
            int r = idx >> 4, c4 = (idx & 15) * 4;
            stK[it] = *(const float4*)(kp + (size_t)r * D + c4);
            stV[it] = *(const float4*)(vp + (size_t)r * D + c4);
        }
    };
    auto sts_tile = [&](int kt) {
        const int buf = kt & 1;
        #pragma unroll
        for (int it = 0; it < 4; it++) {
            int idx = tid + it * 256;
            int r = idx >> 4, c4 = (idx & 15) * 4;
            uint32_t off = r * AST + c4 * 2;
            store_split4(sm + KHI_OFF(buf) + off, sm + KLO_OFF(buf) + off, stK[it]);
            store_split4(sm + VHI_OFF(buf) + off, sm + VLO_OFF(buf) + off, stV[it]);
        }
    };

    float o[8][4];
    #pragma unroll
    for (int nf = 0; nf < 8; nf++)
        #pragma unroll
        for (int e = 0; e < 4; e++) o[nf][e] = 0.0f;
    float m0 = -1e30f, m1 = -1e30f, l0 = 0.0f, l1 = 0.0f;

    const int ntiles = 2 * (qt + 1);
    const int rbase  = q0 + warp * 16 + (lane >> 2);

    ldg_tile(0);
    sts_tile(0);
    __syncthreads();

    for (int kt = 0; kt < ntiles; kt++) {
        const int buf = kt & 1;
        if (kt + 1 < ntiles) ldg_tile(kt + 1);

        float sc[8][4];
        #pragma unroll
        for (int nf = 0; nf < 8; nf++)
            #pragma unroll
            for (int e = 0; e < 4; e++) sc[nf][e] = 0.0f;

        const uint32_t khb = sbase + KHI_OFF(buf);
        const uint32_t klb = sbase + KLO_OFF(buf);
        #pragma unroll
        for (int ks = 0; ks < 4; ks++) {
            #pragma unroll
            for (int nf16 = 0; nf16 < 4; nf16++) {
                uint32_t kb0, kb1, kb2, kb3, kc0, kc1, kc2, kc3;
                int row = nf16 * 16 + (lane & 7) + ((lane & 16) ? 8 : 0);
                int col = ks * 32 + ((lane & 8) ? 16 : 0);
                uint32_t o32 = row * AST + col;
                LDMX4(kb0, kb1, kb2, kb3, khb + o32);
                LDMX4(kc0, kc1, kc2, kc3, klb + o32);
                float* c0p = sc[nf16 * 2];
                float* c1p = sc[nf16 * 2 + 1];
                MMA_BF16(c0p, qh[ks][0], qh[ks][1], qh[ks][2], qh[ks][3], kb0, kb1);
                MMA_BF16(c0p, ql[ks][0], ql[ks][1], ql[ks][2], ql[ks][3], kb0, kb1);
                MMA_BF16(c0p, qh[ks][0], qh[ks][1], qh[ks][2], qh[ks][3], kc0, kc1);
                MMA_BF16(c1p, qh[ks][0], qh[ks][1], qh[ks][2], qh[ks][3], kb2, kb3);
                MMA_BF16(c1p, ql[ks][0], ql[ks][1], ql[ks][2], ql[ks][3], kb2, kb3);
                MMA_BF16(c1p, qh[ks][0], qh[ks][1], qh[ks][2], qh[ks][3], kc2, kc3);
            }
        }

        if (kt * BCA + 63 > q0 + warp * 16) {
            #pragma unroll
            for (int nf = 0; nf < 8; nf++) {
                int col = kt * BCA + nf * 8 + 2 * (lane & 3);
                if (col     > rbase)     sc[nf][0] = -1e30f;
                if (col + 1 > rbase)     sc[nf][1] = -1e30f;
                if (col     > rbase + 8) sc[nf][2] = -1e30f;
                if (col + 1 > rbase + 8) sc[nf][3] = -1e30f;
            }
        }

        float mt0 = -1e30f, mt1 = -1e30f;
        #pragma unroll
        for (int nf = 0; nf < 8; nf++) {
            mt0 = fmaxf(mt0, fmaxf(sc[nf][0], sc[nf][1]));
            mt1 = fmaxf(mt1, fmaxf(sc[nf][2], sc[nf][3]));
        }
        mt0 = fmaxf(mt0, __shfl_xor_sync(0xFFFFFFFFu, mt0, 1));
        mt0 = fmaxf(mt0, __shfl_xor_sync(0xFFFFFFFFu, mt0, 2));
        mt1 = fmaxf(mt1, __shfl_xor_sync(0xFFFFFFFFu, mt1, 1));
        mt1 = fmaxf(mt1, __shfl_xor_sync(0xFFFFFFFFu, mt1, 2));

        float mn0 = fmaxf(m0, mt0), mn1 = fmaxf(m1, mt1);
        float cr0 = __expf(m0 - mn0), cr1 = __expf(m1 - mn1);
        l0 *= cr0; l1 *= cr1;
        #pragma unroll
        for (int nf = 0; nf < 8; nf++) {
            o[nf][0] *= cr0; o[nf][1] *= cr0;
            o[nf][2] *= cr1; o[nf][3] *= cr1;
            sc[nf][0] = __expf(sc[nf][0] - mn0);
            sc[nf][1] = __expf(sc[nf][1] - mn0);
            sc[nf][2] = __expf(sc[nf][2] - mn1);
            sc[nf][3] = __expf(sc[nf][3] - mn1);
            l0 += sc[nf][0] + sc[nf][1];
            l1 += sc[nf][2] + sc[nf][3];
        }
        m0 = mn0; m1 = mn1;

        const uint32_t vhb = sbase + VHI_OFF(buf);
        const uint32_t vlb = sbase + VLO_OFF(buf);
        #pragma unroll
        for (int ks = 0; ks < 4; ks++) {
            uint32_t ph[4], pl[4];
            split_pack2(sc[2 * ks][0],     sc[2 * ks][1],     ph[0], pl[0]);
            split_pack2(sc[2 * ks][2],     sc[2 * ks][3],     ph[1], pl[1]);
            split_pack2(sc[2 * ks + 1][0], sc[2 * ks + 1][1], ph[2], pl[2]);
            split_pack2(sc[2 * ks + 1][2], sc[2 * ks + 1][3], ph[3], pl[3]);
            #pragma unroll
            for (int nf16 = 0; nf16 < 4; nf16++) {
                uint32_t vb0, vb1, vb2, vb3, vc0, vc1, vc2, vc3;
                int kk = ks * 16 + ((lane & 8) ? 8 : 0) + (lane & 7);
                int cb = (nf16 * 16 + ((lane & 16) ? 8 : 0)) * 2;
                uint32_t o32 = kk * AST + cb;
                LDMX4T(vb0, vb1, vb2, vb3, vhb + o32);
                LDMX4T(vc0, vc1, vc2, vc3, vlb + o32);
                float* c0p = o[nf16 * 2];
                float* c1p = o[nf16 * 2 + 1];
                MMA_BF16(c0p, ph[0], ph[1], ph[2], ph[3], vb0, vb1);
                MMA_BF16(c0p, pl[0], pl[1], pl[2], pl[3], vb0, vb1);
                MMA_BF16(c0p, ph[0], ph[1], ph[2], ph[3], vc0, vc1);
                MMA_BF16(c1p, ph[0], ph[1], ph[2], ph[3], vb2, vb3);
                MMA_BF16(c1p, pl[0], pl[1], pl[2], pl[3], vb2, vb3);
                MMA_BF16(c1p, ph[0], ph[1], ph[2], ph[3], vc2, vc3);
            }
        }

        if (kt + 1 < ntiles) sts_tile(kt + 1);
        __syncthreads();
    }

    l0 += __shfl_xor_sync(0xFFFFFFFFu, l0, 1);
    l0 += __shfl_xor_sync(0xFFFFFFFFu, l0, 2);
    l1 += __shfl_xor_sync(0xFFFFFFFFu, l1, 1);
    l1 += __shfl_xor_sync(0xFFFFFFFFu, l1, 2);
    const float i0 = 1.0f / l0;
    const float i1 = 1.0f / l1;

    float* op = out + ((size_t)(b * T + rbase) * (H * D)) + h * D;
    #pragma unroll
    for (int nf = 0; nf < 8; nf++) {
        int col = nf * 8 + 2 * (lane & 3);
        *(float2*)(op + col) = make_float2(o[nf][0] * i0, o[nf][1] * i0);
        *(float2*)(op + (size_t)8 * (H * D) + col) = make_float2(o[nf][2] * i1, o[nf][3] * i1);
    }
}

// ===========================================================================
extern "C" void kernel_launch(void* const* d_in, const int* in_sizes, int n_in,
                              void* d_out, int out_size)
{
    const float* x  = (const float*)d_in[0];   // [B, T, C]
    const float* Wq = (const float*)d_in[1];   // [H, C, D]
    const float* Wk = (const float*)d_in[2];
    const float* Wv = (const float*)d_in[3];
    float* out = (float*)d_out;                 // [B, T, H*D]

    (void)in_sizes; (void)n_in; (void)out_size;

    static int smem_set = 0;
    if (!smem_set) {
        cudaFuncSetAttribute(qkv_fp16_kernel,
                             cudaFuncAttributeMaxDynamicSharedMemorySize, G_SMEM);
        cudaFuncSetAttribute(flash_attn_mma_kernel,
                             cudaFuncAttributeMaxDynamicSharedMemorySize, ATT_SMEM);
        smem_set = 1;
    }

    split_x_kernel<<<(size_t)B * T * C / 1024, 256>>>(x);
    conv_w_kernel<<<dim3(H * C * D / 1024, 3), 256>>>(Wq, Wk, Wv);

    dim3 gemm_grid(T * B / 128, H);             // 64 x 16
    qkv_fp16_kernel<<<gemm_grid, 256, G_SMEM>>>();

    dim3 attn_grid(T / BRA, H, B);              // 8 x 16 x 8
    flash_attn_mma_kernel<<<attn_grid, 256, ATT_SMEM>>>(out);
}

// round 8
// speedup vs baseline: 3.6340x; 1.0017x over previous
#include <cuda_runtime.h>
#include <cuda_bf16.h>
#include <cuda_fp16.h>
#include <math.h>
#include <stdint.h>

// Problem constants
#define B 8
#define T 1024
#define C 1024
#define H 16
#define D 64

// Scratch: Q fp32; K/V pre-split bf16 hi/lo; x split fp16; W fp16
__device__ float         g_q [(size_t)B * H * T * D];
__device__ __nv_bfloat16 g_kh[(size_t)B * H * T * D];
__device__ __nv_bfloat16 g_kl[(size_t)B * H * T * D];
__device__ __nv_bfloat16 g_vh[(size_t)B * H * T * D];
__device__ __nv_bfloat16 g_vl[(size_t)B * H * T * D];
__device__ __half        g_xh[(size_t)B * T * C];
__device__ __half        g_xl[(size_t)B * T * C];
__device__ __half        g_wh[(size_t)3 * H * C * D];

// ===========================================================================
// Helpers
// ===========================================================================
__device__ __forceinline__ uint32_t smem_u32(const void* p) {
    uint32_t a;
    asm("{ .reg .u64 t; cvta.to.shared.u64 t, %1; cvt.u32.u64 %0, t; }"
        : "=r"(a) : "l"(p));
    return a;
}

#define LDMX4(r0, r1, r2, r3, addr)                                           \
    asm volatile("ldmatrix.sync.aligned.m8n8.x4.shared.b16 {%0,%1,%2,%3}, [%4];" \
                 : "=r"(r0), "=r"(r1), "=r"(r2), "=r"(r3) : "r"(addr))

#define LDMX4T(r0, r1, r2, r3, addr)                                          \
    asm volatile("ldmatrix.sync.aligned.m8n8.x4.trans.shared.b16 {%0,%1,%2,%3}, [%4];" \
                 : "=r"(r0), "=r"(r1), "=r"(r2), "=r"(r3) : "r"(addr))

#define MMA_BF16(c, a0, a1, a2, a3, b0, b1)                                   \
    asm volatile("mma.sync.aligned.m16n8k16.row.col.f32.bf16.bf16.f32 "       \
                 "{%0,%1,%2,%3}, {%4,%5,%6,%7}, {%8,%9}, {%0,%1,%2,%3};"      \
                 : "+f"((c)[0]), "+f"((c)[1]), "+f"((c)[2]), "+f"((c)[3])     \
                 : "r"(a0), "r"(a1), "r"(a2), "r"(a3), "r"(b0), "r"(b1))

#define MMA_F16(c, a0, a1, a2, a3, b0, b1)                                    \
    asm volatile("mma.sync.aligned.m16n8k16.row.col.f32.f16.f16.f32 "         \
                 "{%0,%1,%2,%3}, {%4,%5,%6,%7}, {%8,%9}, {%0,%1,%2,%3};"      \
                 : "+f"((c)[0]), "+f"((c)[1]), "+f"((c)[2]), "+f"((c)[3])     \
                 : "r"(a0), "r"(a1), "r"(a2), "r"(a3), "r"(b0), "r"(b1))

#define CPA16(dst, src) \
    asm volatile("cp.async.cg.shared.global [%0], [%1], 16;" :: "r"(dst), "l"(src))
#define CPC()  asm volatile("cp.async.commit_group;" ::: "memory")
#define CPW0() asm volatile("cp.async.wait_group 0;" ::: "memory")
#define CPW1() asm volatile("cp.async.wait_group 1;" ::: "memory")

__device__ __forceinline__ void bf16_split(float v, __nv_bfloat16& hi, __nv_bfloat16& lo) {
    hi = __float2bfloat16_rn(v);
    lo = __float2bfloat16_rn(v - __bfloat162float(hi));
}

__device__ __forceinline__ void split_pack2(float a, float b, uint32_t& hi, uint32_t& lo) {
    __nv_bfloat16 ha, la, hb, lb;
    bf16_split(a, ha, la);
    bf16_split(b, hb, lb);
    hi = (uint32_t)__bfloat16_as_ushort(ha) | ((uint32_t)__bfloat16_as_ushort(hb) << 16);
    lo = (uint32_t)__bfloat16_as_ushort(la) | ((uint32_t)__bfloat16_as_ushort(lb) << 16);
}

__device__ __forceinline__ void store_split4(char* dhi, char* dlo, float4 v) {
    __nv_bfloat16 hx, lx, hy, ly, hz, lz, hw, lw;
    bf16_split(v.x, hx, lx); bf16_split(v.y, hy, ly);
    bf16_split(v.z, hz, lz); bf16_split(v.w, hw, lw);
    *(uint2*)dhi = make_uint2(
        (uint32_t)__bfloat16_as_ushort(hx) | ((uint32_t)__bfloat16_as_ushort(hy) << 16),
        (uint32_t)__bfloat16_as_ushort(hz) | ((uint32_t)__bfloat16_as_ushort(hw) << 16));
    *(uint2*)dlo = make_uint2(
        (uint32_t)__bfloat16_as_ushort(lx) | ((uint32_t)__bfloat16_as_ushort(ly) << 16),
        (uint32_t)__bfloat16_as_ushort(lz) | ((uint32_t)__bfloat16_as_ushort(lw) << 16));
}

__device__ __forceinline__ uint32_t pack_h2(__half a, __half b) {
    __half2 h = __halves2half2(a, b);
    return *(uint32_t*)&h;
}

// ===========================================================================
// Kernel 0a: split x into fp16 hi/lo (exact to ~2^-22)
// ===========================================================================
__global__ __launch_bounds__(256) void split_x_kernel(const float* __restrict__ x)
{
    size_t i = ((size_t)blockIdx.x * 256 + threadIdx.x) * 4;
    float4 v = *(const float4*)(x + i);
    __half hx = __float2half_rn(v.x), hy = __float2half_rn(v.y);
    __half hz = __float2half_rn(v.z), hw = __float2half_rn(v.w);
    __half lx = __float2half_rn(v.x - __half2float(hx));
    __half ly = __float2half_rn(v.y - __half2float(hy));
    __half lz = __float2half_rn(v.z - __half2float(hz));
    __half lw = __float2half_rn(v.w - __half2float(hw));
    *(uint2*)(g_xh + i) = make_uint2(pack_h2(hx, hy), pack_h2(hz, hw));
    *(uint2*)(g_xl + i) = make_uint2(pack_h2(lx, ly), pack_h2(lz, lw));
}

// ===========================================================================
// Kernel 0b: convert W to fp16 (single rounding — the only GEMM error source)
// ===========================================================================
__global__ __launch_bounds__(256) void conv_w_kernel(const float* __restrict__ Wq,
                                                     const float* __restrict__ Wk,
                                                     const float* __restrict__ Wv)
{
    const int mat = blockIdx.y;
    const float* W = (mat == 0) ? Wq : (mat == 1) ? Wk : Wv;
    size_t i = ((size_t)blockIdx.x * 256 + threadIdx.x) * 4;
    float4 v = *(const float4*)(W + i);
    *(uint2*)(g_wh + (size_t)mat * H * C * D + i) = make_uint2(
        pack_h2(__float2half_rn(v.x), __float2half_rn(v.y)),
        pack_h2(__float2half_rn(v.z), __float2half_rn(v.w)));
}

// ===========================================================================
// Kernel 1: QKV projections, fp16 2-term split, cp.async double-buffered.
// Epilogue: Q -> fp32; K,V -> pre-split bf16 hi/lo (consumed by attention
// via cp.async directly — split done ONCE here instead of per query-tile).
// ===========================================================================
#define BK 32
#define NCHUNK (C / BK)
#define GBUF 34304
#define GAH(buf)       ((buf) * GBUF)
#define GAL(buf)       ((buf) * GBUF + 10240)
#define GBW(buf, mat)  ((buf) * GBUF + 20480 + (mat) * 4608)
#define G_SMEM (2 * GBUF)     // 68608

__global__ __launch_bounds__(256)
void qkv_fp16_kernel()
{
    extern __shared__ char sm[];
    const uint32_t sbase = smem_u32(sm);

    const int tid  = threadIdx.x;
    const int warp = tid >> 5;
    const int lane = tid & 31;
    const int wm   = warp >> 1;
    const int wn   = warp & 1;

    const int m0 = blockIdx.x * 128;
    const int h  = blockIdx.y;

    float acc[3][2][4][4];
    #pragma unroll
    for (int m = 0; m < 3; m++)
        #pragma unroll
        for (int i = 0; i < 2; i++)
            #pragma unroll
            for (int j = 0; j < 4; j++)
                #pragma unroll
                for (int k = 0; k < 4; k++)
                    acc[m][i][j][k] = 0.0f;

    auto load_chunk = [&](int ci) {
        const int buf = ci & 1;
        const int k0  = ci * BK;
        #pragma unroll
        for (int i = 0; i < 2; i++) {
            int idx = tid * 2 + i;
            int r   = idx >> 2;
            int seg = idx & 3;
            uint32_t dofs = r * 80 + seg * 16;
            const __half* sh = g_xh + (size_t)(m0 + r) * C + k0 + seg * 8;
            const __half* sl = g_xl + (size_t)(m0 + r) * C + k0 + seg * 8;
            CPA16(sbase + GAH(buf) + dofs, sh);
            CPA16(sbase + GAL(buf) + dofs, sl);
        }
        {
            int r   = tid >> 3;
            int seg = tid & 7;
            uint32_t dofs = r * 144 + seg * 16;
            #pragma unroll
            for (int mat = 0; mat < 3; mat++) {
                const __half* s = g_wh + ((size_t)(mat * H + h)) * C * D
                                 + (size_t)(k0 + r) * D + seg * 8;
                CPA16(sbase + GBW(buf, mat) + dofs, s);
            }
        }
    };

    load_chunk(0); CPC();
    load_chunk(1); CPC();

    for (int ci = 0; ci < NCHUNK; ci++) {
        const int buf = ci & 1;
        if (ci < NCHUNK - 1) { CPW1(); } else { CPW0(); }
        __syncthreads();

        uint32_t ah[2][2][4], al[2][2][4];
        {
            const uint32_t abh = sbase + GAH(buf);
            const uint32_t abl = sbase + GAL(buf);
            #pragma unroll
            for (int mf = 0; mf < 2; mf++) {
                #pragma unroll
                for (int ks = 0; ks < 2; ks++) {
                    int row = wm * 32 + mf * 16 + (lane & 15);
                    int col = ks * 32 + ((lane & 16) ? 16 : 0);
                    uint32_t ao = row * 80 + col;
                    LDMX4(ah[mf][ks][0], ah[mf][ks][1], ah[mf][ks][2], ah[mf][ks][3], abh + ao);
                    LDMX4(al[mf][ks][0], al[mf][ks][1], al[mf][ks][2], al[mf][ks][3], abl + ao);
                }
            }
        }

        #pragma unroll
        for (int mat = 0; mat < 3; mat++) {
            const uint32_t bb = sbase + GBW(buf, mat);
            #pragma unroll
            for (int ks = 0; ks < 2; ks++) {
                #pragma unroll
                for (int nf16 = 0; nf16 < 2; nf16++) {
                    uint32_t b0, b1, b2, b3;
                    int kk = ks * 16 + (lane & 15);
                    int cb = (wn * 32 + nf16 * 16 + ((lane & 16) ? 8 : 0)) * 2;
                    LDMX4T(b0, b1, b2, b3, bb + kk * 144 + cb);
                    #pragma unroll
                    for (int mf = 0; mf < 2; mf++) {
                        float* c0 = acc[mat][mf][nf16 * 2];
                        float* c1 = acc[mat][mf][nf16 * 2 + 1];
                        MMA_F16(c0, ah[mf][ks][0], ah[mf][ks][1], ah[mf][ks][2], ah[mf][ks][3], b0, b1);
                        MMA_F16(c0, al[mf][ks][0], al[mf][ks][1], al[mf][ks][2], al[mf][ks][3], b0, b1);
                        MMA_F16(c1, ah[mf][ks][0], ah[mf][ks][1], ah[mf][ks][2], ah[mf][ks][3], b2, b3);
                        MMA_F16(c1, al[mf][ks][0], al[mf][ks][1], al[mf][ks][2], al[mf][ks][3], b2, b3);
                    }
                }
            }
        }

        __syncthreads();
        if (ci + 2 < NCHUNK) { load_chunk(ci + 2); CPC(); }
    }

    // ---- epilogue: Q fp32; K,V pre-split bf16 hi/lo ----
    const int bb = m0 >> 10;
    #pragma unroll
    for (int mf = 0; mf < 2; mf++) {
        #pragma unroll
        for (int nf = 0; nf < 4; nf++) {
            int row  = wm * 32 + mf * 16 + (lane >> 2);
            int colg = wn * 32 + nf * 8 + (lane & 3) * 2;
            int t    = (m0 + row) & 1023;
            size_t base = (((size_t)(bb * H + h) * T + t) * D) + colg;

            // Q
            {
                const float* c = acc[0][mf][nf];
                *(float2*)(g_q + base) = make_float2(c[0], c[1]);
                *(float2*)(g_q + base + 8 * D) = make_float2(c[2], c[3]);
            }
            // K
            {
                const float* c = acc[1][mf][nf];
                uint32_t hi, lo;
                split_pack2(c[0], c[1], hi, lo);
                *(uint32_t*)(g_kh + base) = hi;
                *(uint32_t*)(g_kl + base) = lo;
                split_pack2(c[2], c[3], hi, lo);
                *(uint32_t*)(g_kh + base + 8 * D) = hi;
                *(uint32_t*)(g_kl + base + 8 * D) = lo;
            }
            // V
            {
                const float* c = acc[2][mf][nf];
                uint32_t hi, lo;
                split_pack2(c[0], c[1], hi, lo);
                *(uint32_t*)(g_vh + base) = hi;
                *(uint32_t*)(g_vl + base) = lo;
                split_pack2(c[2], c[3], hi, lo);
                *(uint32_t*)(g_vh + base + 8 * D) = hi;
                *(uint32_t*)(g_vl + base + 8 * D) = lo;
            }
        }
    }
}

// ===========================================================================
// Kernel 2: causal FlashAttention on mma.sync. K/V tiles arrive PRE-SPLIT
// (bf16 hi/lo) via cp.async 2-stage pipeline — no staging registers, no
// in-loop conversion. Math identical to R6 (same bf16 bits).
// ===========================================================================
#define BRA 128
#define BCA 64
#define AST 144
#define KVT (64 * AST)
#define KHI_OFF(buf) ((buf) * 4 * KVT)
#define KLO_OFF(buf) ((buf) * 4 * KVT + KVT)
#define VHI_OFF(buf) ((buf) * 4 * KVT + 2 * KVT)
#define VLO_OFF(buf) ((buf) * 4 * KVT + 3 * KVT)
#define QLO_OFF (128 * AST)
#define ATT_SMEM (2 * 4 * KVT)

__global__ __launch_bounds__(256)
void flash_attn_mma_kernel(float* __restrict__ out)
{
    extern __shared__ char sm[];
    const uint32_t sbase = smem_u32(sm);

    const int tid  = threadIdx.x;
    const int warp = tid >> 5;
    const int lane = tid & 31;
    const int qt = blockIdx.x;
    const int h  = blockIdx.y;
    const int b  = blockIdx.z;
    const size_t head_base = ((size_t)(b * H + h) * T) * D;
    const int q0 = qt * BRA;

    // ---- Stage Q (pre-scaled) into smem hi/lo; extract persistent frags ----
    {
        const float* qp = g_q + head_base + (size_t)q0 * D;
        #pragma unroll
        for (int it = 0; it < 8; it++) {
            int idx = tid + it * 256;
            int r = idx >> 4, c4 = (idx & 15) * 4;
            float4 v = *(const float4*)(qp + (size_t)r * D + c4);
            v.x *= 0.125f; v.y *= 0.125f; v.z *= 0.125f; v.w *= 0.125f;
            uint32_t off = r * AST + c4 * 2;
            store_split4(sm + off, sm + QLO_OFF + off, v);
        }
    }
    __syncthreads();

    uint32_t qh[4][4], ql[4][4];
    #pragma unroll
    for (int ks = 0; ks < 4; ks++) {
        int row = warp * 16 + (lane & 15);
        int col = ks * 32 + ((lane & 16) ? 16 : 0);
        uint32_t ao = row * AST + col;
        LDMX4(qh[ks][0], qh[ks][1], qh[ks][2], qh[ks][3], sbase + ao);
        LDMX4(ql[ks][0], ql[ks][1], ql[ks][2], ql[ks][3], sbase + QLO_OFF + ao);
    }
    __syncthreads();

    // ---- cp.async tile loader (pre-split K/V, 8 x 16B per thread) ----
    auto load_tile = [&](int kt) {
        const int buf = kt & 1;
        const size_t tb = head_base + (size_t)kt * BCA * D;
        #pragma unroll
        for (int i = 0; i < 2; i++) {
            int idx = tid + i * 256;               // 0..511
            int r   = idx >> 3;                    // 0..63
            int seg = idx & 7;                     // 16B segments
            uint32_t dofs = r * AST + seg * 16;
            size_t so = tb + (size_t)r * D + seg * 8;
            CPA16(sbase + KHI_OFF(buf) + dofs, g_kh + so);
            CPA16(sbase + KLO_OFF(buf) + dofs, g_kl + so);
            CPA16(sbase + VHI_OFF(buf) + dofs, g_vh + so);
            CPA16(sbase + VLO_OFF(buf) + dofs, g_vl + so);
        }
    };

    float o[8][4];
    #pragma unroll
    for (int nf = 0; nf < 8; nf++)
        #pragma unroll
        for (int e = 0; e < 4; e++) o[nf][e] = 0.0f;
    float m0 = -1e30f, m1 = -1e30f, l0 = 0.0f, l1 = 0.0f;

    const int ntiles = 2 * (qt + 1);
    const int rbase  = q0 + warp * 16 + (lane >> 2);

    load_tile(0); CPC();
    if (ntiles > 1) { load_tile(1); CPC(); }

    for (int kt = 0; kt < ntiles; kt++) {
        const int buf = kt & 1;
        if (kt + 1 < ntiles) { CPW1(); } else { CPW0(); }
        __syncthreads();

        // ---- S = Q K^T (3-term) ----
        float sc[8][4];
        #pragma unroll
        for (int nf = 0; nf < 8; nf++)
            #pragma unroll
            for (int e = 0; e < 4; e++) sc[nf][e] = 0.0f;

        const uint32_t khb = sbase + KHI_OFF(buf);
        const uint32_t klb = sbase + KLO_OFF(buf);
        #pragma unroll
        for (int ks = 0; ks < 4; ks++) {
            #pragma unroll
            for (int nf16 = 0; nf16 < 4; nf16++) {
                uint32_t kb0, kb1, kb2, kb3, kc0, kc1, kc2, kc3;
                int row = nf16 * 16 + (lane & 7) + ((lane & 16) ? 8 : 0);
                int col = ks * 32 + ((lane & 8) ? 16 : 0);
                uint32_t o32 = row * AST + col;
                LDMX4(kb0, kb1, kb2, kb3, khb + o32);
                LDMX4(kc0, kc1, kc2, kc3, klb + o32);
                float* c0p = sc[nf16 * 2];
                float* c1p = sc[nf16 * 2 + 1];
                MMA_BF16(c0p, qh[ks][0], qh[ks][1], qh[ks][2], qh[ks][3], kb0, kb1);
                MMA_BF16(c0p, ql[ks][0], ql[ks][1], ql[ks][2], ql[ks][3], kb0, kb1);
                MMA_BF16(c0p, qh[ks][0], qh[ks][1], qh[ks][2], qh[ks][3], kc0, kc1);
                MMA_BF16(c1p, qh[ks][0], qh[ks][1], qh[ks][2], qh[ks][3], kb2, kb3);
                MMA_BF16(c1p, ql[ks][0], ql[ks][1], ql[ks][2], ql[ks][3], kb2, kb3);
                MMA_BF16(c1p, qh[ks][0], qh[ks][1], qh[ks][2], qh[ks][3], kc2, kc3);
            }
        }

        // ---- causal mask on diagonal tiles ----
        if (kt * BCA + 63 > q0 + warp * 16) {
            #pragma unroll
            for (int nf = 0; nf < 8; nf++) {
                int col = kt * BCA + nf * 8 + 2 * (lane & 3);
                if (col     > rbase)     sc[nf][0] = -1e30f;
                if (col + 1 > rbase)     sc[nf][1] = -1e30f;
                if (col     > rbase + 8) sc[nf][2] = -1e30f;
                if (col + 1 > rbase + 8) sc[nf][3] = -1e30f;
            }
        }

        // ---- online softmax ----
        float mt0 = -1e30f, mt1 = -1e30f;
        #pragma unroll
        for (int nf = 0; nf < 8; nf++) {
            mt0 = fmaxf(mt0, fmaxf(sc[nf][0], sc[nf][1]));
            mt1 = fmaxf(mt1, fmaxf(sc[nf][2], sc[nf][3]));
        }
        mt0 = fmaxf(mt0, __shfl_xor_sync(0xFFFFFFFFu, mt0, 1));
        mt0 = fmaxf(mt0, __shfl_xor_sync(0xFFFFFFFFu, mt0, 2));
        mt1 = fmaxf(mt1, __shfl_xor_sync(0xFFFFFFFFu, mt1, 1));
        mt1 = fmaxf(mt1, __shfl_xor_sync(0xFFFFFFFFu, mt1, 2));

        float mn0 = fmaxf(m0, mt0), mn1 = fmaxf(m1, mt1);
        float cr0 = __expf(m0 - mn0), cr1 = __expf(m1 - mn1);
        l0 *= cr0; l1 *= cr1;
        #pragma unroll
        for (int nf = 0; nf < 8; nf++) {
            o[nf][0] *= cr0; o[nf][1] *= cr0;
            o[nf][2] *= cr1; o[nf][3] *= cr1;
            sc[nf][0] = __expf(sc[nf][0] - mn0);
            sc[nf][1] = __expf(sc[nf][1] - mn0);
            sc[nf][2] = __expf(sc[nf][2] - mn1);
            sc[nf][3] = __expf(sc[nf][3] - mn1);
            l0 += sc[nf][0] + sc[nf][1];
            l1 += sc[nf][2] + sc[nf][3];
        }
        m0 = mn0; m1 = mn1;

        // ---- O += P V (3-term) ----
        const uint32_t vhb = sbase + VHI_OFF(buf);
        const uint32_t vlb = sbase + VLO_OFF(buf);
        #pragma unroll
        for (int ks = 0; ks < 4; ks++) {
            uint32_t ph[4], pl[4];
            split_pack2(sc[2 * ks][0],     sc[2 * ks][1],     ph[0], pl[0]);
            split_pack2(sc[2 * ks][2],     sc[2 * ks][3],     ph[1], pl[1]);
            split_pack2(sc[2 * ks + 1][0], sc[2 * ks + 1][1], ph[2], pl[2]);
            split_pack2(sc[2 * ks + 1][2], sc[2 * ks + 1][3], ph[3], pl[3]);
            #pragma unroll
            for (int nf16 = 0; nf16 < 4; nf16++) {
                uint32_t vb0, vb1, vb2, vb3, vc0, vc1, vc2, vc3;
                int kk = ks * 16 + ((lane & 8) ? 8 : 0) + (lane & 7);
                int cb = (nf16 * 16 + ((lane & 16) ? 8 : 0)) * 2;
                uint32_t o32 = kk * AST + cb;
                LDMX4T(vb0, vb1, vb2, vb3, vhb + o32);
                LDMX4T(vc0, vc1, vc2, vc3, vlb + o32);
                float* c0p = o[nf16 * 2];
                float* c1p = o[nf16 * 2 + 1];
                MMA_BF16(c0p, ph[0], ph[1], ph[2], ph[3], vb0, vb1);
                MMA_BF16(c0p, pl[0], pl[1], pl[2], pl[3], vb0, vb1);
                MMA_BF16(c0p, ph[0], ph[1], ph[2], ph[3], vc0, vc1);
                MMA_BF16(c1p, ph[0], ph[1], ph[2], ph[3], vb2, vb3);
                MMA_BF16(c1p, pl[0], pl[1], pl[2], pl[3], vb2, vb3);
                MMA_BF16(c1p, ph[0], ph[1], ph[2], ph[3], vc2, vc3);
            }
        }

        __syncthreads();
        if (kt + 2 < ntiles) { load_tile(kt + 2); CPC(); }
    }

    l0 += __shfl_xor_sync(0xFFFFFFFFu, l0, 1);
    l0 += __shfl_xor_sync(0xFFFFFFFFu, l0, 2);
    l1 += __shfl_xor_sync(0xFFFFFFFFu, l1, 1);
    l1 += __shfl_xor_sync(0xFFFFFFFFu, l1, 2);
    const float i0 = 1.0f / l0;
    const float i1 = 1.0f / l1;

    float* op = out + ((size_t)(b * T + rbase) * (H * D)) + h * D;
    #pragma unroll
    for (int nf = 0; nf < 8; nf++) {
        int col = nf * 8 + 2 * (lane & 3);
        *(float2*)(op + col) = make_float2(o[nf][0] * i0, o[nf][1] * i0);
        *(float2*)(op + (size_t)8 * (H * D) + col) = make_float2(o[nf][2] * i1, o[nf][3] * i1);
    }
}

// ===========================================================================
extern "C" void kernel_launch(void* const* d_in, const int* in_sizes, int n_in,
                              void* d_out, int out_size)
{
    const float* x  = (const float*)d_in[0];   // [B, T, C]
    const float* Wq = (const float*)d_in[1];   // [H, C, D]
    const float* Wk = (const float*)d_in[2];
    const float* Wv = (const float*)d_in[3];
    float* out = (float*)d_out;                 // [B, T, H*D]

    (void)in_sizes; (void)n_in; (void)out_size;

    static int smem_set = 0;
    if (!smem_set) {
        cudaFuncSetAttribute(qkv_fp16_kernel,
                             cudaFuncAttributeMaxDynamicSharedMemorySize, G_SMEM);
        cudaFuncSetAttribute(flash_attn_mma_kernel,
                             cudaFuncAttributeMaxDynamicSharedMemorySize, ATT_SMEM);
        smem_set = 1;
    }

    split_x_kernel<<<(size_t)B * T * C / 1024, 256>>>(x);
    conv_w_kernel<<<dim3(H * C * D / 1024, 3), 256>>>(Wq, Wk, Wv);

    dim3 gemm_grid(T * B / 128, H);             // 64 x 16
    qkv_fp16_kernel<<<gemm_grid, 256, G_SMEM>>>();

    dim3 attn_grid(T / BRA, H, B);              // 8 x 16 x 8
    flash_attn_mma_kernel<<<attn_grid, 256, ATT_SMEM>>>(out);
}

// round 9
// speedup vs baseline: 4.1236x; 1.1347x over previous
#include <cuda_runtime.h>
#include <cuda_bf16.h>
#include <cuda_fp16.h>
#include <math.h>
#include <stdint.h>

// Problem constants
#define B 8
#define T 1024
#define C 1024
#define H 16
#define D 64

// Scratch: Q pre-scaled fp16 hi/lo; K/V single fp16; x split fp16; W fp16
__device__ __half g_qh[(size_t)B * H * T * D];
__device__ __half g_ql[(size_t)B * H * T * D];
__device__ __half g_kf[(size_t)B * H * T * D];
__device__ __half g_vf[(size_t)B * H * T * D];
__device__ __half g_xh[(size_t)B * T * C];
__device__ __half g_xl[(size_t)B * T * C];
__device__ __half g_wh[(size_t)3 * H * C * D];

// ===========================================================================
// Helpers
// ===========================================================================
__device__ __forceinline__ uint32_t smem_u32(const void* p) {
    uint32_t a;
    asm("{ .reg .u64 t; cvta.to.shared.u64 t, %1; cvt.u32.u64 %0, t; }"
        : "=r"(a) : "l"(p));
    return a;
}

#define LDMX4(r0, r1, r2, r3, addr)                                           \
    asm volatile("ldmatrix.sync.aligned.m8n8.x4.shared.b16 {%0,%1,%2,%3}, [%4];" \
                 : "=r"(r0), "=r"(r1), "=r"(r2), "=r"(r3) : "r"(addr))

#define LDMX4T(r0, r1, r2, r3, addr)                                          \
    asm volatile("ldmatrix.sync.aligned.m8n8.x4.trans.shared.b16 {%0,%1,%2,%3}, [%4];" \
                 : "=r"(r0), "=r"(r1), "=r"(r2), "=r"(r3) : "r"(addr))

#define MMA_F16(c, a0, a1, a2, a3, b0, b1)                                    \
    asm volatile("mma.sync.aligned.m16n8k16.row.col.f32.f16.f16.f32 "         \
                 "{%0,%1,%2,%3}, {%4,%5,%6,%7}, {%8,%9}, {%0,%1,%2,%3};"      \
                 : "+f"((c)[0]), "+f"((c)[1]), "+f"((c)[2]), "+f"((c)[3])     \
                 : "r"(a0), "r"(a1), "r"(a2), "r"(a3), "r"(b0), "r"(b1))

#define CPA16(dst, src) \
    asm volatile("cp.async.cg.shared.global [%0], [%1], 16;" :: "r"(dst), "l"(src))
#define CPC()  asm volatile("cp.async.commit_group;" ::: "memory")
#define CPW0() asm volatile("cp.async.wait_group 0;" ::: "memory")
#define CPW1() asm volatile("cp.async.wait_group 1;" ::: "memory")

__device__ __forceinline__ uint32_t pack_h2(__half a, __half b) {
    __half2 h = __halves2half2(a, b);
    return *(uint32_t*)&h;
}

// fp16 hi/lo split of a pair, packed
__device__ __forceinline__ void split_pack2h(float a, float b, uint32_t& hi, uint32_t& lo) {
    __half ha = __float2half_rn(a), hb = __float2half_rn(b);
    __half la = __float2half_rn(a - __half2float(ha));
    __half lb = __float2half_rn(b - __half2float(hb));
    hi = pack_h2(ha, hb);
    lo = pack_h2(la, lb);
}

// ===========================================================================
// Kernel 0a: split x into fp16 hi/lo (exact to ~2^-22)
// ===========================================================================
__global__ __launch_bounds__(256) void split_x_kernel(const float* __restrict__ x)
{
    size_t i = ((size_t)blockIdx.x * 256 + threadIdx.x) * 4;
    float4 v = *(const float4*)(x + i);
    __half hx = __float2half_rn(v.x), hy = __float2half_rn(v.y);
    __half hz = __float2half_rn(v.z), hw = __float2half_rn(v.w);
    __half lx = __float2half_rn(v.x - __half2float(hx));
    __half ly = __float2half_rn(v.y - __half2float(hy));
    __half lz = __float2half_rn(v.z - __half2float(hz));
    __half lw = __float2half_rn(v.w - __half2float(hw));
    *(uint2*)(g_xh + i) = make_uint2(pack_h2(hx, hy), pack_h2(hz, hw));
    *(uint2*)(g_xl + i) = make_uint2(pack_h2(lx, ly), pack_h2(lz, lw));
}

// ===========================================================================
// Kernel 0b: convert W to fp16 (single rounding)
// ===========================================================================
__global__ __launch_bounds__(256) void conv_w_kernel(const float* __restrict__ Wq,
                                                     const float* __restrict__ Wk,
                                                     const float* __restrict__ Wv)
{
    const int mat = blockIdx.y;
    const float* W = (mat == 0) ? Wq : (mat == 1) ? Wk : Wv;
    size_t i = ((size_t)blockIdx.x * 256 + threadIdx.x) * 4;
    float4 v = *(const float4*)(W + i);
    *(uint2*)(g_wh + (size_t)mat * H * C * D + i) = make_uint2(
        pack_h2(__float2half_rn(v.x), __float2half_rn(v.y)),
        pack_h2(__float2half_rn(v.z), __float2half_rn(v.w)));
}

// ===========================================================================
// Kernel 1: QKV projections, fp16 2-term split, cp.async double-buffered.
// Epilogue: Q -> pre-scaled fp16 hi/lo split; K,V -> single fp16.
// ===========================================================================
#define BK 32
#define NCHUNK (C / BK)
#define GBUF 34304
#define GAH(buf)       ((buf) * GBUF)
#define GAL(buf)       ((buf) * GBUF + 10240)
#define GBW(buf, mat)  ((buf) * GBUF + 20480 + (mat) * 4608)
#define G_SMEM (2 * GBUF)     // 68608

__global__ __launch_bounds__(256)
void qkv_fp16_kernel()
{
    extern __shared__ char sm[];
    const uint32_t sbase = smem_u32(sm);

    const int tid  = threadIdx.x;
    const int warp = tid >> 5;
    const int lane = tid & 31;
    const int wm   = warp >> 1;
    const int wn   = warp & 1;

    const int m0 = blockIdx.x * 128;
    const int h  = blockIdx.y;

    float acc[3][2][4][4];
    #pragma unroll
    for (int m = 0; m < 3; m++)
        #pragma unroll
        for (int i = 0; i < 2; i++)
            #pragma unroll
            for (int j = 0; j < 4; j++)
                #pragma unroll
                for (int k = 0; k < 4; k++)
                    acc[m][i][j][k] = 0.0f;

    auto load_chunk = [&](int ci) {
        const int buf = ci & 1;
        const int k0  = ci * BK;
        #pragma unroll
        for (int i = 0; i < 2; i++) {
            int idx = tid * 2 + i;
            int r   = idx >> 2;
            int seg = idx & 3;
            uint32_t dofs = r * 80 + seg * 16;
            const __half* sh = g_xh + (size_t)(m0 + r) * C + k0 + seg * 8;
            const __half* sl = g_xl + (size_t)(m0 + r) * C + k0 + seg * 8;
            CPA16(sbase + GAH(buf) + dofs, sh);
            CPA16(sbase + GAL(buf) + dofs, sl);
        }
        {
            int r   = tid >> 3;
            int seg = tid & 7;
            uint32_t dofs = r * 144 + seg * 16;
            #pragma unroll
            for (int mat = 0; mat < 3; mat++) {
                const __half* s = g_wh + ((size_t)(mat * H + h)) * C * D
                                 + (size_t)(k0 + r) * D + seg * 8;
                CPA16(sbase + GBW(buf, mat) + dofs, s);
            }
        }
    };

    load_chunk(0); CPC();
    load_chunk(1); CPC();

    for (int ci = 0; ci < NCHUNK; ci++) {
        const int buf = ci & 1;
        if (ci < NCHUNK - 1) { CPW1(); } else { CPW0(); }
        __syncthreads();

        uint32_t ah[2][2][4], al[2][2][4];
        {
            const uint32_t abh = sbase + GAH(buf);
            const uint32_t abl = sbase + GAL(buf);
            #pragma unroll
            for (int mf = 0; mf < 2; mf++) {
                #pragma unroll
                for (int ks = 0; ks < 2; ks++) {
                    int row = wm * 32 + mf * 16 + (lane & 15);
                    int col = ks * 32 + ((lane & 16) ? 16 : 0);
                    uint32_t ao = row * 80 + col;
                    LDMX4(ah[mf][ks][0], ah[mf][ks][1], ah[mf][ks][2], ah[mf][ks][3], abh + ao);
                    LDMX4(al[mf][ks][0], al[mf][ks][1], al[mf][ks][2], al[mf][ks][3], abl + ao);
                }
            }
        }

        #pragma unroll
        for (int mat = 0; mat < 3; mat++) {
            const uint32_t bb = sbase + GBW(buf, mat);
            #pragma unroll
            for (int ks = 0; ks < 2; ks++) {
                #pragma unroll
                for (int nf16 = 0; nf16 < 2; nf16++) {
                    uint32_t b0, b1, b2, b3;
                    int kk = ks * 16 + (lane & 15);
                    int cb = (wn * 32 + nf16 * 16 + ((lane & 16) ? 8 : 0)) * 2;
                    LDMX4T(b0, b1, b2, b3, bb + kk * 144 + cb);
                    #pragma unroll
                    for (int mf = 0; mf < 2; mf++) {
                        float* c0 = acc[mat][mf][nf16 * 2];
                        float* c1 = acc[mat][mf][nf16 * 2 + 1];
                        MMA_F16(c0, ah[mf][ks][0], ah[mf][ks][1], ah[mf][ks][2], ah[mf][ks][3], b0, b1);
                        MMA_F16(c0, al[mf][ks][0], al[mf][ks][1], al[mf][ks][2], al[mf][ks][3], b0, b1);
                        MMA_F16(c1, ah[mf][ks][0], ah[mf][ks][1], ah[mf][ks][2], ah[mf][ks][3], b2, b3);
                        MMA_F16(c1, al[mf][ks][0], al[mf][ks][1], al[mf][ks][2], al[mf][ks][3], b2, b3);
                    }
                }
            }
        }

        __syncthreads();
        if (ci + 2 < NCHUNK) { load_chunk(ci + 2); CPC(); }
    }

    // ---- epilogue: Q pre-scaled fp16 hi/lo; K,V single fp16 ----
    const int bb = m0 >> 10;
    #pragma unroll
    for (int mf = 0; mf < 2; mf++) {
        #pragma unroll
        for (int nf = 0; nf < 4; nf++) {
            int row  = wm * 32 + mf * 16 + (lane >> 2);
            int colg = wn * 32 + nf * 8 + (lane & 3) * 2;
            int t    = (m0 + row) & 1023;
            size_t base = (((size_t)(bb * H + h) * T + t) * D) + colg;

            // Q: scale by D^-0.5, split fp16 hi/lo
            {
                const float* c = acc[0][mf][nf];
                uint32_t hi, lo;
                split_pack2h(c[0] * 0.125f, c[1] * 0.125f, hi, lo);
                *(uint32_t*)(g_qh + base) = hi;
                *(uint32_t*)(g_ql + base) = lo;
                split_pack2h(c[2] * 0.125f, c[3] * 0.125f, hi, lo);
                *(uint32_t*)(g_qh + base + 8 * D) = hi;
                *(uint32_t*)(g_ql + base + 8 * D) = lo;
            }
            // K single fp16
            {
                const float* c = acc[1][mf][nf];
                *(uint32_t*)(g_kf + base) =
                    pack_h2(__float2half_rn(c[0]), __float2half_rn(c[1]));
                *(uint32_t*)(g_kf + base + 8 * D) =
                    pack_h2(__float2half_rn(c[2]), __float2half_rn(c[3]));
            }
            // V single fp16
            {
                const float* c = acc[2][mf][nf];
                *(uint32_t*)(g_vf + base) =
                    pack_h2(__float2half_rn(c[0]), __float2half_rn(c[1]));
                *(uint32_t*)(g_vf + base + 8 * D) =
                    pack_h2(__float2half_rn(c[2]), __float2half_rn(c[3]));
            }
        }
    }
}

// ===========================================================================
// Kernel 2: causal FlashAttention. Q arrives pre-split fp16 hi/lo; K/V single
// fp16. S = Qh K + Ql K; O += Ph V + Pl V (P split fp16, exact). All operand
// staging via cp.async; no in-loop conversion except the P split.
// ===========================================================================
#define BRA 128
#define BCA 64
#define AST 144
#define KVT (64 * AST)            // 9216
#define KF_OFF(buf) ((buf) * 2 * KVT)
#define VF_OFF(buf) ((buf) * 2 * KVT + KVT)
#define QH_OFF 0
#define QL_OFF (128 * AST)        // 18432
#define ATT_SMEM (4 * KVT)        // 36864 (Q staging reuses tile region)

__global__ __launch_bounds__(256)
void flash_attn_mma_kernel(float* __restrict__ out)
{
    extern __shared__ char sm[];
    const uint32_t sbase = smem_u32(sm);

    const int tid  = threadIdx.x;
    const int warp = tid >> 5;
    const int lane = tid & 31;
    const int qt = blockIdx.x;
    const int h  = blockIdx.y;
    const int b  = blockIdx.z;
    const size_t head_base = ((size_t)(b * H + h) * T) * D;
    const int q0 = qt * BRA;

    // ---- Stage Q hi/lo via cp.async (no conversion) ----
    {
        const __half* qhp = g_qh + head_base + (size_t)q0 * D;
        const __half* qlp = g_ql + head_base + (size_t)q0 * D;
        #pragma unroll
        for (int it = 0; it < 4; it++) {
            int idx = tid + it * 256;              // 0..1023
            int r   = idx >> 3;                    // 0..127
            int seg = idx & 7;
            uint32_t dofs = r * AST + seg * 16;
            CPA16(sbase + QH_OFF + dofs, qhp + (size_t)r * D + seg * 8);
            CPA16(sbase + QL_OFF + dofs, qlp + (size_t)r * D + seg * 8);
        }
        CPC(); CPW0();
    }
    __syncthreads();

    uint32_t qh[4][4], ql[4][4];
    #pragma unroll
    for (int ks = 0; ks < 4; ks++) {
        int row = warp * 16 + (lane & 15);
        int col = ks * 32 + ((lane & 16) ? 16 : 0);
        uint32_t ao = row * AST + col;
        LDMX4(qh[ks][0], qh[ks][1], qh[ks][2], qh[ks][3], sbase + QH_OFF + ao);
        LDMX4(ql[ks][0], ql[ks][1], ql[ks][2], ql[ks][3], sbase + QL_OFF + ao);
    }
    __syncthreads();

    // ---- cp.async K/V tile loader (single fp16) ----
    auto load_tile = [&](int kt) {
        const int buf = kt & 1;
        const size_t tb = head_base + (size_t)kt * BCA * D;
        #pragma unroll
        for (int i = 0; i < 2; i++) {
            int idx = tid + i * 256;               // 0..511
            int r   = idx >> 3;                    // 0..63
            int seg = idx & 7;
            uint32_t dofs = r * AST + seg * 16;
            size_t so = tb + (size_t)r * D + seg * 8;
            CPA16(sbase + KF_OFF(buf) + dofs, g_kf + so);
            CPA16(sbase + VF_OFF(buf) + dofs, g_vf + so);
        }
    };

    float o[8][4];
    #pragma unroll
    for (int nf = 0; nf < 8; nf++)
        #pragma unroll
        for (int e = 0; e < 4; e++) o[nf][e] = 0.0f;
    float m0 = -1e30f, m1 = -1e30f, l0 = 0.0f, l1 = 0.0f;

    const int ntiles = 2 * (qt + 1);
    const int rbase  = q0 + warp * 16 + (lane >> 2);

    load_tile(0); CPC();
    if (ntiles > 1) { load_tile(1); CPC(); }

    for (int kt = 0; kt < ntiles; kt++) {
        const int buf = kt & 1;
        if (kt + 1 < ntiles) { CPW1(); } else { CPW0(); }
        __syncthreads();

        // ---- S = Qh K + Ql K ----
        float sc[8][4];
        #pragma unroll
        for (int nf = 0; nf < 8; nf++)
            #pragma unroll
            for (int e = 0; e < 4; e++) sc[nf][e] = 0.0f;

        const uint32_t kfb = sbase + KF_OFF(buf);
        #pragma unroll
        for (int ks = 0; ks < 4; ks++) {
            #pragma unroll
            for (int nf16 = 0; nf16 < 4; nf16++) {
                uint32_t kb0, kb1, kb2, kb3;
                int row = nf16 * 16 + (lane & 7) + ((lane & 16) ? 8 : 0);
                int col = ks * 32 + ((lane & 8) ? 16 : 0);
                uint32_t o32 = row * AST + col;
                LDMX4(kb0, kb1, kb2, kb3, kfb + o32);
                float* c0p = sc[nf16 * 2];
                float* c1p = sc[nf16 * 2 + 1];
                MMA_F16(c0p, qh[ks][0], qh[ks][1], qh[ks][2], qh[ks][3], kb0, kb1);
                MMA_F16(c0p, ql[ks][0], ql[ks][1], ql[ks][2], ql[ks][3], kb0, kb1);
                MMA_F16(c1p, qh[ks][0], qh[ks][1], qh[ks][2], qh[ks][3], kb2, kb3);
                MMA_F16(c1p, ql[ks][0], ql[ks][1], ql[ks][2], ql[ks][3], kb2, kb3);
            }
        }

        // ---- causal mask on diagonal tiles ----
        if (kt * BCA + 63 > q0 + warp * 16) {
            #pragma unroll
            for (int nf = 0; nf < 8; nf++) {
                int col = kt * BCA + nf * 8 + 2 * (lane & 3);
                if (col     > rbase)     sc[nf][0] = -1e30f;
                if (col + 1 > rbase)     sc[nf][1] = -1e30f;
                if (col     > rbase + 8) sc[nf][2] = -1e30f;
                if (col + 1 > rbase + 8) sc[nf][3] = -1e30f;
            }
        }

        // ---- online softmax ----
        float mt0 = -1e30f, mt1 = -1e30f;
        #pragma unroll
        for (int nf = 0; nf < 8; nf++) {
            mt0 = fmaxf(mt0, fmaxf(sc[nf][0], sc[nf][1]));
            mt1 = fmaxf(mt1, fmaxf(sc[nf][2], sc[nf][3]));
        }
        mt0 = fmaxf(mt0, __shfl_xor_sync(0xFFFFFFFFu, mt0, 1));
        mt0 = fmaxf(mt0, __shfl_xor_sync(0xFFFFFFFFu, mt0, 2));
        mt1 = fmaxf(mt1, __shfl_xor_sync(0xFFFFFFFFu, mt1, 1));
        mt1 = fmaxf(mt1, __shfl_xor_sync(0xFFFFFFFFu, mt1, 2));

        float mn0 = fmaxf(m0, mt0), mn1 = fmaxf(m1, mt1);
        float cr0 = __expf(m0 - mn0), cr1 = __expf(m1 - mn1);
        l0 *= cr0; l1 *= cr1;
        #pragma unroll
        for (int nf = 0; nf < 8; nf++) {
            o[nf][0] *= cr0; o[nf][1] *= cr0;
            o[nf][2] *= cr1; o[nf][3] *= cr1;
            sc[nf][0] = __expf(sc[nf][0] - mn0);
            sc[nf][1] = __expf(sc[nf][1] - mn0);
            sc[nf][2] = __expf(sc[nf][2] - mn1);
            sc[nf][3] = __expf(sc[nf][3] - mn1);
            l0 += sc[nf][0] + sc[nf][1];
            l1 += sc[nf][2] + sc[nf][3];
        }
        m0 = mn0; m1 = mn1;

        // ---- O += Ph V + Pl V ----
        const uint32_t vfb = sbase + VF_OFF(buf);
        #pragma unroll
        for (int ks = 0; ks < 4; ks++) {
            uint32_t ph[4], pl[4];
            split_pack2h(sc[2 * ks][0],     sc[2 * ks][1],     ph[0], pl[0]);
            split_pack2h(sc[2 * ks][2],     sc[2 * ks][3],     ph[1], pl[1]);
            split_pack2h(sc[2 * ks + 1][0], sc[2 * ks + 1][1], ph[2], pl[2]);
            split_pack2h(sc[2 * ks + 1][2], sc[2 * ks + 1][3], ph[3], pl[3]);
            #pragma unroll
            for (int nf16 = 0; nf16 < 4; nf16++) {
                uint32_t vb0, vb1, vb2, vb3;
                int kk = ks * 16 + ((lane & 8) ? 8 : 0) + (lane & 7);
                int cb = (nf16 * 16 + ((lane & 16) ? 8 : 0)) * 2;
                uint32_t o32 = kk * AST + cb;
                LDMX4T(vb0, vb1, vb2, vb3, vfb + o32);
                float* c0p = o[nf16 * 2];
                float* c1p = o[nf16 * 2 + 1];
                MMA_F16(c0p, ph[0], ph[1], ph[2], ph[3], vb0, vb1);
                MMA_F16(c0p, pl[0], pl[1], pl[2], pl[3], vb0, vb1);
                MMA_F16(c1p, ph[0], ph[1], ph[2], ph[3], vb2, vb3);
                MMA_F16(c1p, pl[0], pl[1], pl[2], pl[3], vb2, vb3);
            }
        }

        __syncthreads();
        if (kt + 2 < ntiles) { load_tile(kt + 2); CPC(); }
    }

    l0 += __shfl_xor_sync(0xFFFFFFFFu, l0, 1);
    l0 += __shfl_xor_sync(0xFFFFFFFFu, l0, 2);
    l1 += __shfl_xor_sync(0xFFFFFFFFu, l1, 1);
    l1 += __shfl_xor_sync(0xFFFFFFFFu, l1, 2);
    const float i0 = 1.0f / l0;
    const float i1 = 1.0f / l1;

    float* op = out + ((size_t)(b * T + rbase) * (H * D)) + h * D;
    #pragma unroll
    for (int nf = 0; nf < 8; nf++) {
        int col = nf * 8 + 2 * (lane & 3);
        *(float2*)(op + col) = make_float2(o[nf][0] * i0, o[nf][1] * i0);
        *(float2*)(op + (size_t)8 * (H * D) + col) = make_float2(o[nf][2] * i1, o[nf][3] * i1);
    }
}

// ===========================================================================
extern "C" void kernel_launch(void* const* d_in, const int* in_sizes, int n_in,
                              void* d_out, int out_size)
{
    const float* x  = (const float*)d_in[0];   // [B, T, C]
    const float* Wq = (const float*)d_in[1];   // [H, C, D]
    const float* Wk = (const float*)d_in[2];
    const float* Wv = (const float*)d_in[3];
    float* out = (float*)d_out;                 // [B, T, H*D]

    (void)in_sizes; (void)n_in; (void)out_size;

    static int smem_set = 0;
    if (!smem_set) {
        cudaFuncSetAttribute(qkv_fp16_kernel,
                             cudaFuncAttributeMaxDynamicSharedMemorySize, G_SMEM);
        cudaFuncSetAttribute(flash_attn_mma_kernel,
                             cudaFuncAttributeMaxDynamicSharedMemorySize, ATT_SMEM);
        smem_set = 1;
    }

    split_x_kernel<<<(size_t)B * T * C / 1024, 256>>>(x);
    conv_w_kernel<<<dim3(H * C * D / 1024, 3), 256>>>(Wq, Wk, Wv);

    dim3 gemm_grid(T * B / 128, H);             // 64 x 16
    qkv_fp16_kernel<<<gemm_grid, 256, G_SMEM>>>();

    dim3 attn_grid(T / BRA, H, B);              // 8 x 16 x 8
    flash_attn_mma_kernel<<<attn_grid, 256, ATT_SMEM>>>(out);
}

// round 10
// speedup vs baseline: 4.1457x; 1.0054x over previous
#include <cuda_runtime.h>
#include <cuda_bf16.h>
#include <cuda_fp16.h>
#include <math.h>
#include <stdint.h>

// Problem constants
#define B 8
#define T 1024
#define C 1024
#define H 16
#define D 64

// Scratch: Q pre-scaled fp16 hi/lo; K/V single fp16; x split fp16; W fp16
__device__ __half g_qh[(size_t)B * H * T * D];
__device__ __half g_ql[(size_t)B * H * T * D];
__device__ __half g_kf[(size_t)B * H * T * D];
__device__ __half g_vf[(size_t)B * H * T * D];
__device__ __half g_xh[(size_t)B * T * C];
__device__ __half g_xl[(size_t)B * T * C];
__device__ __half g_wh[(size_t)3 * H * C * D];

// ===========================================================================
// Helpers
// ===========================================================================
__device__ __forceinline__ uint32_t smem_u32(const void* p) {
    uint32_t a;
    asm("{ .reg .u64 t; cvta.to.shared.u64 t, %1; cvt.u32.u64 %0, t; }"
        : "=r"(a) : "l"(p));
    return a;
}

#define LDMX4(r0, r1, r2, r3, addr)                                           \
    asm volatile("ldmatrix.sync.aligned.m8n8.x4.shared.b16 {%0,%1,%2,%3}, [%4];" \
                 : "=r"(r0), "=r"(r1), "=r"(r2), "=r"(r3) : "r"(addr))

#define LDMX4T(r0, r1, r2, r3, addr)                                          \
    asm volatile("ldmatrix.sync.aligned.m8n8.x4.trans.shared.b16 {%0,%1,%2,%3}, [%4];" \
                 : "=r"(r0), "=r"(r1), "=r"(r2), "=r"(r3) : "r"(addr))

#define MMA_F16(c, a0, a1, a2, a3, b0, b1)                                    \
    asm volatile("mma.sync.aligned.m16n8k16.row.col.f32.f16.f16.f32 "         \
                 "{%0,%1,%2,%3}, {%4,%5,%6,%7}, {%8,%9}, {%0,%1,%2,%3};"      \
                 : "+f"((c)[0]), "+f"((c)[1]), "+f"((c)[2]), "+f"((c)[3])     \
                 : "r"(a0), "r"(a1), "r"(a2), "r"(a3), "r"(b0), "r"(b1))

#define CPA16(dst, src) \
    asm volatile("cp.async.cg.shared.global [%0], [%1], 16;" :: "r"(dst), "l"(src))
#define CPC()  asm volatile("cp.async.commit_group;" ::: "memory")
#define CPW0() asm volatile("cp.async.wait_group 0;" ::: "memory")
#define CPW1() asm volatile("cp.async.wait_group 1;" ::: "memory")

__device__ __forceinline__ uint32_t pack_h2(__half a, __half b) {
    __half2 h = __halves2half2(a, b);
    return *(uint32_t*)&h;
}

// fp16 hi/lo split of a pair, packed
__device__ __forceinline__ void split_pack2h(float a, float b, uint32_t& hi, uint32_t& lo) {
    __half ha = __float2half_rn(a), hb = __float2half_rn(b);
    __half la = __float2half_rn(a - __half2float(ha));
    __half lb = __float2half_rn(b - __half2float(hb));
    hi = pack_h2(ha, hb);
    lo = pack_h2(la, lb);
}

// ===========================================================================
// Kernel 0a: split x into fp16 hi/lo (exact to ~2^-22)
// ===========================================================================
__global__ __launch_bounds__(256) void split_x_kernel(const float* __restrict__ x)
{
    size_t i = ((size_t)blockIdx.x * 256 + threadIdx.x) * 4;
    float4 v = *(const float4*)(x + i);
    __half hx = __float2half_rn(v.x), hy = __float2half_rn(v.y);
    __half hz = __float2half_rn(v.z), hw = __float2half_rn(v.w);
    __half lx = __float2half_rn(v.x - __half2float(hx));
    __half ly = __float2half_rn(v.y - __half2float(hy));
    __half lz = __float2half_rn(v.z - __half2float(hz));
    __half lw = __float2half_rn(v.w - __half2float(hw));
    *(uint2*)(g_xh + i) = make_uint2(pack_h2(hx, hy), pack_h2(hz, hw));
    *(uint2*)(g_xl + i) = make_uint2(pack_h2(lx, ly), pack_h2(lz, lw));
}

// ===========================================================================
// Kernel 0b: convert W to fp16 (single rounding)
// ===========================================================================
__global__ __launch_bounds__(256) void conv_w_kernel(const float* __restrict__ Wq,
                                                     const float* __restrict__ Wk,
                                                     const float* __restrict__ Wv)
{
    const int mat = blockIdx.y;
    const float* W = (mat == 0) ? Wq : (mat == 1) ? Wk : Wv;
    size_t i = ((size_t)blockIdx.x * 256 + threadIdx.x) * 4;
    float4 v = *(const float4*)(W + i);
    *(uint2*)(g_wh + (size_t)mat * H * C * D + i) = make_uint2(
        pack_h2(__float2half_rn(v.x), __float2half_rn(v.y)),
        pack_h2(__float2half_rn(v.z), __float2half_rn(v.w)));
}

// ===========================================================================
// Kernel 1: QKV projections, fp16 2-term split.
// 3-stage cp.async pipeline, ONE __syncthreads per chunk, loads for chunk
// i+2 issued BEFORE compute of chunk i (the barrier already protects the
// target buffer: it was consumed at i-1).
// Epilogue: Q -> pre-scaled fp16 hi/lo split; K,V -> single fp16.
// ===========================================================================
#define BK 32
#define NCHUNK (C / BK)
#define GBUF 34304
#define GAH(buf)       ((buf) * GBUF)
#define GAL(buf)       ((buf) * GBUF + 10240)
#define GBW(buf, mat)  ((buf) * GBUF + 20480 + (mat) * 4608)
#define G_SMEM (3 * GBUF)     // 102912

__global__ __launch_bounds__(256)
void qkv_fp16_kernel()
{
    extern __shared__ char sm[];
    const uint32_t sbase = smem_u32(sm);

    const int tid  = threadIdx.x;
    const int warp = tid >> 5;
    const int lane = tid & 31;
    const int wm   = warp >> 1;
    const int wn   = warp & 1;

    const int m0 = blockIdx.x * 128;
    const int h  = blockIdx.y;

    float acc[3][2][4][4];
    #pragma unroll
    for (int m = 0; m < 3; m++)
        #pragma unroll
        for (int i = 0; i < 2; i++)
            #pragma unroll
            for (int j = 0; j < 4; j++)
                #pragma unroll
                for (int k = 0; k < 4; k++)
                    acc[m][i][j][k] = 0.0f;

    auto load_chunk = [&](int ci) {
        const int buf = ci % 3;
        const int k0  = ci * BK;
        #pragma unroll
        for (int i = 0; i < 2; i++) {
            int idx = tid * 2 + i;
            int r   = idx >> 2;
            int seg = idx & 3;
            uint32_t dofs = r * 80 + seg * 16;
            const __half* sh = g_xh + (size_t)(m0 + r) * C + k0 + seg * 8;
            const __half* sl = g_xl + (size_t)(m0 + r) * C + k0 + seg * 8;
            CPA16(sbase + GAH(buf) + dofs, sh);
            CPA16(sbase + GAL(buf) + dofs, sl);
        }
        {
            int r   = tid >> 3;
            int seg = tid & 7;
            uint32_t dofs = r * 144 + seg * 16;
            #pragma unroll
            for (int mat = 0; mat < 3; mat++) {
                const __half* s = g_wh + ((size_t)(mat * H + h)) * C * D
                                 + (size_t)(k0 + r) * D + seg * 8;
                CPA16(sbase + GBW(buf, mat) + dofs, s);
            }
        }
    };

    load_chunk(0); CPC();
    load_chunk(1); CPC();

    for (int ci = 0; ci < NCHUNK; ci++) {
        const int buf = ci % 3;
        if (ci < NCHUNK - 1) { CPW1(); } else { CPW0(); }
        __syncthreads();

        // Prefetch chunk ci+2 into the buffer consumed at ci-1 (barrier-safe),
        // BEFORE compute so the loads overlap the MMA block.
        if (ci + 2 < NCHUNK) { load_chunk(ci + 2); CPC(); }

        uint32_t ah[2][2][4], al[2][2][4];
        {
            const uint32_t abh = sbase + GAH(buf);
            const uint32_t abl = sbase + GAL(buf);
            #pragma unroll
            for (int mf = 0; mf < 2; mf++) {
                #pragma unroll
                for (int ks = 0; ks < 2; ks++) {
                    int row = wm * 32 + mf * 16 + (lane & 15);
                    int col = ks * 32 + ((lane & 16) ? 16 : 0);
                    uint32_t ao = row * 80 + col;
                    LDMX4(ah[mf][ks][0], ah[mf][ks][1], ah[mf][ks][2], ah[mf][ks][3], abh + ao);
                    LDMX4(al[mf][ks][0], al[mf][ks][1], al[mf][ks][2], al[mf][ks][3], abl + ao);
                }
            }
        }

        #pragma unroll
        for (int mat = 0; mat < 3; mat++) {
            const uint32_t bb = sbase + GBW(buf, mat);
            #pragma unroll
            for (int ks = 0; ks < 2; ks++) {
                #pragma unroll
                for (int nf16 = 0; nf16 < 2; nf16++) {
                    uint32_t b0, b1, b2, b3;
                    int kk = ks * 16 + (lane & 15);
                    int cb = (wn * 32 + nf16 * 16 + ((lane & 16) ? 8 : 0)) * 2;
                    LDMX4T(b0, b1, b2, b3, bb + kk * 144 + cb);
                    #pragma unroll
                    for (int mf = 0; mf < 2; mf++) {
                        float* c0 = acc[mat][mf][nf16 * 2];
                        float* c1 = acc[mat][mf][nf16 * 2 + 1];
                        MMA_F16(c0, ah[mf][ks][0], ah[mf][ks][1], ah[mf][ks][2], ah[mf][ks][3], b0, b1);
                        MMA_F16(c0, al[mf][ks][0], al[mf][ks][1], al[mf][ks][2], al[mf][ks][3], b0, b1);
                        MMA_F16(c1, ah[mf][ks][0], ah[mf][ks][1], ah[mf][ks][2], ah[mf][ks][3], b2, b3);
                        MMA_F16(c1, al[mf][ks][0], al[mf][ks][1], al[mf][ks][2], al[mf][ks][3], b2, b3);
                    }
                }
            }
        }
    }

    // ---- epilogue: Q pre-scaled fp16 hi/lo; K,V single fp16 ----
    const int bb = m0 >> 10;
    #pragma unroll
    for (int mf = 0; mf < 2; mf++) {
        #pragma unroll
        for (int nf = 0; nf < 4; nf++) {
            int row  = wm * 32 + mf * 16 + (lane >> 2);
            int colg = wn * 32 + nf * 8 + (lane & 3) * 2;
            int t    = (m0 + row) & 1023;
            size_t base = (((size_t)(bb * H + h) * T + t) * D) + colg;

            // Q: scale by D^-0.5, split fp16 hi/lo
            {
                const float* c = acc[0][mf][nf];
                uint32_t hi, lo;
                split_pack2h(c[0] * 0.125f, c[1] * 0.125f, hi, lo);
                *(uint32_t*)(g_qh + base) = hi;
                *(uint32_t*)(g_ql + base) = lo;
                split_pack2h(c[2] * 0.125f, c[3] * 0.125f, hi, lo);
                *(uint32_t*)(g_qh + base + 8 * D) = hi;
                *(uint32_t*)(g_ql + base + 8 * D) = lo;
            }
            // K single fp16
            {
                const float* c = acc[1][mf][nf];
                *(uint32_t*)(g_kf + base) =
                    pack_h2(__float2half_rn(c[0]), __float2half_rn(c[1]));
                *(uint32_t*)(g_kf + base + 8 * D) =
                    pack_h2(__float2half_rn(c[2]), __float2half_rn(c[3]));
            }
            // V single fp16
            {
                const float* c = acc[2][mf][nf];
                *(uint32_t*)(g_vf + base) =
                    pack_h2(__float2half_rn(c[0]), __float2half_rn(c[1]));
                *(uint32_t*)(g_vf + base + 8 * D) =
                    pack_h2(__float2half_rn(c[2]), __float2half_rn(c[3]));
            }
        }
    }
}

// ===========================================================================
// Kernel 2: causal FlashAttention (unchanged from R9 — 145us).
// ===========================================================================
#define BRA 128
#define BCA 64
#define AST 144
#define KVT (64 * AST)            // 9216
#define KF_OFF(buf) ((buf) * 2 * KVT)
#define VF_OFF(buf) ((buf) * 2 * KVT + KVT)
#define QH_OFF 0
#define QL_OFF (128 * AST)        // 18432
#define ATT_SMEM (4 * KVT)        // 36864

__global__ __launch_bounds__(256)
void flash_attn_mma_kernel(float* __restrict__ out)
{
    extern __shared__ char sm[];
    const uint32_t sbase = smem_u32(sm);

    const int tid  = threadIdx.x;
    const int warp = tid >> 5;
    const int lane = tid & 31;
    const int qt = blockIdx.x;
    const int h  = blockIdx.y;
    const int b  = blockIdx.z;
    const size_t head_base = ((size_t)(b * H + h) * T) * D;
    const int q0 = qt * BRA;

    // ---- Stage Q hi/lo via cp.async ----
    {
        const __half* qhp = g_qh + head_base + (size_t)q0 * D;
        const __half* qlp = g_ql + head_base + (size_t)q0 * D;
        #pragma unroll
        for (int it = 0; it < 4; it++) {
            int idx = tid + it * 256;
            int r   = idx >> 3;
            int seg = idx & 7;
            uint32_t dofs = r * AST + seg * 16;
            CPA16(sbase + QH_OFF + dofs, qhp + (size_t)r * D + seg * 8);
            CPA16(sbase + QL_OFF + dofs, qlp + (size_t)r * D + seg * 8);
        }
        CPC(); CPW0();
    }
    __syncthreads();

    uint32_t qh[4][4], ql[4][4];
    #pragma unroll
    for (int ks = 0; ks < 4; ks++) {
        int row = warp * 16 + (lane & 15);
        int col = ks * 32 + ((lane & 16) ? 16 : 0);
        uint32_t ao = row * AST + col;
        LDMX4(qh[ks][0], qh[ks][1], qh[ks][2], qh[ks][3], sbase + QH_OFF + ao);
        LDMX4(ql[ks][0], ql[ks][1], ql[ks][2], ql[ks][3], sbase + QL_OFF + ao);
    }
    __syncthreads();

    auto load_tile = [&](int kt) {
        const int buf = kt & 1;
        const size_t tb = head_base + (size_t)kt * BCA * D;
        #pragma unroll
        for (int i = 0; i < 2; i++) {
            int idx = tid + i * 256;
            int r   = idx >> 3;
            int seg = idx & 7;
            uint32_t dofs = r * AST + seg * 16;
            size_t so = tb + (size_t)r * D + seg * 8;
            CPA16(sbase + KF_OFF(buf) + dofs, g_kf + so);
            CPA16(sbase + VF_OFF(buf) + dofs, g_vf + so);
        }
    };

    float o[8][4];
    #pragma unroll
    for (int nf = 0; nf < 8; nf++)
        #pragma unroll
        for (int e = 0; e < 4; e++) o[nf][e] = 0.0f;
    float m0 = -1e30f, m1 = -1e30f, l0 = 0.0f, l1 = 0.0f;

    const int ntiles = 2 * (qt + 1);
    const int rbase  = q0 + warp * 16 + (lane >> 2);

    load_tile(0); CPC();
    if (ntiles > 1) { load_tile(1); CPC(); }

    for (int kt = 0; kt < ntiles; kt++) {
        const int buf = kt & 1;
        if (kt + 1 < ntiles) { CPW1(); } else { CPW0(); }
        __syncthreads();

        float sc[8][4];
        #pragma unroll
        for (int nf = 0; nf < 8; nf++)
            #pragma unroll
            for (int e = 0; e < 4; e++) sc[nf][e] = 0.0f;

        const uint32_t kfb = sbase + KF_OFF(buf);
        #pragma unroll
        for (int ks = 0; ks < 4; ks++) {
            #pragma unroll
            for (int nf16 = 0; nf16 < 4; nf16++) {
                uint32_t kb0, kb1, kb2, kb3;
                int row = nf16 * 16 + (lane & 7) + ((lane & 16) ? 8 : 0);
                int col = ks * 32 + ((lane & 8) ? 16 : 0);
                uint32_t o32 = row * AST + col;
                LDMX4(kb0, kb1, kb2, kb3, kfb + o32);
                float* c0p = sc[nf16 * 2];
                float* c1p = sc[nf16 * 2 + 1];
                MMA_F16(c0p, qh[ks][0], qh[ks][1], qh[ks][2], qh[ks][3], kb0, kb1);
                MMA_F16(c0p, ql[ks][0], ql[ks][1], ql[ks][2], ql[ks][3], kb0, kb1);
                MMA_F16(c1p, qh[ks][0], qh[ks][1], qh[ks][2], qh[ks][3], kb2, kb3);
                MMA_F16(c1p, ql[ks][0], ql[ks][1], ql[ks][2], ql[ks][3], kb2, kb3);
            }
        }

        if (kt * BCA + 63 > q0 + warp * 16) {
            #pragma unroll
            for (int nf = 0; nf < 8; nf++) {
                int col = kt * BCA + nf * 8 + 2 * (lane & 3);
                if (col     > rbase)     sc[nf][0] = -1e30f;
                if (col + 1 > rbase)     sc[nf][1] = -1e30f;
                if (col     > rbase + 8) sc[nf][2] = -1e30f;
                if (col + 1 > rbase + 8) sc[nf][3] = -1e30f;
            }
        }

        float mt0 = -1e30f, mt1 = -1e30f;
        #pragma unroll
        for (int nf = 0; nf < 8; nf++) {
            mt0 = fmaxf(mt0, fmaxf(sc[nf][0], sc[nf][1]));
            mt1 = fmaxf(mt1, fmaxf(sc[nf][2], sc[nf][3]));
        }
        mt0 = fmaxf(mt0, __shfl_xor_sync(0xFFFFFFFFu, mt0, 1));
        mt0 = fmaxf(mt0, __shfl_xor_sync(0xFFFFFFFFu, mt0, 2));
        mt1 = fmaxf(mt1, __shfl_xor_sync(0xFFFFFFFFu, mt1, 1));
        mt1 = fmaxf(mt1, __shfl_xor_sync(0xFFFFFFFFu, mt1, 2));

        float mn0 = fmaxf(m0, mt0), mn1 = fmaxf(m1, mt1);
        float cr0 = __expf(m0 - mn0), cr1 = __expf(m1 - mn1);
        l0 *= cr0; l1 *= cr1;
        #pragma unroll
        for (int nf = 0; nf < 8; nf++) {
            o[nf][0] *= cr0; o[nf][1] *= cr0;
            o[nf][2] *= cr1; o[nf][3] *= cr1;
            sc[nf][0] = __expf(sc[nf][0] - mn0);
            sc[nf][1] = __expf(sc[nf][1] - mn0);
            sc[nf][2] = __expf(sc[nf][2] - mn1);
            sc[nf][3] = __expf(sc[nf][3] - mn1);
            l0 += sc[nf][0] + sc[nf][1];
            l1 += sc[nf][2] + sc[nf][3];
        }
        m0 = mn0; m1 = mn1;

        const uint32_t vfb = sbase + VF_OFF(buf);
        #pragma unroll
        for (int ks = 0; ks < 4; ks++) {
            uint32_t ph[4], pl[4];
            split_pack2h(sc[2 * ks][0],     sc[2 * ks][1],     ph[0], pl[0]);
            split_pack2h(sc[2 * ks][2],     sc[2 * ks][3],     ph[1], pl[1]);
            split_pack2h(sc[2 * ks + 1][0], sc[2 * ks + 1][1], ph[2], pl[2]);
            split_pack2h(sc[2 * ks + 1][2], sc[2 * ks + 1][3], ph[3], pl[3]);
            #pragma unroll
            for (int nf16 = 0; nf16 < 4; nf16++) {
                uint32_t vb0, vb1, vb2, vb3;
                int kk = ks * 16 + ((lane & 8) ? 8 : 0) + (lane & 7);
                int cb = (nf16 * 16 + ((lane & 16) ? 8 : 0)) * 2;
                uint32_t o32 = kk * AST + cb;
                LDMX4T(vb0, vb1, vb2, vb3, vfb + o32);
                float* c0p = o[nf16 * 2];
                float* c1p = o[nf16 * 2 + 1];
                MMA_F16(c0p, ph[0], ph[1], ph[2], ph[3], vb0, vb1);
                MMA_F16(c0p, pl[0], pl[1], pl[2], pl[3], vb0, vb1);
                MMA_F16(c1p, ph[0], ph[1], ph[2], ph[3], vb2, vb3);
                MMA_F16(c1p, pl[0], pl[1], pl[2], pl[3], vb2, vb3);
            }
        }

        __syncthreads();
        if (kt + 2 < ntiles) { load_tile(kt + 2); CPC(); }
    }

    l0 += __shfl_xor_sync(0xFFFFFFFFu, l0, 1);
    l0 += __shfl_xor_sync(0xFFFFFFFFu, l0, 2);
    l1 += __shfl_xor_sync(0xFFFFFFFFu, l1, 1);
    l1 += __shfl_xor_sync(0xFFFFFFFFu, l1, 2);
    const float i0 = 1.0f / l0;
    const float i1 = 1.0f / l1;

    float* op = out + ((size_t)(b * T + rbase) * (H * D)) + h * D;
    #pragma unroll
    for (int nf = 0; nf < 8; nf++) {
        int col = nf * 8 + 2 * (lane & 3);
        *(float2*)(op + col) = make_float2(o[nf][0] * i0, o[nf][1] * i0);
        *(float2*)(op + (size_t)8 * (H * D) + col) = make_float2(o[nf][2] * i1, o[nf][3] * i1);
    }
}

// ===========================================================================
extern "C" void kernel_launch(void* const* d_in, const int* in_sizes, int n_in,
                              void* d_out, int out_size)
{
    const float* x  = (const float*)d_in[0];   // [B, T, C]
    const float* Wq = (const float*)d_in[1];   // [H, C, D]
    const float* Wk = (const float*)d_in[2];
    const float* Wv = (const float*)d_in[3];
    float* out = (float*)d_out;                 // [B, T, H*D]

    (void)in_sizes; (void)n_in; (void)out_size;

    static int smem_set = 0;
    if (!smem_set) {
        cudaFuncSetAttribute(qkv_fp16_kernel,
                             cudaFuncAttributeMaxDynamicSharedMemorySize, G_SMEM);
        cudaFuncSetAttribute(flash_attn_mma_kernel,
                             cudaFuncAttributeMaxDynamicSharedMemorySize, ATT_SMEM);
        smem_set = 1;
    }

    split_x_kernel<<<(size_t)B * T * C / 1024, 256>>>(x);
    conv_w_kernel<<<dim3(H * C * D / 1024, 3), 256>>>(Wq, Wk, Wv);

    dim3 gemm_grid(T * B / 128, H);             // 64 x 16
    qkv_fp16_kernel<<<gemm_grid, 256, G_SMEM>>>();

    dim3 attn_grid(T / BRA, H, B);              // 8 x 16 x 8
    flash_attn_mma_kernel<<<attn_grid, 256, ATT_SMEM>>>(out);
}

// round 11
// speedup vs baseline: 4.5748x; 1.1035x over previous
#include <cuda_runtime.h>
#include <cuda_bf16.h>
#include <cuda_fp16.h>
#include <math.h>
#include <stdint.h>

// Problem constants
#define B 8
#define T 1024
#define C 1024
#define H 16
#define D 64

// Scratch: Q pre-scaled fp16 hi/lo; K/V single fp16; x split fp16; W fp16
__device__ __half g_qh[(size_t)B * H * T * D];
__device__ __half g_ql[(size_t)B * H * T * D];
__device__ __half g_kf[(size_t)B * H * T * D];
__device__ __half g_vf[(size_t)B * H * T * D];
__device__ __half g_xh[(size_t)B * T * C];
__device__ __half g_xl[(size_t)B * T * C];
__device__ __half g_wh[(size_t)3 * H * C * D];

// ===========================================================================
// Helpers
// ===========================================================================
__device__ __forceinline__ uint32_t smem_u32(const void* p) {
    uint32_t a;
    asm("{ .reg .u64 t; cvta.to.shared.u64 t, %1; cvt.u32.u64 %0, t; }"
        : "=r"(a) : "l"(p));
    return a;
}

#define LDMX4(r0, r1, r2, r3, addr)                                           \
    asm volatile("ldmatrix.sync.aligned.m8n8.x4.shared.b16 {%0,%1,%2,%3}, [%4];" \
                 : "=r"(r0), "=r"(r1), "=r"(r2), "=r"(r3) : "r"(addr))

#define LDMX4T(r0, r1, r2, r3, addr)                                          \
    asm volatile("ldmatrix.sync.aligned.m8n8.x4.trans.shared.b16 {%0,%1,%2,%3}, [%4];" \
                 : "=r"(r0), "=r"(r1), "=r"(r2), "=r"(r3) : "r"(addr))

#define MMA_F16(c, a0, a1, a2, a3, b0, b1)                                    \
    asm volatile("mma.sync.aligned.m16n8k16.row.col.f32.f16.f16.f32 "         \
                 "{%0,%1,%2,%3}, {%4,%5,%6,%7}, {%8,%9}, {%0,%1,%2,%3};"      \
                 : "+f"((c)[0]), "+f"((c)[1]), "+f"((c)[2]), "+f"((c)[3])     \
                 : "r"(a0), "r"(a1), "r"(a2), "r"(a3), "r"(b0), "r"(b1))

#define CPA16(dst, src) \
    asm volatile("cp.async.cg.shared.global [%0], [%1], 16;" :: "r"(dst), "l"(src))
#define CPC()  asm volatile("cp.async.commit_group;" ::: "memory")
#define CPW0() asm volatile("cp.async.wait_group 0;" ::: "memory")
#define CPW1() asm volatile("cp.async.wait_group 1;" ::: "memory")

__device__ __forceinline__ uint32_t pack_h2(__half a, __half b) {
    __half2 h = __halves2half2(a, b);
    return *(uint32_t*)&h;
}

// fp16 hi/lo split of a pair, packed
__device__ __forceinline__ void split_pack2h(float a, float b, uint32_t& hi, uint32_t& lo) {
    __half ha = __float2half_rn(a), hb = __float2half_rn(b);
    __half la = __float2half_rn(a - __half2float(ha));
    __half lb = __float2half_rn(b - __half2float(hb));
    hi = pack_h2(ha, hb);
    lo = pack_h2(la, lb);
}

// ===========================================================================
// Kernel 0a: split x into fp16 hi/lo (exact to ~2^-22)
// ===========================================================================
__global__ __launch_bounds__(256) void split_x_kernel(const float* __restrict__ x)
{
    size_t i = ((size_t)blockIdx.x * 256 + threadIdx.x) * 4;
    float4 v = *(const float4*)(x + i);
    __half hx = __float2half_rn(v.x), hy = __float2half_rn(v.y);
    __half hz = __float2half_rn(v.z), hw = __float2half_rn(v.w);
    __half lx = __float2half_rn(v.x - __half2float(hx));
    __half ly = __float2half_rn(v.y - __half2float(hy));
    __half lz = __float2half_rn(v.z - __half2float(hz));
    __half lw = __float2half_rn(v.w - __half2float(hw));
    *(uint2*)(g_xh + i) = make_uint2(pack_h2(hx, hy), pack_h2(hz, hw));
    *(uint2*)(g_xl + i) = make_uint2(pack_h2(lx, ly), pack_h2(lz, lw));
}

// ===========================================================================
// Kernel 0b: convert W to fp16 (single rounding)
// ===========================================================================
__global__ __launch_bounds__(256) void conv_w_kernel(const float* __restrict__ Wq,
                                                     const float* __restrict__ Wk,
                                                     const float* __restrict__ Wv)
{
    const int mat = blockIdx.y;
    const float* W = (mat == 0) ? Wq : (mat == 1) ? Wk : Wv;
    size_t i = ((size_t)blockIdx.x * 256 + threadIdx.x) * 4;
    float4 v = *(const float4*)(W + i);
    *(uint2*)(g_wh + (size_t)mat * H * C * D + i) = make_uint2(
        pack_h2(__float2half_rn(v.x), __float2half_rn(v.y)),
        pack_h2(__float2half_rn(v.z), __float2half_rn(v.w)));
}

// ===========================================================================
// Kernel 1: QKV projections, fp16 2-term split.
// 512 threads / 16 warps per CTA (warp tile 16x32, acc halved to 48 floats)
// to double warps-per-SM and hide HMMA latency. 3-stage cp.async pipeline,
// one barrier per chunk, prefetch before compute.
// ===========================================================================
#define BK 32
#define NCHUNK (C / BK)
#define GBUF 34304
#define GAH(buf)       ((buf) * GBUF)
#define GAL(buf)       ((buf) * GBUF + 10240)
#define GBW(buf, mat)  ((buf) * GBUF + 20480 + (mat) * 4608)
#define G_SMEM (3 * GBUF)     // 102912

__global__ __launch_bounds__(512)
void qkv_fp16_kernel()
{
    extern __shared__ char sm[];
    const uint32_t sbase = smem_u32(sm);

    const int tid  = threadIdx.x;
    const int warp = tid >> 5;            // 0..15
    const int lane = tid & 31;
    const int wm   = warp >> 1;           // 0..7 -> rows [wm*16, +16)
    const int wn   = warp & 1;            // 0..1 -> cols [wn*32, +32) per mat

    const int m0 = blockIdx.x * 128;
    const int h  = blockIdx.y;

    float acc[3][4][4];
    #pragma unroll
    for (int m = 0; m < 3; m++)
        #pragma unroll
        for (int j = 0; j < 4; j++)
            #pragma unroll
            for (int k = 0; k < 4; k++)
                acc[m][j][k] = 0.0f;

    auto load_chunk = [&](int ci) {
        const int buf = ci % 3;
        const int k0  = ci * BK;
        // A: 128 rows x 4 16B-segments, hi+lo: one pair per thread
        {
            int r   = tid >> 2;                    // 0..127
            int seg = tid & 3;
            uint32_t dofs = r * 80 + seg * 16;
            CPA16(sbase + GAH(buf) + dofs, g_xh + (size_t)(m0 + r) * C + k0 + seg * 8);
            CPA16(sbase + GAL(buf) + dofs, g_xl + (size_t)(m0 + r) * C + k0 + seg * 8);
        }
        // B: 3 mats x 32 rows x 8 segs = 256 per mat; threads 0..255
        if (tid < 256) {
            int r   = tid >> 3;                    // 0..31
            int seg = tid & 7;
            uint32_t dofs = r * 144 + seg * 16;
            #pragma unroll
            for (int mat = 0; mat < 3; mat++) {
                const __half* s = g_wh + ((size_t)(mat * H + h)) * C * D
                                 + (size_t)(k0 + r) * D + seg * 8;
                CPA16(sbase + GBW(buf, mat) + dofs, s);
            }
        }
    };

    load_chunk(0); CPC();
    load_chunk(1); CPC();

    for (int ci = 0; ci < NCHUNK; ci++) {
        const int buf = ci % 3;
        if (ci < NCHUNK - 1) { CPW1(); } else { CPW0(); }
        __syncthreads();

        if (ci + 2 < NCHUNK) { load_chunk(ci + 2); CPC(); }

        // ---- A fragments (hi + lo), 2 ksteps ----
        uint32_t ah[2][4], al[2][4];
        {
            const uint32_t abh = sbase + GAH(buf);
            const uint32_t abl = sbase + GAL(buf);
            #pragma unroll
            for (int ks = 0; ks < 2; ks++) {
                int row = wm * 16 + (lane & 15);
                int col = ks * 32 + ((lane & 16) ? 16 : 0);
                uint32_t ao = row * 80 + col;
                LDMX4(ah[ks][0], ah[ks][1], ah[ks][2], ah[ks][3], abh + ao);
                LDMX4(al[ks][0], al[ks][1], al[ks][2], al[ks][3], abl + ao);
            }
        }

        #pragma unroll
        for (int mat = 0; mat < 3; mat++) {
            const uint32_t bb = sbase + GBW(buf, mat);
            #pragma unroll
            for (int ks = 0; ks < 2; ks++) {
                #pragma unroll
                for (int nf16 = 0; nf16 < 2; nf16++) {
                    uint32_t b0, b1, b2, b3;
                    int kk = ks * 16 + (lane & 15);
                    int cb = (wn * 32 + nf16 * 16 + ((lane & 16) ? 8 : 0)) * 2;
                    LDMX4T(b0, b1, b2, b3, bb + kk * 144 + cb);
                    float* c0 = acc[mat][nf16 * 2];
                    float* c1 = acc[mat][nf16 * 2 + 1];
                    MMA_F16(c0, ah[ks][0], ah[ks][1], ah[ks][2], ah[ks][3], b0, b1);
                    MMA_F16(c0, al[ks][0], al[ks][1], al[ks][2], al[ks][3], b0, b1);
                    MMA_F16(c1, ah[ks][0], ah[ks][1], ah[ks][2], ah[ks][3], b2, b3);
                    MMA_F16(c1, al[ks][0], al[ks][1], al[ks][2], al[ks][3], b2, b3);
                }
            }
        }
    }

    // ---- epilogue: Q pre-scaled fp16 hi/lo; K,V single fp16 ----
    const int bb = m0 >> 10;
    #pragma unroll
    for (int nf = 0; nf < 4; nf++) {
        int row  = wm * 16 + (lane >> 2);
        int colg = wn * 32 + nf * 8 + (lane & 3) * 2;
        int t    = (m0 + row) & 1023;
        size_t base = (((size_t)(bb * H + h) * T + t) * D) + colg;

        // Q: scale by D^-0.5, split fp16 hi/lo
        {
            const float* c = acc[0][nf];
            uint32_t hi, lo;
            split_pack2h(c[0] * 0.125f, c[1] * 0.125f, hi, lo);
            *(uint32_t*)(g_qh + base) = hi;
            *(uint32_t*)(g_ql + base) = lo;
            split_pack2h(c[2] * 0.125f, c[3] * 0.125f, hi, lo);
            *(uint32_t*)(g_qh + base + 8 * D) = hi;
            *(uint32_t*)(g_ql + base + 8 * D) = lo;
        }
        // K single fp16
        {
            const float* c = acc[1][nf];
            *(uint32_t*)(g_kf + base) =
                pack_h2(__float2half_rn(c[0]), __float2half_rn(c[1]));
            *(uint32_t*)(g_kf + base + 8 * D) =
                pack_h2(__float2half_rn(c[2]), __float2half_rn(c[3]));
        }
        // V single fp16
        {
            const float* c = acc[2][nf];
            *(uint32_t*)(g_vf + base) =
                pack_h2(__float2half_rn(c[0]), __float2half_rn(c[1]));
            *(uint32_t*)(g_vf + base + 8 * D) =
                pack_h2(__float2half_rn(c[2]), __float2half_rn(c[3]));
        }
    }
}

// ===========================================================================
// Kernel 2: causal FlashAttention. Q stays resident in SMEM (q frags
// re-ldmatrix'd per k-step — frees 32 regs), target 2 CTAs/SM.
// ===========================================================================
#define BRA 128
#define BCA 64
#define AST 144
#define KVT (64 * AST)            // 9216
#define QH_OFF 0
#define QL_OFF 18432
#define KV_BASE 36864
#define KF_OFF(buf) (KV_BASE + (buf) * 2 * KVT)
#define VF_OFF(buf) (KV_BASE + (buf) * 2 * KVT + KVT)
#define ATT_SMEM (KV_BASE + 4 * KVT)   // 73728

__global__ __launch_bounds__(256, 2)
void flash_attn_mma_kernel(float* __restrict__ out)
{
    extern __shared__ char sm[];
    const uint32_t sbase = smem_u32(sm);

    const int tid  = threadIdx.x;
    const int warp = tid >> 5;
    const int lane = tid & 31;
    const int qt = blockIdx.x;
    const int h  = blockIdx.y;
    const int b  = blockIdx.z;
    const size_t head_base = ((size_t)(b * H + h) * T) * D;
    const int q0 = qt * BRA;

    // ---- Stage Q hi/lo via cp.async (persistent in SMEM) ----
    {
        const __half* qhp = g_qh + head_base + (size_t)q0 * D;
        const __half* qlp = g_ql + head_base + (size_t)q0 * D;
        #pragma unroll
        for (int it = 0; it < 4; it++) {
            int idx = tid + it * 256;
            int r   = idx >> 3;
            int seg = idx & 7;
            uint32_t dofs = r * AST + seg * 16;
            CPA16(sbase + QH_OFF + dofs, qhp + (size_t)r * D + seg * 8);
            CPA16(sbase + QL_OFF + dofs, qlp + (size_t)r * D + seg * 8);
        }
        CPC();
    }

    auto load_tile = [&](int kt) {
        const int buf = kt & 1;
        const size_t tb = head_base + (size_t)kt * BCA * D;
        #pragma unroll
        for (int i = 0; i < 2; i++) {
            int idx = tid + i * 256;
            int r   = idx >> 3;
            int seg = idx & 7;
            uint32_t dofs = r * AST + seg * 16;
            size_t so = tb + (size_t)r * D + seg * 8;
            CPA16(sbase + KF_OFF(buf) + dofs, g_kf + so);
            CPA16(sbase + VF_OFF(buf) + dofs, g_vf + so);
        }
    };

    float o[8][4];
    #pragma unroll
    for (int nf = 0; nf < 8; nf++)
        #pragma unroll
        for (int e = 0; e < 4; e++) o[nf][e] = 0.0f;
    float m0 = -1e30f, m1 = -1e30f, l0 = 0.0f, l1 = 0.0f;

    const int ntiles = 2 * (qt + 1);
    const int rbase  = q0 + warp * 16 + (lane >> 2);

    load_tile(0); CPC();
    if (ntiles > 1) { load_tile(1); CPC(); }

    const int qrow = warp * 16 + (lane & 15);

    for (int kt = 0; kt < ntiles; kt++) {
        const int buf = kt & 1;
        if (kt + 1 < ntiles) { CPW1(); } else { CPW0(); }
        __syncthreads();

        // ---- S = Qh K + Ql K (q frags reloaded per k-step from SMEM) ----
        float sc[8][4];
        #pragma unroll
        for (int nf = 0; nf < 8; nf++)
            #pragma unroll
            for (int e = 0; e < 4; e++) sc[nf][e] = 0.0f;

        const uint32_t kfb = sbase + KF_OFF(buf);
        #pragma unroll
        for (int ks = 0; ks < 4; ks++) {
            uint32_t qh0, qh1, qh2, qh3, ql0, ql1, ql2, ql3;
            {
                int col = ks * 32 + ((lane & 16) ? 16 : 0);
                uint32_t ao = qrow * AST + col;
                LDMX4(qh0, qh1, qh2, qh3, sbase + QH_OFF + ao);
                LDMX4(ql0, ql1, ql2, ql3, sbase + QL_OFF + ao);
            }
            #pragma unroll
            for (int nf16 = 0; nf16 < 4; nf16++) {
                uint32_t kb0, kb1, kb2, kb3;
                int row = nf16 * 16 + (lane & 7) + ((lane & 16) ? 8 : 0);
                int col = ks * 32 + ((lane & 8) ? 16 : 0);
                uint32_t o32 = row * AST + col;
                LDMX4(kb0, kb1, kb2, kb3, kfb + o32);
                float* c0p = sc[nf16 * 2];
                float* c1p = sc[nf16 * 2 + 1];
                MMA_F16(c0p, qh0, qh1, qh2, qh3, kb0, kb1);
                MMA_F16(c0p, ql0, ql1, ql2, ql3, kb0, kb1);
                MMA_F16(c1p, qh0, qh1, qh2, qh3, kb2, kb3);
                MMA_F16(c1p, ql0, ql1, ql2, ql3, kb2, kb3);
            }
        }

        // ---- causal mask on diagonal tiles ----
        if (kt * BCA + 63 > q0 + warp * 16) {
            #pragma unroll
            for (int nf = 0; nf < 8; nf++) {
                int col = kt * BCA + nf * 8 + 2 * (lane & 3);
                if (col     > rbase)     sc[nf][0] = -1e30f;
                if (col + 1 > rbase)     sc[nf][1] = -1e30f;
                if (col     > rbase + 8) sc[nf][2] = -1e30f;
                if (col + 1 > rbase + 8) sc[nf][3] = -1e30f;
            }
        }

        // ---- online softmax ----
        float mt0 = -1e30f, mt1 = -1e30f;
        #pragma unroll
        for (int nf = 0; nf < 8; nf++) {
            mt0 = fmaxf(mt0, fmaxf(sc[nf][0], sc[nf][1]));
            mt1 = fmaxf(mt1, fmaxf(sc[nf][2], sc[nf][3]));
        }
        mt0 = fmaxf(mt0, __shfl_xor_sync(0xFFFFFFFFu, mt0, 1));
        mt0 = fmaxf(mt0, __shfl_xor_sync(0xFFFFFFFFu, mt0, 2));
        mt1 = fmaxf(mt1, __shfl_xor_sync(0xFFFFFFFFu, mt1, 1));
        mt1 = fmaxf(mt1, __shfl_xor_sync(0xFFFFFFFFu, mt1, 2));

        float mn0 = fmaxf(m0, mt0), mn1 = fmaxf(m1, mt1);
        float cr0 = __expf(m0 - mn0), cr1 = __expf(m1 - mn1);
        l0 *= cr0; l1 *= cr1;
        #pragma unroll
        for (int nf = 0; nf < 8; nf++) {
            o[nf][0] *= cr0; o[nf][1] *= cr0;
            o[nf][2] *= cr1; o[nf][3] *= cr1;
            sc[nf][0] = __expf(sc[nf][0] - mn0);
            sc[nf][1] = __expf(sc[nf][1] - mn0);
            sc[nf][2] = __expf(sc[nf][2] - mn1);
            sc[nf][3] = __expf(sc[nf][3] - mn1);
            l0 += sc[nf][0] + sc[nf][1];
            l1 += sc[nf][2] + sc[nf][3];
        }
        m0 = mn0; m1 = mn1;

        // ---- O += Ph V + Pl V ----
        const uint32_t vfb = sbase + VF_OFF(buf);
        #pragma unroll
        for (int ks = 0; ks < 4; ks++) {
            uint32_t ph[4], pl[4];
            split_pack2h(sc[2 * ks][0],     sc[2 * ks][1],     ph[0], pl[0]);
            split_pack2h(sc[2 * ks][2],     sc[2 * ks][3],     ph[1], pl[1]);
            split_pack2h(sc[2 * ks + 1][0], sc[2 * ks + 1][1], ph[2], pl[2]);
            split_pack2h(sc[2 * ks + 1][2], sc[2 * ks + 1][3], ph[3], pl[3]);
            #pragma unroll
            for (int nf16 = 0; nf16 < 4; nf16++) {
                uint32_t vb0, vb1, vb2, vb3;
                int kk = ks * 16 + ((lane & 8) ? 8 : 0) + (lane & 7);
                int cb = (nf16 * 16 + ((lane & 16) ? 8 : 0)) * 2;
                uint32_t o32 = kk * AST + cb;
                LDMX4T(vb0, vb1, vb2, vb3, vfb + o32);
                float* c0p = o[nf16 * 2];
                float* c1p = o[nf16 * 2 + 1];
                MMA_F16(c0p, ph[0], ph[1], ph[2], ph[3], vb0, vb1);
                MMA_F16(c0p, pl[0], pl[1], pl[2], pl[3], vb0, vb1);
                MMA_F16(c1p, ph[0], ph[1], ph[2], ph[3], vb2, vb3);
                MMA_F16(c1p, pl[0], pl[1], pl[2], pl[3], vb2, vb3);
            }
        }

        __syncthreads();
        if (kt + 2 < ntiles) { load_tile(kt + 2); CPC(); }
    }

    l0 += __shfl_xor_sync(0xFFFFFFFFu, l0, 1);
    l0 += __shfl_xor_sync(0xFFFFFFFFu, l0, 2);
    l1 += __shfl_xor_sync(0xFFFFFFFFu, l1, 1);
    l1 += __shfl_xor_sync(0xFFFFFFFFu, l1, 2);
    const float i0 = 1.0f / l0;
    const float i1 = 1.0f / l1;

    float* op = out + ((size_t)(b * T + rbase) * (H * D)) + h * D;
    #pragma unroll
    for (int nf = 0; nf < 8; nf++) {
        int col = nf * 8 + 2 * (lane & 3);
        *(float2*)(op + col) = make_float2(o[nf][0] * i0, o[nf][1] * i0);
        *(float2*)(op + (size_t)8 * (H * D) + col) = make_float2(o[nf][2] * i1, o[nf][3] * i1);
    }
}

// ===========================================================================
extern "C" void kernel_launch(void* const* d_in, const int* in_sizes, int n_in,
                              void* d_out, int out_size)
{
    const float* x  = (const float*)d_in[0];   // [B, T, C]
    const float* Wq = (const float*)d_in[1];   // [H, C, D]
    const float* Wk = (const float*)d_in[2];
    const float* Wv = (const float*)d_in[3];
    float* out = (float*)d_out;                 // [B, T, H*D]

    (void)in_sizes; (void)n_in; (void)out_size;

    static int smem_set = 0;
    if (!smem_set) {
        cudaFuncSetAttribute(qkv_fp16_kernel,
                             cudaFuncAttributeMaxDynamicSharedMemorySize, G_SMEM);
        cudaFuncSetAttribute(flash_attn_mma_kernel,
                             cudaFuncAttributeMaxDynamicSharedMemorySize, ATT_SMEM);
        smem_set = 1;
    }

    split_x_kernel<<<(size_t)B * T * C / 1024, 256>>>(x);
    conv_w_kernel<<<dim3(H * C * D / 1024, 3), 256>>>(Wq, Wk, Wv);

    dim3 gemm_grid(T * B / 128, H);             // 64 x 16
    qkv_fp16_kernel<<<gemm_grid, 512, G_SMEM>>>();

    dim3 attn_grid(T / BRA, H, B);              // 8 x 16 x 8
    flash_attn_mma_kernel<<<attn_grid, 256, ATT_SMEM>>>(out);
}

// round 12
// speedup vs baseline: 6.3281x; 1.3832x over previous
#include <cuda_runtime.h>
#include <cuda_bf16.h>
#include <cuda_fp16.h>
#include <math.h>
#include <stdint.h>

// Problem constants
#define B 8
#define T 1024
#define C 1024
#define H 16
#define D 64

// Scratch: Q pre-scaled fp16 hi/lo; K/V single fp16; x fp16; W fp16
__device__ __half g_qh[(size_t)B * H * T * D];
__device__ __half g_ql[(size_t)B * H * T * D];
__device__ __half g_kf[(size_t)B * H * T * D];
__device__ __half g_vf[(size_t)B * H * T * D];
__device__ __half g_xf[(size_t)B * T * C];
__device__ __half g_wh[(size_t)3 * H * C * D];

// ===========================================================================
// Helpers
// ===========================================================================
__device__ __forceinline__ uint32_t smem_u32(const void* p) {
    uint32_t a;
    asm("{ .reg .u64 t; cvta.to.shared.u64 t, %1; cvt.u32.u64 %0, t; }"
        : "=r"(a) : "l"(p));
    return a;
}

#define LDMX4(r0, r1, r2, r3, addr)                                           \
    asm volatile("ldmatrix.sync.aligned.m8n8.x4.shared.b16 {%0,%1,%2,%3}, [%4];" \
                 : "=r"(r0), "=r"(r1), "=r"(r2), "=r"(r3) : "r"(addr))

#define LDMX4T(r0, r1, r2, r3, addr)                                          \
    asm volatile("ldmatrix.sync.aligned.m8n8.x4.trans.shared.b16 {%0,%1,%2,%3}, [%4];" \
                 : "=r"(r0), "=r"(r1), "=r"(r2), "=r"(r3) : "r"(addr))

#define MMA_F16(c, a0, a1, a2, a3, b0, b1)                                    \
    asm volatile("mma.sync.aligned.m16n8k16.row.col.f32.f16.f16.f32 "         \
                 "{%0,%1,%2,%3}, {%4,%5,%6,%7}, {%8,%9}, {%0,%1,%2,%3};"      \
                 : "+f"((c)[0]), "+f"((c)[1]), "+f"((c)[2]), "+f"((c)[3])     \
                 : "r"(a0), "r"(a1), "r"(a2), "r"(a3), "r"(b0), "r"(b1))

#define CPA16(dst, src) \
    asm volatile("cp.async.cg.shared.global [%0], [%1], 16;" :: "r"(dst), "l"(src))
#define CPC()  asm volatile("cp.async.commit_group;" ::: "memory")
#define CPW0() asm volatile("cp.async.wait_group 0;" ::: "memory")
#define CPW1() asm volatile("cp.async.wait_group 1;" ::: "memory")

__device__ __forceinline__ uint32_t pack_h2(__half a, __half b) {
    __half2 h = __halves2half2(a, b);
    return *(uint32_t*)&h;
}

// fp16 hi/lo split of a pair, packed
__device__ __forceinline__ void split_pack2h(float a, float b, uint32_t& hi, uint32_t& lo) {
    __half ha = __float2half_rn(a), hb = __float2half_rn(b);
    __half la = __float2half_rn(a - __half2float(ha));
    __half lb = __float2half_rn(b - __half2float(hb));
    hi = pack_h2(ha, hb);
    lo = pack_h2(la, lb);
}

// ===========================================================================
// Kernel 0a: convert x to fp16 (single rounding)
// ===========================================================================
__global__ __launch_bounds__(256) void conv_x_kernel(const float* __restrict__ x)
{
    size_t i = ((size_t)blockIdx.x * 256 + threadIdx.x) * 4;
    float4 v = *(const float4*)(x + i);
    *(uint2*)(g_xf + i) = make_uint2(
        pack_h2(__float2half_rn(v.x), __float2half_rn(v.y)),
        pack_h2(__float2half_rn(v.z), __float2half_rn(v.w)));
}

// ===========================================================================
// Kernel 0b: convert W to fp16 (single rounding)
// ===========================================================================
__global__ __launch_bounds__(256) void conv_w_kernel(const float* __restrict__ Wq,
                                                     const float* __restrict__ Wk,
                                                     const float* __restrict__ Wv)
{
    const int mat = blockIdx.y;
    const float* W = (mat == 0) ? Wq : (mat == 1) ? Wk : Wv;
    size_t i = ((size_t)blockIdx.x * 256 + threadIdx.x) * 4;
    float4 v = *(const float4*)(W + i);
    *(uint2*)(g_wh + (size_t)mat * H * C * D + i) = make_uint2(
        pack_h2(__float2half_rn(v.x), __float2half_rn(v.y)),
        pack_h2(__float2half_rn(v.z), __float2half_rn(v.w)));
}

// ===========================================================================
// Kernel 1: QKV projections, plain fp16 x fp16 (single-rounded operands).
// 512 threads / 16 warps per CTA, warp tile 16x32. 3-stage cp.async
// pipeline, one barrier per chunk, prefetch before compute.
// Epilogue: Q -> pre-scaled fp16 hi/lo split; K,V -> single fp16.
// ===========================================================================
#define BK 32
#define NCHUNK (C / BK)
#define GBUF 24064
#define GA(buf)        ((buf) * GBUF)
#define GBW(buf, mat)  ((buf) * GBUF + 10240 + (mat) * 4608)
#define G_SMEM (3 * GBUF)     // 72192

__global__ __launch_bounds__(512)
void qkv_fp16_kernel()
{
    extern __shared__ char sm[];
    const uint32_t sbase = smem_u32(sm);

    const int tid  = threadIdx.x;
    const int warp = tid >> 5;            // 0..15
    const int lane = tid & 31;
    const int wm   = warp >> 1;           // 0..7 -> rows [wm*16, +16)
    const int wn   = warp & 1;            // 0..1 -> cols [wn*32, +32) per mat

    const int m0 = blockIdx.x * 128;
    const int h  = blockIdx.y;

    float acc[3][4][4];
    #pragma unroll
    for (int m = 0; m < 3; m++)
        #pragma unroll
        for (int j = 0; j < 4; j++)
            #pragma unroll
            for (int k = 0; k < 4; k++)
                acc[m][j][k] = 0.0f;

    auto load_chunk = [&](int ci) {
        const int buf = ci % 3;
        const int k0  = ci * BK;
        // A: 128 rows x 4 16B-segments = 512 cp.async, one per thread
        {
            int r   = tid >> 2;                    // 0..127
            int seg = tid & 3;
            uint32_t dofs = r * 80 + seg * 16;
            CPA16(sbase + GA(buf) + dofs, g_xf + (size_t)(m0 + r) * C + k0 + seg * 8);
        }
        // B: 3 mats x 32 rows x 8 segs = 256 per mat; threads 0..255
        if (tid < 256) {
            int r   = tid >> 3;                    // 0..31
            int seg = tid & 7;
            uint32_t dofs = r * 144 + seg * 16;
            #pragma unroll
            for (int mat = 0; mat < 3; mat++) {
                const __half* s = g_wh + ((size_t)(mat * H + h)) * C * D
                                 + (size_t)(k0 + r) * D + seg * 8;
                CPA16(sbase + GBW(buf, mat) + dofs, s);
            }
        }
    };

    load_chunk(0); CPC();
    load_chunk(1); CPC();

    for (int ci = 0; ci < NCHUNK; ci++) {
        const int buf = ci % 3;
        if (ci < NCHUNK - 1) { CPW1(); } else { CPW0(); }
        __syncthreads();

        if (ci + 2 < NCHUNK) { load_chunk(ci + 2); CPC(); }

        // ---- A fragments, 2 ksteps ----
        uint32_t ah[2][4];
        {
            const uint32_t ab = sbase + GA(buf);
            #pragma unroll
            for (int ks = 0; ks < 2; ks++) {
                int row = wm * 16 + (lane & 15);
                int col = ks * 32 + ((lane & 16) ? 16 : 0);
                LDMX4(ah[ks][0], ah[ks][1], ah[ks][2], ah[ks][3], ab + row * 80 + col);
            }
        }

        #pragma unroll
        for (int mat = 0; mat < 3; mat++) {
            const uint32_t bb = sbase + GBW(buf, mat);
            #pragma unroll
            for (int ks = 0; ks < 2; ks++) {
                #pragma unroll
                for (int nf16 = 0; nf16 < 2; nf16++) {
                    uint32_t b0, b1, b2, b3;
                    int kk = ks * 16 + (lane & 15);
                    int cb = (wn * 32 + nf16 * 16 + ((lane & 16) ? 8 : 0)) * 2;
                    LDMX4T(b0, b1, b2, b3, bb + kk * 144 + cb);
                    float* c0 = acc[mat][nf16 * 2];
                    float* c1 = acc[mat][nf16 * 2 + 1];
                    MMA_F16(c0, ah[ks][0], ah[ks][1], ah[ks][2], ah[ks][3], b0, b1);
                    MMA_F16(c1, ah[ks][0], ah[ks][1], ah[ks][2], ah[ks][3], b2, b3);
                }
            }
        }
    }

    // ---- epilogue: Q pre-scaled fp16 hi/lo; K,V single fp16 ----
    const int bb = m0 >> 10;
    #pragma unroll
    for (int nf = 0; nf < 4; nf++) {
        int row  = wm * 16 + (lane >> 2);
        int colg = wn * 32 + nf * 8 + (lane & 3) * 2;
        int t    = (m0 + row) & 1023;
        size_t base = (((size_t)(bb * H + h) * T + t) * D) + colg;

        // Q: scale by D^-0.5, split fp16 hi/lo
        {
            const float* c = acc[0][nf];
            uint32_t hi, lo;
            split_pack2h(c[0] * 0.125f, c[1] * 0.125f, hi, lo);
            *(uint32_t*)(g_qh + base) = hi;
            *(uint32_t*)(g_ql + base) = lo;
            split_pack2h(c[2] * 0.125f, c[3] * 0.125f, hi, lo);
            *(uint32_t*)(g_qh + base + 8 * D) = hi;
            *(uint32_t*)(g_ql + base + 8 * D) = lo;
        }
        // K single fp16
        {
            const float* c = acc[1][nf];
            *(uint32_t*)(g_kf + base) =
                pack_h2(__float2half_rn(c[0]), __float2half_rn(c[1]));
            *(uint32_t*)(g_kf + base + 8 * D) =
                pack_h2(__float2half_rn(c[2]), __float2half_rn(c[3]));
        }
        // V single fp16
        {
            const float* c = acc[2][nf];
            *(uint32_t*)(g_vf + base) =
                pack_h2(__float2half_rn(c[0]), __float2half_rn(c[1]));
            *(uint32_t*)(g_vf + base + 8 * D) =
                pack_h2(__float2half_rn(c[2]), __float2half_rn(c[3]));
        }
    }
}

// ===========================================================================
// Kernel 2: causal FlashAttention. Q hi/lo resident in SMEM (2 CTAs/SM);
// S = Qh K + Ql K (split kept — score path is error-sensitive);
// O += P V with SINGLE fp16 P (P in [0,1], rel 2^-11 — margin allows it).
// ===========================================================================
#define BRA 128
#define BCA 64
#define AST 144
#define KVT (64 * AST)            // 9216
#define QH_OFF 0
#define QL_OFF 18432
#define KV_BASE 36864
#define KF_OFF(buf) (KV_BASE + (buf) * 2 * KVT)
#define VF_OFF(buf) (KV_BASE + (buf) * 2 * KVT + KVT)
#define ATT_SMEM (KV_BASE + 4 * KVT)   // 73728

__global__ __launch_bounds__(256, 2)
void flash_attn_mma_kernel(float* __restrict__ out)
{
    extern __shared__ char sm[];
    const uint32_t sbase = smem_u32(sm);

    const int tid  = threadIdx.x;
    const int warp = tid >> 5;
    const int lane = tid & 31;
    const int qt = blockIdx.x;
    const int h  = blockIdx.y;
    const int b  = blockIdx.z;
    const size_t head_base = ((size_t)(b * H + h) * T) * D;
    const int q0 = qt * BRA;

    // ---- Stage Q hi/lo via cp.async (persistent in SMEM) ----
    {
        const __half* qhp = g_qh + head_base + (size_t)q0 * D;
        const __half* qlp = g_ql + head_base + (size_t)q0 * D;
        #pragma unroll
        for (int it = 0; it < 4; it++) {
            int idx = tid + it * 256;
            int r   = idx >> 3;
            int seg = idx & 7;
            uint32_t dofs = r * AST + seg * 16;
            CPA16(sbase + QH_OFF + dofs, qhp + (size_t)r * D + seg * 8);
            CPA16(sbase + QL_OFF + dofs, qlp + (size_t)r * D + seg * 8);
        }
        CPC();
    }

    auto load_tile = [&](int kt) {
        const int buf = kt & 1;
        const size_t tb = head_base + (size_t)kt * BCA * D;
        #pragma unroll
        for (int i = 0; i < 2; i++) {
            int idx = tid + i * 256;
            int r   = idx >> 3;
            int seg = idx & 7;
            uint32_t dofs = r * AST + seg * 16;
            size_t so = tb + (size_t)r * D + seg * 8;
            CPA16(sbase + KF_OFF(buf) + dofs, g_kf + so);
            CPA16(sbase + VF_OFF(buf) + dofs, g_vf + so);
        }
    };

    float o[8][4];
    #pragma unroll
    for (int nf = 0; nf < 8; nf++)
        #pragma unroll
        for (int e = 0; e < 4; e++) o[nf][e] = 0.0f;
    float m0 = -1e30f, m1 = -1e30f, l0 = 0.0f, l1 = 0.0f;

    const int ntiles = 2 * (qt + 1);
    const int rbase  = q0 + warp * 16 + (lane >> 2);

    load_tile(0); CPC();
    if (ntiles > 1) { load_tile(1); CPC(); }

    const int qrow = warp * 16 + (lane & 15);

    for (int kt = 0; kt < ntiles; kt++) {
        const int buf = kt & 1;
        if (kt + 1 < ntiles) { CPW1(); } else { CPW0(); }
        __syncthreads();

        // ---- S = Qh K + Ql K ----
        float sc[8][4];
        #pragma unroll
        for (int nf = 0; nf < 8; nf++)
            #pragma unroll
            for (int e = 0; e < 4; e++) sc[nf][e] = 0.0f;

        const uint32_t kfb = sbase + KF_OFF(buf);
        #pragma unroll
        for (int ks = 0; ks < 4; ks++) {
            uint32_t qh0, qh1, qh2, qh3, ql0, ql1, ql2, ql3;
            {
                int col = ks * 32 + ((lane & 16) ? 16 : 0);
                uint32_t ao = qrow * AST + col;
                LDMX4(qh0, qh1, qh2, qh3, sbase + QH_OFF + ao);
                LDMX4(ql0, ql1, ql2, ql3, sbase + QL_OFF + ao);
            }
            #pragma unroll
            for (int nf16 = 0; nf16 < 4; nf16++) {
                uint32_t kb0, kb1, kb2, kb3;
                int row = nf16 * 16 + (lane & 7) + ((lane & 16) ? 8 : 0);
                int col = ks * 32 + ((lane & 8) ? 16 : 0);
                uint32_t o32 = row * AST + col;
                LDMX4(kb0, kb1, kb2, kb3, kfb + o32);
                float* c0p = sc[nf16 * 2];
                float* c1p = sc[nf16 * 2 + 1];
                MMA_F16(c0p, qh0, qh1, qh2, qh3, kb0, kb1);
                MMA_F16(c0p, ql0, ql1, ql2, ql3, kb0, kb1);
                MMA_F16(c1p, qh0, qh1, qh2, qh3, kb2, kb3);
                MMA_F16(c1p, ql0, ql1, ql2, ql3, kb2, kb3);
            }
        }

        // ---- causal mask on diagonal tiles ----
        if (kt * BCA + 63 > q0 + warp * 16) {
            #pragma unroll
            for (int nf = 0; nf < 8; nf++) {
                int col = kt * BCA + nf * 8 + 2 * (lane & 3);
                if (col     > rbase)     sc[nf][0] = -1e30f;
                if (col + 1 > rbase)     sc[nf][1] = -1e30f;
                if (col     > rbase + 8) sc[nf][2] = -1e30f;
                if (col + 1 > rbase + 8) sc[nf][3] = -1e30f;
            }
        }

        // ---- online softmax ----
        float mt0 = -1e30f, mt1 = -1e30f;
        #pragma unroll
        for (int nf = 0; nf < 8; nf++) {
            mt0 = fmaxf(mt0, fmaxf(sc[nf][0], sc[nf][1]));
            mt1 = fmaxf(mt1, fmaxf(sc[nf][2], sc[nf][3]));
        }
        mt0 = fmaxf(mt0, __shfl_xor_sync(0xFFFFFFFFu, mt0, 1));
        mt0 = fmaxf(mt0, __shfl_xor_sync(0xFFFFFFFFu, mt0, 2));
        mt1 = fmaxf(mt1, __shfl_xor_sync(0xFFFFFFFFu, mt1, 1));
        mt1 = fmaxf(mt1, __shfl_xor_sync(0xFFFFFFFFu, mt1, 2));

        float mn0 = fmaxf(m0, mt0), mn1 = fmaxf(m1, mt1);
        float cr0 = __expf(m0 - mn0), cr1 = __expf(m1 - mn1);
        l0 *= cr0; l1 *= cr1;
        #pragma unroll
        for (int nf = 0; nf < 8; nf++) {
            o[nf][0] *= cr0; o[nf][1] *= cr0;
            o[nf][2] *= cr1; o[nf][3] *= cr1;
            sc[nf][0] = __expf(sc[nf][0] - mn0);
            sc[nf][1] = __expf(sc[nf][1] - mn0);
            sc[nf][2] = __expf(sc[nf][2] - mn1);
            sc[nf][3] = __expf(sc[nf][3] - mn1);
            l0 += sc[nf][0] + sc[nf][1];
            l1 += sc[nf][2] + sc[nf][3];
        }
        m0 = mn0; m1 = mn1;

        // ---- O += P V (single fp16 P) ----
        const uint32_t vfb = sbase + VF_OFF(buf);
        #pragma unroll
        for (int ks = 0; ks < 4; ks++) {
            uint32_t ph[4];
            ph[0] = pack_h2(__float2half_rn(sc[2 * ks][0]),     __float2half_rn(sc[2 * ks][1]));
            ph[1] = pack_h2(__float2half_rn(sc[2 * ks][2]),     __float2half_rn(sc[2 * ks][3]));
            ph[2] = pack_h2(__float2half_rn(sc[2 * ks + 1][0]), __float2half_rn(sc[2 * ks + 1][1]));
            ph[3] = pack_h2(__float2half_rn(sc[2 * ks + 1][2]), __float2half_rn(sc[2 * ks + 1][3]));
            #pragma unroll
            for (int nf16 = 0; nf16 < 4; nf16++) {
                uint32_t vb0, vb1, vb2, vb3;
                int kk = ks * 16 + ((lane & 8) ? 8 : 0) + (lane & 7);
                int cb = (nf16 * 16 + ((lane & 16) ? 8 : 0)) * 2;
                uint32_t o32 = kk * AST + cb;
                LDMX4T(vb0, vb1, vb2, vb3, vfb + o32);
                MMA_F16(o[nf16 * 2],     ph[0], ph[1], ph[2], ph[3], vb0, vb1);
                MMA_F16(o[nf16 * 2 + 1], ph[0], ph[1], ph[2], ph[3], vb2, vb3);
            }
        }

        __syncthreads();
        if (kt + 2 < ntiles) { load_tile(kt + 2); CPC(); }
    }

    l0 += __shfl_xor_sync(0xFFFFFFFFu, l0, 1);
    l0 += __shfl_xor_sync(0xFFFFFFFFu, l0, 2);
    l1 += __shfl_xor_sync(0xFFFFFFFFu, l1, 1);
    l1 += __shfl_xor_sync(0xFFFFFFFFu, l1, 2);
    const float i0 = 1.0f / l0;
    const float i1 = 1.0f / l1;

    float* op = out + ((size_t)(b * T + rbase) * (H * D)) + h * D;
    #pragma unroll
    for (int nf = 0; nf < 8; nf++) {
        int col = nf * 8 + 2 * (lane & 3);
        *(float2*)(op + col) = make_float2(o[nf][0] * i0, o[nf][1] * i0);
        *(float2*)(op + (size_t)8 * (H * D) + col) = make_float2(o[nf][2] * i1, o[nf][3] * i1);
    }
}

// ===========================================================================
extern "C" void kernel_launch(void* const* d_in, const int* in_sizes, int n_in,
                              void* d_out, int out_size)
{
    const float* x  = (const float*)d_in[0];   // [B, T, C]
    const float* Wq = (const float*)d_in[1];   // [H, C, D]
    const float* Wk = (const float*)d_in[2];
    const float* Wv = (const float*)d_in[3];
    float* out = (float*)d_out;                 // [B, T, H*D]

    (void)in_sizes; (void)n_in; (void)out_size;

    static int smem_set = 0;
    if (!smem_set) {
        cudaFuncSetAttribute(qkv_fp16_kernel,
                             cudaFuncAttributeMaxDynamicSharedMemorySize, G_SMEM);
        cudaFuncSetAttribute(flash_attn_mma_kernel,
                             cudaFuncAttributeMaxDynamicSharedMemorySize, ATT_SMEM);
        smem_set = 1;
    }

    conv_x_kernel<<<(size_t)B * T * C / 1024, 256>>>(x);
    conv_w_kernel<<<dim3(H * C * D / 1024, 3), 256>>>(Wq, Wk, Wv);

    dim3 gemm_grid(T * B / 128, H);             // 64 x 16
    qkv_fp16_kernel<<<gemm_grid, 512, G_SMEM>>>();

    dim3 attn_grid(T / BRA, H, B);              // 8 x 16 x 8
    flash_attn_mma_kernel<<<attn_grid, 256, ATT_SMEM>>>(out);
}

// round 13
// speedup vs baseline: 7.2101x; 1.1394x over previous
#include <cuda_runtime.h>
#include <cuda_bf16.h>
#include <cuda_fp16.h>
#include <math.h>
#include <stdint.h>

// Problem constants
#define B 8
#define T 1024
#define C 1024
#define H 16
#define D 64

// Scratch: Q pre-scaled fp16; K/V fp16; x fp16; W fp16
__device__ __half g_qf[(size_t)B * H * T * D];
__device__ __half g_kf[(size_t)B * H * T * D];
__device__ __half g_vf[(size_t)B * H * T * D];
__device__ __half g_xf[(size_t)B * T * C];
__device__ __half g_wh[(size_t)3 * H * C * D];

// ===========================================================================
// Helpers
// ===========================================================================
__device__ __forceinline__ uint32_t smem_u32(const void* p) {
    uint32_t a;
    asm("{ .reg .u64 t; cvta.to.shared.u64 t, %1; cvt.u32.u64 %0, t; }"
        : "=r"(a) : "l"(p));
    return a;
}

#define LDMX4(r0, r1, r2, r3, addr)                                           \
    asm volatile("ldmatrix.sync.aligned.m8n8.x4.shared.b16 {%0,%1,%2,%3}, [%4];" \
                 : "=r"(r0), "=r"(r1), "=r"(r2), "=r"(r3) : "r"(addr))

#define LDMX4T(r0, r1, r2, r3, addr)                                          \
    asm volatile("ldmatrix.sync.aligned.m8n8.x4.trans.shared.b16 {%0,%1,%2,%3}, [%4];" \
                 : "=r"(r0), "=r"(r1), "=r"(r2), "=r"(r3) : "r"(addr))

#define MMA_F16(c, a0, a1, a2, a3, b0, b1)                                    \
    asm volatile("mma.sync.aligned.m16n8k16.row.col.f32.f16.f16.f32 "         \
                 "{%0,%1,%2,%3}, {%4,%5,%6,%7}, {%8,%9}, {%0,%1,%2,%3};"      \
                 : "+f"((c)[0]), "+f"((c)[1]), "+f"((c)[2]), "+f"((c)[3])     \
                 : "r"(a0), "r"(a1), "r"(a2), "r"(a3), "r"(b0), "r"(b1))

#define CPA16(dst, src) \
    asm volatile("cp.async.cg.shared.global [%0], [%1], 16;" :: "r"(dst), "l"(src))
#define CPC()  asm volatile("cp.async.commit_group;" ::: "memory")
#define CPW0() asm volatile("cp.async.wait_group 0;" ::: "memory")
#define CPW1() asm volatile("cp.async.wait_group 1;" ::: "memory")

__device__ __forceinline__ uint32_t pack_h2(__half a, __half b) {
    __half2 h = __halves2half2(a, b);
    return *(uint32_t*)&h;
}

// ===========================================================================
// Kernel 0a: convert x to fp16 (single rounding)
// ===========================================================================
__global__ __launch_bounds__(256) void conv_x_kernel(const float* __restrict__ x)
{
    size_t i = ((size_t)blockIdx.x * 256 + threadIdx.x) * 4;
    float4 v = *(const float4*)(x + i);
    *(uint2*)(g_xf + i) = make_uint2(
        pack_h2(__float2half_rn(v.x), __float2half_rn(v.y)),
        pack_h2(__float2half_rn(v.z), __float2half_rn(v.w)));
}

// ===========================================================================
// Kernel 0b: convert W to fp16 (single rounding)
// ===========================================================================
__global__ __launch_bounds__(256) void conv_w_kernel(const float* __restrict__ Wq,
                                                     const float* __restrict__ Wk,
                                                     const float* __restrict__ Wv)
{
    const int mat = blockIdx.y;
    const float* W = (mat == 0) ? Wq : (mat == 1) ? Wk : Wv;
    size_t i = ((size_t)blockIdx.x * 256 + threadIdx.x) * 4;
    float4 v = *(const float4*)(W + i);
    *(uint2*)(g_wh + (size_t)mat * H * C * D + i) = make_uint2(
        pack_h2(__float2half_rn(v.x), __float2half_rn(v.y)),
        pack_h2(__float2half_rn(v.z), __float2half_rn(v.w)));
}

// ===========================================================================
// Kernel 1: QKV projections, fp16 x fp16.
// B tile FLATTENED to [32 k][192 n] (stride 400B, conflict-free) so the
// three matrices share one fragment space. Warp grid 4x4: warp tile
// 32 rows x 48 cols -> 10 LDSM per 24 MMAs (was 14). 512 threads,
// 3-stage cp.async pipeline, one barrier per chunk.
// ===========================================================================
#define BK 32
#define NCHUNK (C / BK)
#define BSTR 400
#define GBUF (10240 + 32 * BSTR)          // A 10240 + B 12800 = 23040
#define GA(buf)  ((buf) * GBUF)
#define GB(buf)  ((buf) * GBUF + 10240)
#define G_SMEM (3 * GBUF)                 // 69120

__global__ __launch_bounds__(512)
void qkv_fp16_kernel()
{
    extern __shared__ char sm[];
    const uint32_t sbase = smem_u32(sm);

    const int tid  = threadIdx.x;
    const int warp = tid >> 5;            // 0..15
    const int lane = tid & 31;
    const int wm   = warp >> 2;           // 0..3 -> rows [wm*32, +32)
    const int wn   = warp & 3;            // 0..3 -> cols [wn*48, +48)

    const int m0 = blockIdx.x * 128;
    const int h  = blockIdx.y;

    float acc[2][6][4];                   // [mf][n8 frag][4]
    #pragma unroll
    for (int i = 0; i < 2; i++)
        #pragma unroll
        for (int j = 0; j < 6; j++)
            #pragma unroll
            for (int k = 0; k < 4; k++)
                acc[i][j][k] = 0.0f;

    auto load_chunk = [&](int ci) {
        const int buf = ci % 3;
        const int k0  = ci * BK;
        // A: 128 rows x 4 16B-segs = 512 cp.async, one per thread
        {
            int r   = tid >> 2;
            int seg = tid & 3;
            CPA16(sbase + GA(buf) + r * 80 + seg * 16,
                  g_xf + (size_t)(m0 + r) * C + k0 + seg * 8);
        }
        // B: 32 k-rows x 24 16B-segs (3 mats x 8) = 768 cp.async
        #pragma unroll
        for (int it = 0; it < 2; it++) {
            int idx = tid + it * 512;
            if (idx < 768) {
                int k   = idx / 24;
                int rem = idx - k * 24;
                int mat = rem >> 3;
                int seg = rem & 7;
                CPA16(sbase + GB(buf) + k * BSTR + mat * 128 + seg * 16,
                      g_wh + ((size_t)(mat * H + h)) * C * D
                           + (size_t)(k0 + k) * D + seg * 8);
            }
        }
    };

    load_chunk(0); CPC();
    load_chunk(1); CPC();

    for (int ci = 0; ci < NCHUNK; ci++) {
        const int buf = ci % 3;
        if (ci < NCHUNK - 1) { CPW1(); } else { CPW0(); }
        __syncthreads();

        if (ci + 2 < NCHUNK) { load_chunk(ci + 2); CPC(); }

        // ---- A fragments: 2 mf x 2 ks ----
        uint32_t ah[2][2][4];
        {
            const uint32_t ab = sbase + GA(buf);
            #pragma unroll
            for (int mf = 0; mf < 2; mf++) {
                #pragma unroll
                for (int ks = 0; ks < 2; ks++) {
                    int row = wm * 32 + mf * 16 + (lane & 15);
                    int col = ks * 32 + ((lane & 16) ? 16 : 0);
                    LDMX4(ah[mf][ks][0], ah[mf][ks][1], ah[mf][ks][2], ah[mf][ks][3],
                          ab + row * 80 + col);
                }
            }
        }

        // ---- B fragments + MMA: 2 ks x 3 col-frags (16 cols each) ----
        const uint32_t bb = sbase + GB(buf);
        #pragma unroll
        for (int ks = 0; ks < 2; ks++) {
            #pragma unroll
            for (int f = 0; f < 3; f++) {
                uint32_t b0, b1, b2, b3;
                int kk = ks * 16 + (lane & 15);
                int cb = (wn * 48 + f * 16 + ((lane & 16) ? 8 : 0)) * 2;
                LDMX4T(b0, b1, b2, b3, bb + kk * BSTR + cb);
                #pragma unroll
                for (int mf = 0; mf < 2; mf++) {
                    MMA_F16(acc[mf][f * 2],     ah[mf][ks][0], ah[mf][ks][1],
                            ah[mf][ks][2], ah[mf][ks][3], b0, b1);
                    MMA_F16(acc[mf][f * 2 + 1], ah[mf][ks][0], ah[mf][ks][1],
                            ah[mf][ks][2], ah[mf][ks][3], b2, b3);
                }
            }
        }
    }

    // ---- epilogue: all outputs single fp16; Q pre-scaled by D^-0.5 ----
    const int bb = m0 >> 10;
    #pragma unroll
    for (int mf = 0; mf < 2; mf++) {
        #pragma unroll
        for (int f8 = 0; f8 < 6; f8++) {
            int ng   = wn * 48 + f8 * 8;           // warp-uniform
            int mat  = ng >> 6;
            int coln = (ng & 63) + (lane & 3) * 2;
            int row  = wm * 32 + mf * 16 + (lane >> 2);
            int t    = (m0 + row) & 1023;
            size_t base = (((size_t)(bb * H + h) * T + t) * D) + coln;

            const float* c = acc[mf][f8];
            float s = (mat == 0) ? 0.125f : 1.0f;
            __half* g = (mat == 0) ? g_qf : (mat == 1) ? g_kf : g_vf;
            *(uint32_t*)(g + base) =
                pack_h2(__float2half_rn(c[0] * s), __float2half_rn(c[1] * s));
            *(uint32_t*)(g + base + 8 * D) =
                pack_h2(__float2half_rn(c[2] * s), __float2half_rn(c[3] * s));
        }
    }
}

// ===========================================================================
// Kernel 2: causal FlashAttention. Q single fp16 (pre-scaled) resident in
// SMEM; S = Q K (one term); O += P V (single fp16 P). 2 CTAs/SM.
// ===========================================================================
#define BRA 128
#define BCA 64
#define AST 144
#define KVT (64 * AST)            // 9216
#define QF_OFF 0
#define KV_BASE 18432
#define KF_OFF(buf) (KV_BASE + (buf) * 2 * KVT)
#define VF_OFF(buf) (KV_BASE + (buf) * 2 * KVT + KVT)
#define ATT_SMEM (KV_BASE + 4 * KVT)   // 55296

__global__ __launch_bounds__(256, 2)
void flash_attn_mma_kernel(float* __restrict__ out)
{
    extern __shared__ char sm[];
    const uint32_t sbase = smem_u32(sm);

    const int tid  = threadIdx.x;
    const int warp = tid >> 5;
    const int lane = tid & 31;
    const int qt = blockIdx.x;
    const int h  = blockIdx.y;
    const int b  = blockIdx.z;
    const size_t head_base = ((size_t)(b * H + h) * T) * D;
    const int q0 = qt * BRA;

    // ---- Stage Q via cp.async (persistent in SMEM) ----
    {
        const __half* qp = g_qf + head_base + (size_t)q0 * D;
        #pragma unroll
        for (int it = 0; it < 4; it++) {
            int idx = tid + it * 256;
            int r   = idx >> 3;
            int seg = idx & 7;
            CPA16(sbase + QF_OFF + r * AST + seg * 16, qp + (size_t)r * D + seg * 8);
        }
        CPC();
    }

    auto load_tile = [&](int kt) {
        const int buf = kt & 1;
        const size_t tb = head_base + (size_t)kt * BCA * D;
        #pragma unroll
        for (int i = 0; i < 2; i++) {
            int idx = tid + i * 256;
            int r   = idx >> 3;
            int seg = idx & 7;
            uint32_t dofs = r * AST + seg * 16;
            size_t so = tb + (size_t)r * D + seg * 8;
            CPA16(sbase + KF_OFF(buf) + dofs, g_kf + so);
            CPA16(sbase + VF_OFF(buf) + dofs, g_vf + so);
        }
    };

    float o[8][4];
    #pragma unroll
    for (int nf = 0; nf < 8; nf++)
        #pragma unroll
        for (int e = 0; e < 4; e++) o[nf][e] = 0.0f;
    float m0 = -1e30f, m1 = -1e30f, l0 = 0.0f, l1 = 0.0f;

    const int ntiles = 2 * (qt + 1);
    const int rbase  = q0 + warp * 16 + (lane >> 2);

    load_tile(0); CPC();
    if (ntiles > 1) { load_tile(1); CPC(); }

    const int qrow = warp * 16 + (lane & 15);

    for (int kt = 0; kt < ntiles; kt++) {
        const int buf = kt & 1;
        if (kt + 1 < ntiles) { CPW1(); } else { CPW0(); }
        __syncthreads();

        // ---- S = Q K ----
        float sc[8][4];
        #pragma unroll
        for (int nf = 0; nf < 8; nf++)
            #pragma unroll
            for (int e = 0; e < 4; e++) sc[nf][e] = 0.0f;

        const uint32_t kfb = sbase + KF_OFF(buf);
        #pragma unroll
        for (int ks = 0; ks < 4; ks++) {
            uint32_t q0r, q1r, q2r, q3r;
            {
                int col = ks * 32 + ((lane & 16) ? 16 : 0);
                LDMX4(q0r, q1r, q2r, q3r, sbase + QF_OFF + qrow * AST + col);
            }
            #pragma unroll
            for (int nf16 = 0; nf16 < 4; nf16++) {
                uint32_t kb0, kb1, kb2, kb3;
                int row = nf16 * 16 + (lane & 7) + ((lane & 16) ? 8 : 0);
                int col = ks * 32 + ((lane & 8) ? 16 : 0);
                LDMX4(kb0, kb1, kb2, kb3, kfb + row * AST + col);
                MMA_F16(sc[nf16 * 2],     q0r, q1r, q2r, q3r, kb0, kb1);
                MMA_F16(sc[nf16 * 2 + 1], q0r, q1r, q2r, q3r, kb2, kb3);
            }
        }

        // ---- causal mask on diagonal tiles ----
        if (kt * BCA + 63 > q0 + warp * 16) {
            #pragma unroll
            for (int nf = 0; nf < 8; nf++) {
                int col = kt * BCA + nf * 8 + 2 * (lane & 3);
                if (col     > rbase)     sc[nf][0] = -1e30f;
                if (col + 1 > rbase)     sc[nf][1] = -1e30f;
                if (col     > rbase + 8) sc[nf][2] = -1e30f;
                if (col + 1 > rbase + 8) sc[nf][3] = -1e30f;
            }
        }

        // ---- online softmax ----
        float mt0 = -1e30f, mt1 = -1e30f;
        #pragma unroll
        for (int nf = 0; nf < 8; nf++) {
            mt0 = fmaxf(mt0, fmaxf(sc[nf][0], sc[nf][1]));
            mt1 = fmaxf(mt1, fmaxf(sc[nf][2], sc[nf][3]));
        }
        mt0 = fmaxf(mt0, __shfl_xor_sync(0xFFFFFFFFu, mt0, 1));
        mt0 = fmaxf(mt0, __shfl_xor_sync(0xFFFFFFFFu, mt0, 2));
        mt1 = fmaxf(mt1, __shfl_xor_sync(0xFFFFFFFFu, mt1, 1));
        mt1 = fmaxf(mt1, __shfl_xor_sync(0xFFFFFFFFu, mt1, 2));

        float mn0 = fmaxf(m0, mt0), mn1 = fmaxf(m1, mt1);
        float cr0 = __expf(m0 - mn0), cr1 = __expf(m1 - mn1);
        l0 *= cr0; l1 *= cr1;
        #pragma unroll
        for (int nf = 0; nf < 8; nf++) {
            o[nf][0] *= cr0; o[nf][1] *= cr0;
            o[nf][2] *= cr1; o[nf][3] *= cr1;
            sc[nf][0] = __expf(sc[nf][0] - mn0);
            sc[nf][1] = __expf(sc[nf][1] - mn0);
            sc[nf][2] = __expf(sc[nf][2] - mn1);
            sc[nf][3] = __expf(sc[nf][3] - mn1);
            l0 += sc[nf][0] + sc[nf][1];
            l1 += sc[nf][2] + sc[nf][3];
        }
        m0 = mn0; m1 = mn1;

        // ---- O += P V (single fp16 P) ----
        const uint32_t vfb = sbase + VF_OFF(buf);
        #pragma unroll
        for (int ks = 0; ks < 4; ks++) {
            uint32_t ph[4];
            ph[0] = pack_h2(__float2half_rn(sc[2 * ks][0]),     __float2half_rn(sc[2 * ks][1]));
            ph[1] = pack_h2(__float2half_rn(sc[2 * ks][2]),     __float2half_rn(sc[2 * ks][3]));
            ph[2] = pack_h2(__float2half_rn(sc[2 * ks + 1][0]), __float2half_rn(sc[2 * ks + 1][1]));
            ph[3] = pack_h2(__float2half_rn(sc[2 * ks + 1][2]), __float2half_rn(sc[2 * ks + 1][3]));
            #pragma unroll
            for (int nf16 = 0; nf16 < 4; nf16++) {
                uint32_t vb0, vb1, vb2, vb3;
                int kk = ks * 16 + ((lane & 8) ? 8 : 0) + (lane & 7);
                int cb = (nf16 * 16 + ((lane & 16) ? 8 : 0)) * 2;
                LDMX4T(vb0, vb1, vb2, vb3, vfb + kk * AST + cb);
                MMA_F16(o[nf16 * 2],     ph[0], ph[1], ph[2], ph[3], vb0, vb1);
                MMA_F16(o[nf16 * 2 + 1], ph[0], ph[1], ph[2], ph[3], vb2, vb3);
            }
        }

        __syncthreads();
        if (kt + 2 < ntiles) { load_tile(kt + 2); CPC(); }
    }

    l0 += __shfl_xor_sync(0xFFFFFFFFu, l0, 1);
    l0 += __shfl_xor_sync(0xFFFFFFFFu, l0, 2);
    l1 += __shfl_xor_sync(0xFFFFFFFFu, l1, 1);
    l1 += __shfl_xor_sync(0xFFFFFFFFu, l1, 2);
    const float i0 = 1.0f / l0;
    const float i1 = 1.0f / l1;

    float* op = out + ((size_t)(b * T + rbase) * (H * D)) + h * D;
    #pragma unroll
    for (int nf = 0; nf < 8; nf++) {
        int col = nf * 8 + 2 * (lane & 3);
        *(float2*)(op + col) = make_float2(o[nf][0] * i0, o[nf][1] * i0);
        *(float2*)(op + (size_t)8 * (H * D) + col) = make_float2(o[nf][2] * i1, o[nf][3] * i1);
    }
}

// ===========================================================================
extern "C" void kernel_launch(void* const* d_in, const int* in_sizes, int n_in,
                              void* d_out, int out_size)
{
    const float* x  = (const float*)d_in[0];   // [B, T, C]
    const float* Wq = (const float*)d_in[1];   // [H, C, D]
    const float* Wk = (const float*)d_in[2];
    const float* Wv = (const float*)d_in[3];
    float* out = (float*)d_out;                 // [B, T, H*D]

    (void)in_sizes; (void)n_in; (void)out_size;

    static int smem_set = 0;
    if (!smem_set) {
        cudaFuncSetAttribute(qkv_fp16_kernel,
                             cudaFuncAttributeMaxDynamicSharedMemorySize, G_SMEM);
        cudaFuncSetAttribute(flash_attn_mma_kernel,
                             cudaFuncAttributeMaxDynamicSharedMemorySize, ATT_SMEM);
        smem_set = 1;
    }

    conv_x_kernel<<<(size_t)B * T * C / 1024, 256>>>(x);
    conv_w_kernel<<<dim3(H * C * D / 1024, 3), 256>>>(Wq, Wk, Wv);

    dim3 gemm_grid(T * B / 128, H);             // 64 x 16
    qkv_fp16_kernel<<<gemm_grid, 512, G_SMEM>>>();

    dim3 attn_grid(T / BRA, H, B);              // 8 x 16 x 8
    flash_attn_mma_kernel<<<attn_grid, 256, ATT_SMEM>>>(out);
}

// round 15
// speedup vs baseline: 7.5219x; 1.0432x over previous
#include <cuda_runtime.h>
#include <cuda_bf16.h>
#include <cuda_fp16.h>
#include <math.h>
#include <stdint.h>

// Problem constants
#define B 8
#define T 1024
#define C 1024
#define H 16
#define D 64

// Scratch: Q pre-scaled fp16; K/V fp16; x fp16; W fp16
__device__ __half g_qf[(size_t)B * H * T * D];
__device__ __half g_kf[(size_t)B * H * T * D];
__device__ __half g_vf[(size_t)B * H * T * D];
__device__ __half g_xf[(size_t)B * T * C];
__device__ __half g_wh[(size_t)3 * H * C * D];

// ===========================================================================
// Helpers
// ===========================================================================
__device__ __forceinline__ uint32_t smem_u32(const void* p) {
    uint32_t a;
    asm("{ .reg .u64 t; cvta.to.shared.u64 t, %1; cvt.u32.u64 %0, t; }"
        : "=r"(a) : "l"(p));
    return a;
}

#define LDMX4(r0, r1, r2, r3, addr)                                           \
    asm volatile("ldmatrix.sync.aligned.m8n8.x4.shared.b16 {%0,%1,%2,%3}, [%4];" \
                 : "=r"(r0), "=r"(r1), "=r"(r2), "=r"(r3) : "r"(addr))

#define LDMX4T(r0, r1, r2, r3, addr)                                          \
    asm volatile("ldmatrix.sync.aligned.m8n8.x4.trans.shared.b16 {%0,%1,%2,%3}, [%4];" \
                 : "=r"(r0), "=r"(r1), "=r"(r2), "=r"(r3) : "r"(addr))

#define MMA_F16(c, a0, a1, a2, a3, b0, b1)                                    \
    asm volatile("mma.sync.aligned.m16n8k16.row.col.f32.f16.f16.f32 "         \
                 "{%0,%1,%2,%3}, {%4,%5,%6,%7}, {%8,%9}, {%0,%1,%2,%3};"      \
                 : "+f"((c)[0]), "+f"((c)[1]), "+f"((c)[2]), "+f"((c)[3])     \
                 : "r"(a0), "r"(a1), "r"(a2), "r"(a3), "r"(b0), "r"(b1))

#define CPA16(dst, src) \
    asm volatile("cp.async.cg.shared.global [%0], [%1], 16;" :: "r"(dst), "l"(src))
#define CPC()  asm volatile("cp.async.commit_group;" ::: "memory")
#define CPW0() asm volatile("cp.async.wait_group 0;" ::: "memory")
#define CPW1() asm volatile("cp.async.wait_group 1;" ::: "memory")

__device__ __forceinline__ uint32_t pack_h2(__half a, __half b) {
    __half2 h = __halves2half2(a, b);
    return *(uint32_t*)&h;
}

// ===========================================================================
// Kernel 0a: convert x to fp16 (single rounding)
// ===========================================================================
__global__ __launch_bounds__(256) void conv_x_kernel(const float* __restrict__ x)
{
    size_t i = ((size_t)blockIdx.x * 256 + threadIdx.x) * 4;
    float4 v = *(const float4*)(x + i);
    *(uint2*)(g_xf + i) = make_uint2(
        pack_h2(__float2half_rn(v.x), __float2half_rn(v.y)),
        pack_h2(__float2half_rn(v.z), __float2half_rn(v.w)));
}

// ===========================================================================
// Kernel 0b: convert W to fp16 (single rounding)
// ===========================================================================
__global__ __launch_bounds__(256) void conv_w_kernel(const float* __restrict__ Wq,
                                                     const float* __restrict__ Wk,
                                                     const float* __restrict__ Wv)
{
    const int mat = blockIdx.y;
    const float* W = (mat == 0) ? Wq : (mat == 1) ? Wk : Wv;
    size_t i = ((size_t)blockIdx.x * 256 + threadIdx.x) * 4;
    float4 v = *(const float4*)(W + i);
    *(uint2*)(g_wh + (size_t)mat * H * C * D + i) = make_uint2(
        pack_h2(__float2half_rn(v.x), __float2half_rn(v.y)),
        pack_h2(__float2half_rn(v.z), __float2half_rn(v.w)));
}

// ===========================================================================
// Kernel 1: QKV projections, fp16 x fp16. BK=64 (half the barriers of BK=32;
// same K accumulation order -> bit-identical results). B tile flattened to
// [64 k][192 n] (stride 400B); A stride 272B — both ldmatrix conflict-free.
// Warp grid 4x4 (warp tile 32 rows x 48 cols). 512 threads, 3-stage
// cp.async pipeline, one barrier per chunk, prefetch before compute.
// ===========================================================================
#define BK 64
#define NCHUNK (C / BK)                   // 16
#define ASTR 272
#define BSTR 400
#define GBUF (128 * ASTR + 64 * BSTR)     // 34816 + 25600 = 60416
#define GA(buf)  ((buf) * GBUF)
#define GB(buf)  ((buf) * GBUF + 128 * ASTR)
#define G_SMEM (3 * GBUF)                 // 181248

__global__ __launch_bounds__(512)
void qkv_fp16_kernel()
{
    extern __shared__ char sm[];
    const uint32_t sbase = smem_u32(sm);

    const int tid  = threadIdx.x;
    const int warp = tid >> 5;            // 0..15
    const int lane = tid & 31;
    const int wm   = warp >> 2;           // 0..3 -> rows [wm*32, +32)
    const int wn   = warp & 3;            // 0..3 -> cols [wn*48, +48)

    const int m0 = blockIdx.x * 128;
    const int h  = blockIdx.y;

    float acc[2][6][4];                   // [mf][n8 frag][4]
    #pragma unroll
    for (int i = 0; i < 2; i++)
        #pragma unroll
        for (int j = 0; j < 6; j++)
            #pragma unroll
            for (int k = 0; k < 4; k++)
                acc[i][j][k] = 0.0f;

    auto load_chunk = [&](int ci) {
        const int buf = ci % 3;
        const int k0  = ci * BK;
        // A: 128 rows x 8 16B-segs = 1024 cp.async, 2 per thread
        #pragma unroll
        for (int i = 0; i < 2; i++) {
            int idx = tid + i * 512;
            int r   = idx >> 3;
            int seg = idx & 7;
            CPA16(sbase + GA(buf) + r * ASTR + seg * 16,
                  g_xf + (size_t)(m0 + r) * C + k0 + seg * 8);
        }
        // B: 64 k-rows x 24 16B-segs (3 mats x 8) = 1536 cp.async, 3 per thread
        #pragma unroll
        for (int i = 0; i < 3; i++) {
            int idx = tid + i * 512;
            int k   = idx / 24;
            int rem = idx - k * 24;
            int mat = rem >> 3;
            int seg = rem & 7;
            CPA16(sbase + GB(buf) + k * BSTR + mat * 128 + seg * 16,
                  g_wh + ((size_t)(mat * H + h)) * C * D
                       + (size_t)(k0 + k) * D + seg * 8);
        }
    };

    load_chunk(0); CPC();
    load_chunk(1); CPC();

    for (int ci = 0; ci < NCHUNK; ci++) {
        const int buf = ci % 3;
        if (ci < NCHUNK - 1) { CPW1(); } else { CPW0(); }
        __syncthreads();

        if (ci + 2 < NCHUNK) { load_chunk(ci + 2); CPC(); }

        // ---- A fragments: 2 mf x 4 ks ----
        uint32_t ah[2][4][4];
        {
            const uint32_t ab = sbase + GA(buf);
            #pragma unroll
            for (int mf = 0; mf < 2; mf++) {
                #pragma unroll
                for (int ks = 0; ks < 4; ks++) {
                    int row = wm * 32 + mf * 16 + (lane & 15);
                    int col = ks * 32 + ((lane & 16) ? 16 : 0);
                    LDMX4(ah[mf][ks][0], ah[mf][ks][1], ah[mf][ks][2], ah[mf][ks][3],
                          ab + row * ASTR + col);
                }
            }
        }

        // ---- B fragments + MMA: 4 ks x 3 col-frags (16 cols each) ----
        const uint32_t bb = sbase + GB(buf);
        #pragma unroll
        for (int ks = 0; ks < 4; ks++) {
            #pragma unroll
            for (int f = 0; f < 3; f++) {
                uint32_t b0, b1, b2, b3;
                int kk = ks * 16 + (lane & 15);
                int cb = (wn * 48 + f * 16 + ((lane & 16) ? 8 : 0)) * 2;
                LDMX4T(b0, b1, b2, b3, bb + kk * BSTR + cb);
                #pragma unroll
                for (int mf = 0; mf < 2; mf++) {
                    MMA_F16(acc[mf][f * 2],     ah[mf][ks][0], ah[mf][ks][1],
                            ah[mf][ks][2], ah[mf][ks][3], b0, b1);
                    MMA_F16(acc[mf][f * 2 + 1], ah[mf][ks][0], ah[mf][ks][1],
                            ah[mf][ks][2], ah[mf][ks][3], b2, b3);
                }
            }
        }
    }

    // ---- epilogue: all outputs single fp16; Q pre-scaled by D^-0.5 ----
    const int bb = m0 >> 10;
    #pragma unroll
    for (int mf = 0; mf < 2; mf++) {
        #pragma unroll
        for (int f8 = 0; f8 < 6; f8++) {
            int ng   = wn * 48 + f8 * 8;           // warp-uniform
            int mat  = ng >> 6;
            int coln = (ng & 63) + (lane & 3) * 2;
            int row  = wm * 32 + mf * 16 + (lane >> 2);
            int t    = (m0 + row) & 1023;
            size_t base = (((size_t)(bb * H + h) * T + t) * D) + coln;

            const float* c = acc[mf][f8];
            float s = (mat == 0) ? 0.125f : 1.0f;
            __half* g = (mat == 0) ? g_qf : (mat == 1) ? g_kf : g_vf;
            *(uint32_t*)(g + base) =
                pack_h2(__float2half_rn(c[0] * s), __float2half_rn(c[1] * s));
            *(uint32_t*)(g + base + 8 * D) =
                pack_h2(__float2half_rn(c[2] * s), __float2half_rn(c[3] * s));
        }
    }
}

// ===========================================================================
// Kernel 2: causal FlashAttention. Q single fp16 (pre-scaled) in SMEM;
// S = Q K; O += P V (single fp16 P). 2 CTAs/SM.
// NEW: per-warp causal group skip. Key-group kg (16 keys) of tile kt is
// needed by warp w iff 4*kt + kg <= 8*qt + w (warp-uniform). Skipped groups
// had p == 0 exactly before -> outputs bit-identical, ~10% less MMA+exp.
// ===========================================================================
#define BRA 128
#define BCA 64
#define AST 144
#define KVT (64 * AST)            // 9216
#define QF_OFF 0
#define KV_BASE 18432
#define KF_OFF(buf) (KV_BASE + (buf) * 2 * KVT)
#define VF_OFF(buf) (KV_BASE + (buf) * 2 * KVT + KVT)
#define ATT_SMEM (KV_BASE + 4 * KVT)   // 55296

__global__ __launch_bounds__(256, 2)
void flash_attn_mma_kernel(float* __restrict__ out)
{
    extern __shared__ char sm[];
    const uint32_t sbase = smem_u32(sm);

    const int tid  = threadIdx.x;
    const int warp = tid >> 5;
    const int lane = tid & 31;
    const int qt = blockIdx.x;
    const int h  = blockIdx.y;
    const int b  = blockIdx.z;
    const size_t head_base = ((size_t)(b * H + h) * T) * D;
    const int q0 = qt * BRA;

    // ---- Stage Q via cp.async (persistent in SMEM) ----
    {
        const __half* qp = g_qf + head_base + (size_t)q0 * D;
        #pragma unroll
        for (int it = 0; it < 4; it++) {
            int idx = tid + it * 256;
            int r   = idx >> 3;
            int seg = idx & 7;
            CPA16(sbase + QF_OFF + r * AST + seg * 16, qp + (size_t)r * D + seg * 8);
        }
        CPC();
    }

    auto load_tile = [&](int kt) {
        const int buf = kt & 1;
        const size_t tb = head_base + (size_t)kt * BCA * D;
        #pragma unroll
        for (int i = 0; i < 2; i++) {
            int idx = tid + i * 256;
            int r   = idx >> 3;
            int seg = idx & 7;
            uint32_t dofs = r * AST + seg * 16;
            size_t so = tb + (size_t)r * D + seg * 8;
            CPA16(sbase + KF_OFF(buf) + dofs, g_kf + so);
            CPA16(sbase + VF_OFF(buf) + dofs, g_vf + so);
        }
    };

    float o[8][4];
    #pragma unroll
    for (int nf = 0; nf < 8; nf++)
        #pragma unroll
        for (int e = 0; e < 4; e++) o[nf][e] = 0.0f;
    float m0 = -1e30f, m1 = -1e30f, l0 = 0.0f, l1 = 0.0f;

    const int ntiles = 2 * (qt + 1);
    const int rbase  = q0 + warp * 16 + (lane >> 2);
    const int glim   = 8 * qt + warp;      // allowed: 4*kt + kg <= glim

    load_tile(0); CPC();
    if (ntiles > 1) { load_tile(1); CPC(); }

    const int qrow = warp * 16 + (lane & 15);

    for (int kt = 0; kt < ntiles; kt++) {
        const int buf = kt & 1;
        if (kt + 1 < ntiles) { CPW1(); } else { CPW0(); }
        __syncthreads();

        // number of allowed 16-key groups in this tile (warp-uniform, 0..4)
        int ng = glim - 4 * kt + 1;
        if (ng > 4) ng = 4;

        // ---- S = Q K (allowed groups only) ----
        float sc[8][4];
        #pragma unroll
        for (int nf = 0; nf < 8; nf++)
            #pragma unroll
            for (int e = 0; e < 4; e++) sc[nf][e] = 0.0f;

        if (ng > 0) {
            const uint32_t kfb = sbase + KF_OFF(buf);
            #pragma unroll
            for (int ks = 0; ks < 4; ks++) {
                uint32_t q0r, q1r, q2r, q3r;
                {
                    int col = ks * 32 + ((lane & 16) ? 16 : 0);
                    LDMX4(q0r, q1r, q2r, q3r, sbase + QF_OFF + qrow * AST + col);
                }
                #pragma unroll
                for (int kg = 0; kg < 4; kg++) {
                    if (kg < ng) {
                        uint32_t kb0, kb1, kb2, kb3;
                        int row = kg * 16 + (lane & 7) + ((lane & 16) ? 8 : 0);
                        int col = ks * 32 + ((lane & 8) ? 16 : 0);
                        LDMX4(kb0, kb1, kb2, kb3, kfb + row * AST + col);
                        MMA_F16(sc[kg * 2],     q0r, q1r, q2r, q3r, kb0, kb1);
                        MMA_F16(sc[kg * 2 + 1], q0r, q1r, q2r, q3r, kb2, kb3);
                    }
                }
            }

            // ---- causal mask (boundary group) ----
            if (kt * BCA + 63 > q0 + warp * 16) {
                #pragma unroll
                for (int nf = 0; nf < 8; nf++) {
                    int col = kt * BCA + nf * 8 + 2 * (lane & 3);
                    if (col     > rbase)     sc[nf][0] = -1e30f;
                    if (col + 1 > rbase)     sc[nf][1] = -1e30f;
                    if (col     > rbase + 8) sc[nf][2] = -1e30f;
                    if (col + 1 > rbase + 8) sc[nf][3] = -1e30f;
                }
            }

            // ---- online softmax (allowed groups only) ----
            float mt0 = -1e30f, mt1 = -1e30f;
            #pragma unroll
            for (int kg = 0; kg < 4; kg++) {
                if (kg < ng) {
                    #pragma unroll
                    for (int f = 0; f < 2; f++) {
                        mt0 = fmaxf(mt0, fmaxf(sc[kg * 2 + f][0], sc[kg * 2 + f][1]));
                        mt1 = fmaxf(mt1, fmaxf(sc[kg * 2 + f][2], sc[kg * 2 + f][3]));
                    }
                }
            }
            mt0 = fmaxf(mt0, __shfl_xor_sync(0xFFFFFFFFu, mt0, 1));
            mt0 = fmaxf(mt0, __shfl_xor_sync(0xFFFFFFFFu, mt0, 2));
            mt1 = fmaxf(mt1, __shfl_xor_sync(0xFFFFFFFFu, mt1, 1));
            mt1 = fmaxf(mt1, __shfl_xor_sync(0xFFFFFFFFu, mt1, 2));

            float mn0 = fmaxf(m0, mt0), mn1 = fmaxf(m1, mt1);
            float cr0 = __expf(m0 - mn0), cr1 = __expf(m1 - mn1);
            l0 *= cr0; l1 *= cr1;
            #pragma unroll
            for (int nf = 0; nf < 8; nf++) {
                o[nf][0] *= cr0; o[nf][1] *= cr0;
                o[nf][2] *= cr1; o[nf][3] *= cr1;
            }
            #pragma unroll
            for (int kg = 0; kg < 4; kg++) {
                if (kg < ng) {
                    #pragma unroll
                    for (int f = 0; f < 2; f++) {
                        float* s = sc[kg * 2 + f];
                        s[0] = __expf(s[0] - mn0);
                        s[1] = __expf(s[1] - mn0);
                        s[2] = __expf(s[2] - mn1);
                        s[3] = __expf(s[3] - mn1);
                        l0 += s[0] + s[1];
                        l1 += s[2] + s[3];
                    }
                }
            }
            m0 = mn0; m1 = mn1;

            // ---- O += P V (allowed key groups only; single fp16 P) ----
            const uint32_t vfb = sbase + VF_OFF(buf);
            #pragma unroll
            for (int ks = 0; ks < 4; ks++) {
                if (ks < ng) {
                    uint32_t ph[4];
                    ph[0] = pack_h2(__float2half_rn(sc[2 * ks][0]),     __float2half_rn(sc[2 * ks][1]));
                    ph[1] = pack_h2(__float2half_rn(sc[2 * ks][2]),     __float2half_rn(sc[2 * ks][3]));
                    ph[2] = pack_h2(__float2half_rn(sc[2 * ks + 1][0]), __float2half_rn(sc[2 * ks + 1][1]));
                    ph[3] = pack_h2(__float2half_rn(sc[2 * ks + 1][2]), __float2half_rn(sc[2 * ks + 1][3]));
                    #pragma unroll
                    for (int nf16 = 0; nf16 < 4; nf16++) {
                        uint32_t vb0, vb1, vb2, vb3;
                        int kk = ks * 16 + ((lane & 8) ? 8 : 0) + (lane & 7);
                        int cb = (nf16 * 16 + ((lane & 16) ? 8 : 0)) * 2;
                        LDMX4T(vb0, vb1, vb2, vb3, vfb + kk * AST + cb);
                        MMA_F16(o[nf16 * 2],     ph[0], ph[1], ph[2], ph[3], vb0, vb1);
                        MMA_F16(o[nf16 * 2 + 1], ph[0], ph[1], ph[2], ph[3], vb2, vb3);
                    }
                }
            }
        }

        __syncthreads();
        if (kt + 2 < ntiles) { load_tile(kt + 2); CPC(); }
    }

    l0 += __shfl_xor_sync(0xFFFFFFFFu, l0, 1);
    l0 += __shfl_xor_sync(0xFFFFFFFFu, l0, 2);
    l1 += __shfl_xor_sync(0xFFFFFFFFu, l1, 1);
    l1 += __shfl_xor_sync(0xFFFFFFFFu, l1, 2);
    const float i0 = 1.0f / l0;
    const float i1 = 1.0f / l1;

    float* op = out + ((size_t)(b * T + rbase) * (H * D)) + h * D;
    #pragma unroll
    for (int nf = 0; nf < 8; nf++) {
        int col = nf * 8 + 2 * (lane & 3);
        *(float2*)(op + col) = make_float2(o[nf][0] * i0, o[nf][1] * i0);
        *(float2*)(op + (size_t)8 * (H * D) + col) = make_float2(o[nf][2] * i1, o[nf][3] * i1);
    }
}

// ===========================================================================
extern "C" void kernel_launch(void* const* d_in, const int* in_sizes, int n_in,
                              void* d_out, int out_size)
{
    const float* x  = (const float*)d_in[0];   // [B, T, C]
    const float* Wq = (const float*)d_in[1];   // [H, C, D]
    const float* Wk = (const float*)d_in[2];
    const float* Wv = (const float*)d_in[3];
    float* out = (float*)d_out;                 // [B, T, H*D]

    (void)in_sizes; (void)n_in; (void)out_size;

    static int smem_set = 0;
    if (!smem_set) {
        cudaFuncSetAttribute(qkv_fp16_kernel,
                             cudaFuncAttributeMaxDynamicSharedMemorySize, G_SMEM);
        cudaFuncSetAttribute(flash_attn_mma_kernel,
                             cudaFuncAttributeMaxDynamicSharedMemorySize, ATT_SMEM);
        smem_set = 1;
    }

    conv_x_kernel<<<(size_t)B * T * C / 1024, 256>>>(x);
    conv_w_kernel<<<dim3(H * C * D / 1024, 3), 256>>>(Wq, Wk, Wv);

    dim3 gemm_grid(T * B / 128, H);             // 64 x 16
    qkv_fp16_kernel<<<gemm_grid, 512, G_SMEM>>>();

    dim3 attn_grid(T / BRA, H, B);              // 8 x 16 x 8
    flash_attn_mma_kernel<<<attn_grid, 256, ATT_SMEM>>>(out);
}

// round 16
// speedup vs baseline: 7.5289x; 1.0009x over previous
#include <cuda_runtime.h>
#include <cuda_bf16.h>
#include <cuda_fp16.h>
#include <math.h>
#include <stdint.h>

// Problem constants
#define B 8
#define T 1024
#define C 1024
#define H 16
#define D 64

// Scratch: Q pre-scaled fp16; K/V fp16; x fp16; W fp16
__device__ __half g_qf[(size_t)B * H * T * D];
__device__ __half g_kf[(size_t)B * H * T * D];
__device__ __half g_vf[(size_t)B * H * T * D];
__device__ __half g_xf[(size_t)B * T * C];
__device__ __half g_wh[(size_t)3 * H * C * D];

// ===========================================================================
// Helpers
// ===========================================================================
__device__ __forceinline__ uint32_t smem_u32(const void* p) {
    uint32_t a;
    asm("{ .reg .u64 t; cvta.to.shared.u64 t, %1; cvt.u32.u64 %0, t; }"
        : "=r"(a) : "l"(p));
    return a;
}

#define LDMX4(r0, r1, r2, r3, addr)                                           \
    asm volatile("ldmatrix.sync.aligned.m8n8.x4.shared.b16 {%0,%1,%2,%3}, [%4];" \
                 : "=r"(r0), "=r"(r1), "=r"(r2), "=r"(r3) : "r"(addr))

#define LDMX4T(r0, r1, r2, r3, addr)                                          \
    asm volatile("ldmatrix.sync.aligned.m8n8.x4.trans.shared.b16 {%0,%1,%2,%3}, [%4];" \
                 : "=r"(r0), "=r"(r1), "=r"(r2), "=r"(r3) : "r"(addr))

#define MMA_F16(c, a0, a1, a2, a3, b0, b1)                                    \
    asm volatile("mma.sync.aligned.m16n8k16.row.col.f32.f16.f16.f32 "         \
                 "{%0,%1,%2,%3}, {%4,%5,%6,%7}, {%8,%9}, {%0,%1,%2,%3};"      \
                 : "+f"((c)[0]), "+f"((c)[1]), "+f"((c)[2]), "+f"((c)[3])     \
                 : "r"(a0), "r"(a1), "r"(a2), "r"(a3), "r"(b0), "r"(b1))

#define CPA16(dst, src) \
    asm volatile("cp.async.cg.shared.global [%0], [%1], 16;" :: "r"(dst), "l"(src))
#define CPC()  asm volatile("cp.async.commit_group;" ::: "memory")
#define CPW0() asm volatile("cp.async.wait_group 0;" ::: "memory")
#define CPW1() asm volatile("cp.async.wait_group 1;" ::: "memory")

__device__ __forceinline__ uint32_t pack_h2(__half a, __half b) {
    __half2 h = __halves2half2(a, b);
    return *(uint32_t*)&h;
}

// ===========================================================================
// Kernel 0: convert x and W to fp16 (single rounding), one launch.
// Blocks [0, XB): x. Blocks [XB, XB + 3*WB): Wq/Wk/Wv.
// ===========================================================================
#define XB ((B * T * C) / 1024)            // 8192
#define WB ((H * C * D) / 1024)            // 1024

__global__ __launch_bounds__(256) void conv_all_kernel(const float* __restrict__ x,
                                                       const float* __restrict__ Wq,
                                                       const float* __restrict__ Wk,
                                                       const float* __restrict__ Wv)
{
    int blk = blockIdx.x;
    if (blk < XB) {
        size_t i = ((size_t)blk * 256 + threadIdx.x) * 4;
        float4 v = *(const float4*)(x + i);
        *(uint2*)(g_xf + i) = make_uint2(
            pack_h2(__float2half_rn(v.x), __float2half_rn(v.y)),
            pack_h2(__float2half_rn(v.z), __float2half_rn(v.w)));
    } else {
        int wb  = blk - XB;
        int mat = wb / WB;
        int rem = wb - mat * WB;
        const float* W = (mat == 0) ? Wq : (mat == 1) ? Wk : Wv;
        size_t i = ((size_t)rem * 256 + threadIdx.x) * 4;
        float4 v = *(const float4*)(W + i);
        *(uint2*)(g_wh + (size_t)mat * H * C * D + i) = make_uint2(
            pack_h2(__float2half_rn(v.x), __float2half_rn(v.y)),
            pack_h2(__float2half_rn(v.z), __float2half_rn(v.w)));
    }
}

// ===========================================================================
// Kernel 1: QKV projections, fp16 x fp16, BK=64 (unchanged from R15).
// ===========================================================================
#define BK 64
#define NCHUNK (C / BK)                   // 16
#define ASTR 272
#define BSTR 400
#define GBUF (128 * ASTR + 64 * BSTR)     // 60416
#define GA(buf)  ((buf) * GBUF)
#define GB(buf)  ((buf) * GBUF + 128 * ASTR)
#define G_SMEM (3 * GBUF)                 // 181248

__global__ __launch_bounds__(512)
void qkv_fp16_kernel()
{
    extern __shared__ char sm[];
    const uint32_t sbase = smem_u32(sm);

    const int tid  = threadIdx.x;
    const int warp = tid >> 5;            // 0..15
    const int lane = tid & 31;
    const int wm   = warp >> 2;           // 0..3
    const int wn   = warp & 3;            // 0..3

    const int m0 = blockIdx.x * 128;
    const int h  = blockIdx.y;

    float acc[2][6][4];
    #pragma unroll
    for (int i = 0; i < 2; i++)
        #pragma unroll
        for (int j = 0; j < 6; j++)
            #pragma unroll
            for (int k = 0; k < 4; k++)
                acc[i][j][k] = 0.0f;

    auto load_chunk = [&](int ci) {
        const int buf = ci % 3;
        const int k0  = ci * BK;
        #pragma unroll
        for (int i = 0; i < 2; i++) {
            int idx = tid + i * 512;
            int r   = idx >> 3;
            int seg = idx & 7;
            CPA16(sbase + GA(buf) + r * ASTR + seg * 16,
                  g_xf + (size_t)(m0 + r) * C + k0 + seg * 8);
        }
        #pragma unroll
        for (int i = 0; i < 3; i++) {
            int idx = tid + i * 512;
            int k   = idx / 24;
            int rem = idx - k * 24;
            int mat = rem >> 3;
            int seg = rem & 7;
            CPA16(sbase + GB(buf) + k * BSTR + mat * 128 + seg * 16,
                  g_wh + ((size_t)(mat * H + h)) * C * D
                       + (size_t)(k0 + k) * D + seg * 8);
        }
    };

    load_chunk(0); CPC();
    load_chunk(1); CPC();

    for (int ci = 0; ci < NCHUNK; ci++) {
        const int buf = ci % 3;
        if (ci < NCHUNK - 1) { CPW1(); } else { CPW0(); }
        __syncthreads();

        if (ci + 2 < NCHUNK) { load_chunk(ci + 2); CPC(); }

        uint32_t ah[2][4][4];
        {
            const uint32_t ab = sbase + GA(buf);
            #pragma unroll
            for (int mf = 0; mf < 2; mf++) {
                #pragma unroll
                for (int ks = 0; ks < 4; ks++) {
                    int row = wm * 32 + mf * 16 + (lane & 15);
                    int col = ks * 32 + ((lane & 16) ? 16 : 0);
                    LDMX4(ah[mf][ks][0], ah[mf][ks][1], ah[mf][ks][2], ah[mf][ks][3],
                          ab + row * ASTR + col);
                }
            }
        }

        const uint32_t bb = sbase + GB(buf);
        #pragma unroll
        for (int ks = 0; ks < 4; ks++) {
            #pragma unroll
            for (int f = 0; f < 3; f++) {
                uint32_t b0, b1, b2, b3;
                int kk = ks * 16 + (lane & 15);
                int cb = (wn * 48 + f * 16 + ((lane & 16) ? 8 : 0)) * 2;
                LDMX4T(b0, b1, b2, b3, bb + kk * BSTR + cb);
                #pragma unroll
                for (int mf = 0; mf < 2; mf++) {
                    MMA_F16(acc[mf][f * 2],     ah[mf][ks][0], ah[mf][ks][1],
                            ah[mf][ks][2], ah[mf][ks][3], b0, b1);
                    MMA_F16(acc[mf][f * 2 + 1], ah[mf][ks][0], ah[mf][ks][1],
                            ah[mf][ks][2], ah[mf][ks][3], b2, b3);
                }
            }
        }
    }

    // ---- epilogue: all outputs single fp16; Q pre-scaled by D^-0.5 ----
    const int bb = m0 >> 10;
    #pragma unroll
    for (int mf = 0; mf < 2; mf++) {
        #pragma unroll
        for (int f8 = 0; f8 < 6; f8++) {
            int ng   = wn * 48 + f8 * 8;           // warp-uniform
            int mat  = ng >> 6;
            int coln = (ng & 63) + (lane & 3) * 2;
            int row  = wm * 32 + mf * 16 + (lane >> 2);
            int t    = (m0 + row) & 1023;
            size_t base = (((size_t)(bb * H + h) * T + t) * D) + coln;

            const float* c = acc[mf][f8];
            float s = (mat == 0) ? 0.125f : 1.0f;
            __half* g = (mat == 0) ? g_qf : (mat == 1) ? g_kf : g_vf;
            *(uint32_t*)(g + base) =
                pack_h2(__float2half_rn(c[0] * s), __float2half_rn(c[1] * s));
            *(uint32_t*)(g + base + 8 * D) =
                pack_h2(__float2half_rn(c[2] * s), __float2half_rn(c[3] * s));
        }
    }
}

// ===========================================================================
// Kernel 2: causal FlashAttention. Q fp16 in SMEM; S = Q K; O += P V.
// 2 CTAs/SM. Causal group-skip (bit-identical). NEW: 3-buffer K/V ring ->
// ONE __syncthreads per tile; longest-CTA-first (reversed qt mapping).
// ===========================================================================
#define BRA 128
#define BCA 64
#define AST 144
#define KVT (64 * AST)            // 9216
#define QF_OFF 0
#define KV_BASE 18432
#define KF_OFF(buf) (KV_BASE + (buf) * 2 * KVT)
#define VF_OFF(buf) (KV_BASE + (buf) * 2 * KVT + KVT)
#define ATT_SMEM (KV_BASE + 6 * KVT)   // 73728

__global__ __launch_bounds__(256, 2)
void flash_attn_mma_kernel(float* __restrict__ out)
{
    extern __shared__ char sm[];
    const uint32_t sbase = smem_u32(sm);

    const int tid  = threadIdx.x;
    const int warp = tid >> 5;
    const int lane = tid & 31;
    const int qt = (int)gridDim.x - 1 - (int)blockIdx.x;   // longest first
    const int h  = blockIdx.y;
    const int b  = blockIdx.z;
    const size_t head_base = ((size_t)(b * H + h) * T) * D;
    const int q0 = qt * BRA;

    // ---- Stage Q via cp.async (persistent in SMEM) ----
    {
        const __half* qp = g_qf + head_base + (size_t)q0 * D;
        #pragma unroll
        for (int it = 0; it < 4; it++) {
            int idx = tid + it * 256;
            int r   = idx >> 3;
            int seg = idx & 7;
            CPA16(sbase + QF_OFF + r * AST + seg * 16, qp + (size_t)r * D + seg * 8);
        }
        CPC();
    }

    auto load_tile = [&](int kt) {
        const int buf = kt % 3;
        const size_t tb = head_base + (size_t)kt * BCA * D;
        #pragma unroll
        for (int i = 0; i < 2; i++) {
            int idx = tid + i * 256;
            int r   = idx >> 3;
            int seg = idx & 7;
            uint32_t dofs = r * AST + seg * 16;
            size_t so = tb + (size_t)r * D + seg * 8;
            CPA16(sbase + KF_OFF(buf) + dofs, g_kf + so);
            CPA16(sbase + VF_OFF(buf) + dofs, g_vf + so);
        }
    };

    float o[8][4];
    #pragma unroll
    for (int nf = 0; nf < 8; nf++)
        #pragma unroll
        for (int e = 0; e < 4; e++) o[nf][e] = 0.0f;
    float m0 = -1e30f, m1 = -1e30f, l0 = 0.0f, l1 = 0.0f;

    const int ntiles = 2 * (qt + 1);
    const int rbase  = q0 + warp * 16 + (lane >> 2);
    const int glim   = 8 * qt + warp;      // allowed: 4*kt + kg <= glim

    load_tile(0); CPC();
    if (ntiles > 1) { load_tile(1); CPC(); }

    const int qrow = warp * 16 + (lane & 15);

    for (int kt = 0; kt < ntiles; kt++) {
        const int buf = kt % 3;
        if (kt + 1 < ntiles) { CPW1(); } else { CPW0(); }
        __syncthreads();

        // Prefetch kt+2 into buffer consumed at kt-1 (protected by the
        // barrier above) BEFORE compute, so loads overlap the tile math.
        if (kt + 2 < ntiles) { load_tile(kt + 2); CPC(); }

        // number of allowed 16-key groups in this tile (warp-uniform, 0..4)
        int ng = glim - 4 * kt + 1;
        if (ng > 4) ng = 4;

        float sc[8][4];
        #pragma unroll
        for (int nf = 0; nf < 8; nf++)
            #pragma unroll
            for (int e = 0; e < 4; e++) sc[nf][e] = 0.0f;

        if (ng > 0) {
            const uint32_t kfb = sbase + KF_OFF(buf);
            #pragma unroll
            for (int ks = 0; ks < 4; ks++) {
                uint32_t q0r, q1r, q2r, q3r;
                {
                    int col = ks * 32 + ((lane & 16) ? 16 : 0);
                    LDMX4(q0r, q1r, q2r, q3r, sbase + QF_OFF + qrow * AST + col);
                }
                #pragma unroll
                for (int kg = 0; kg < 4; kg++) {
                    if (kg < ng) {
                        uint32_t kb0, kb1, kb2, kb3;
                        int row = kg * 16 + (lane & 7) + ((lane & 16) ? 8 : 0);
                        int col = ks * 32 + ((lane & 8) ? 16 : 0);
                        LDMX4(kb0, kb1, kb2, kb3, kfb + row * AST + col);
                        MMA_F16(sc[kg * 2],     q0r, q1r, q2r, q3r, kb0, kb1);
                        MMA_F16(sc[kg * 2 + 1], q0r, q1r, q2r, q3r, kb2, kb3);
                    }
                }
            }

            // ---- causal mask (boundary group) ----
            if (kt * BCA + 63 > q0 + warp * 16) {
                #pragma unroll
                for (int nf = 0; nf < 8; nf++) {
                    int col = kt * BCA + nf * 8 + 2 * (lane & 3);
                    if (col     > rbase)     sc[nf][0] = -1e30f;
                    if (col + 1 > rbase)     sc[nf][1] = -1e30f;
                    if (col     > rbase + 8) sc[nf][2] = -1e30f;
                    if (col + 1 > rbase + 8) sc[nf][3] = -1e30f;
                }
            }

            // ---- online softmax (allowed groups only) ----
            float mt0 = -1e30f, mt1 = -1e30f;
            #pragma unroll
            for (int kg = 0; kg < 4; kg++) {
                if (kg < ng) {
                    #pragma unroll
                    for (int f = 0; f < 2; f++) {
                        mt0 = fmaxf(mt0, fmaxf(sc[kg * 2 + f][0], sc[kg * 2 + f][1]));
                        mt1 = fmaxf(mt1, fmaxf(sc[kg * 2 + f][2], sc[kg * 2 + f][3]));
                    }
                }
            }
            mt0 = fmaxf(mt0, __shfl_xor_sync(0xFFFFFFFFu, mt0, 1));
            mt0 = fmaxf(mt0, __shfl_xor_sync(0xFFFFFFFFu, mt0, 2));
            mt1 = fmaxf(mt1, __shfl_xor_sync(0xFFFFFFFFu, mt1, 1));
            mt1 = fmaxf(mt1, __shfl_xor_sync(0xFFFFFFFFu, mt1, 2));

            float mn0 = fmaxf(m0, mt0), mn1 = fmaxf(m1, mt1);
            float cr0 = __expf(m0 - mn0), cr1 = __expf(m1 - mn1);
            l0 *= cr0; l1 *= cr1;
            #pragma unroll
            for (int nf = 0; nf < 8; nf++) {
                o[nf][0] *= cr0; o[nf][1] *= cr0;
                o[nf][2] *= cr1; o[nf][3] *= cr1;
            }
            #pragma unroll
            for (int kg = 0; kg < 4; kg++) {
                if (kg < ng) {
                    #pragma unroll
                    for (int f = 0; f < 2; f++) {
                        float* s = sc[kg * 2 + f];
                        s[0] = __expf(s[0] - mn0);
                        s[1] = __expf(s[1] - mn0);
                        s[2] = __expf(s[2] - mn1);
                        s[3] = __expf(s[3] - mn1);
                        l0 += s[0] + s[1];
                        l1 += s[2] + s[3];
                    }
                }
            }
            m0 = mn0; m1 = mn1;

            // ---- O += P V (allowed key groups only; single fp16 P) ----
            const uint32_t vfb = sbase + VF_OFF(buf);
            #pragma unroll
            for (int ks = 0; ks < 4; ks++) {
                if (ks < ng) {
                    uint32_t ph[4];
                    ph[0] = pack_h2(__float2half_rn(sc[2 * ks][0]),     __float2half_rn(sc[2 * ks][1]));
                    ph[1] = pack_h2(__float2half_rn(sc[2 * ks][2]),     __float2half_rn(sc[2 * ks][3]));
                    ph[2] = pack_h2(__float2half_rn(sc[2 * ks + 1][0]), __float2half_rn(sc[2 * ks + 1][1]));
                    ph[3] = pack_h2(__float2half_rn(sc[2 * ks + 1][2]), __float2half_rn(sc[2 * ks + 1][3]));
                    #pragma unroll
                    for (int nf16 = 0; nf16 < 4; nf16++) {
                        uint32_t vb0, vb1, vb2, vb3;
                        int kk = ks * 16 + ((lane & 8) ? 8 : 0) + (lane & 7);
                        int cb = (nf16 * 16 + ((lane & 16) ? 8 : 0)) * 2;
                        LDMX4T(vb0, vb1, vb2, vb3, vfb + kk * AST + cb);
                        MMA_F16(o[nf16 * 2],     ph[0], ph[1], ph[2], ph[3], vb0, vb1);
                        MMA_F16(o[nf16 * 2 + 1], ph[0], ph[1], ph[2], ph[3], vb2, vb3);
                    }
                }
            }
        }
    }

    l0 += __shfl_xor_sync(0xFFFFFFFFu, l0, 1);
    l0 += __shfl_xor_sync(0xFFFFFFFFu, l0, 2);
    l1 += __shfl_xor_sync(0xFFFFFFFFu, l1, 1);
    l1 += __shfl_xor_sync(0xFFFFFFFFu, l1, 2);
    const float i0 = 1.0f / l0;
    const float i1 = 1.0f / l1;

    float* op = out + ((size_t)(b * T + rbase) * (H * D)) + h * D;
    #pragma unroll
    for (int nf = 0; nf < 8; nf++) {
        int col = nf * 8 + 2 * (lane & 3);
        *(float2*)(op + col) = make_float2(o[nf][0] * i0, o[nf][1] * i0);
        *(float2*)(op + (size_t)8 * (H * D) + col) = make_float2(o[nf][2] * i1, o[nf][3] * i1);
    }
}

// ===========================================================================
extern "C" void kernel_launch(void* const* d_in, const int* in_sizes, int n_in,
                              void* d_out, int out_size)
{
    const float* x  = (const float*)d_in[0];   // [B, T, C]
    const float* Wq = (const float*)d_in[1];   // [H, C, D]
    const float* Wk = (const float*)d_in[2];
    const float* Wv = (const float*)d_in[3];
    float* out = (float*)d_out;                 // [B, T, H*D]

    (void)in_sizes; (void)n_in; (void)out_size;

    static int smem_set = 0;
    if (!smem_set) {
        cudaFuncSetAttribute(qkv_fp16_kernel,
                             cudaFuncAttributeMaxDynamicSharedMemorySize, G_SMEM);
        cudaFuncSetAttribute(flash_attn_mma_kernel,
                             cudaFuncAttributeMaxDynamicSharedMemorySize, ATT_SMEM);
        smem_set = 1;
    }

    conv_all_kernel<<<XB + 3 * WB, 256>>>(x, Wq, Wk, Wv);

    dim3 gemm_grid(T * B / 128, H);             // 64 x 16
    qkv_fp16_kernel<<<gemm_grid, 512, G_SMEM>>>();

    dim3 attn_grid(T / BRA, H, B);              // 8 x 16 x 8
    flash_attn_mma_kernel<<<attn_grid, 256, ATT_SMEM>>>(out);
}

// round 17
// speedup vs baseline: 7.5898x; 1.0081x over previous
#include <cuda_runtime.h>
#include <cuda_bf16.h>
#include <cuda_fp16.h>
#include <math.h>
#include <stdint.h>

// Problem constants
#define B 8
#define T 1024
#define C 1024
#define H 16
#define D 64

// Scratch: Q pre-scaled fp16; K/V fp16; x fp16; W fp16
__device__ __half g_qf[(size_t)B * H * T * D];
__device__ __half g_kf[(size_t)B * H * T * D];
__device__ __half g_vf[(size_t)B * H * T * D];
__device__ __half g_xf[(size_t)B * T * C];
__device__ __half g_wh[(size_t)3 * H * C * D];

// ===========================================================================
// Helpers
// ===========================================================================
__device__ __forceinline__ uint32_t smem_u32(const void* p) {
    uint32_t a;
    asm("{ .reg .u64 t; cvta.to.shared.u64 t, %1; cvt.u32.u64 %0, t; }"
        : "=r"(a) : "l"(p));
    return a;
}

#define LDMX4(r0, r1, r2, r3, addr)                                           \
    asm volatile("ldmatrix.sync.aligned.m8n8.x4.shared.b16 {%0,%1,%2,%3}, [%4];" \
                 : "=r"(r0), "=r"(r1), "=r"(r2), "=r"(r3) : "r"(addr))

#define LDMX4T(r0, r1, r2, r3, addr)                                          \
    asm volatile("ldmatrix.sync.aligned.m8n8.x4.trans.shared.b16 {%0,%1,%2,%3}, [%4];" \
                 : "=r"(r0), "=r"(r1), "=r"(r2), "=r"(r3) : "r"(addr))

#define MMA_F16(c, a0, a1, a2, a3, b0, b1)                                    \
    asm volatile("mma.sync.aligned.m16n8k16.row.col.f32.f16.f16.f32 "         \
                 "{%0,%1,%2,%3}, {%4,%5,%6,%7}, {%8,%9}, {%0,%1,%2,%3};"      \
                 : "+f"((c)[0]), "+f"((c)[1]), "+f"((c)[2]), "+f"((c)[3])     \
                 : "r"(a0), "r"(a1), "r"(a2), "r"(a3), "r"(b0), "r"(b1))

#define CPA16(dst, src) \
    asm volatile("cp.async.cg.shared.global [%0], [%1], 16;" :: "r"(dst), "l"(src))
#define CPC()  asm volatile("cp.async.commit_group;" ::: "memory")
#define CPW0() asm volatile("cp.async.wait_group 0;" ::: "memory")
#define CPW1() asm volatile("cp.async.wait_group 1;" ::: "memory")

__device__ __forceinline__ uint32_t pack_h2(__half a, __half b) {
    __half2 h = __halves2half2(a, b);
    return *(uint32_t*)&h;
}

__device__ __forceinline__ uint2 cvt4(float4 v) {
    return make_uint2(
        pack_h2(__float2half_rn(v.x), __float2half_rn(v.y)),
        pack_h2(__float2half_rn(v.z), __float2half_rn(v.w)));
}

// ===========================================================================
// Kernel 0: convert x and W to fp16, one launch, 4 independent float4s per
// thread (MLP=4 to hide DRAM latency; the R16 version was MLP=1 and
// latency-bound at 47% DRAM).
// Blocks [0, XB4): x (each covers 1024 float4). [XB4, XB4+3*WB4): Wq/Wk/Wv.
// ===========================================================================
#define XB4 ((B * T * C) / 4096)           // 2048
#define WB4 ((H * C * D) / 4096)           // 256

__global__ __launch_bounds__(256) void conv_all_kernel(const float* __restrict__ x,
                                                       const float* __restrict__ Wq,
                                                       const float* __restrict__ Wk,
                                                       const float* __restrict__ Wv)
{
    int blk = blockIdx.x;
    const float* src;
    __half* dst;
    size_t base;
    if (blk < XB4) {
        src = x; dst = g_xf;
        base = (size_t)blk * 4096;
    } else {
        int wb  = blk - XB4;
        int mat = wb / WB4;
        int rem = wb - mat * WB4;
        src = (mat == 0) ? Wq : (mat == 1) ? Wk : Wv;
        dst = g_wh + (size_t)mat * H * C * D;
        base = (size_t)rem * 4096;
    }
    size_t i0 = base + (size_t)threadIdx.x * 4;
    float4 v0 = *(const float4*)(src + i0);
    float4 v1 = *(const float4*)(src + i0 + 1024);
    float4 v2 = *(const float4*)(src + i0 + 2048);
    float4 v3 = *(const float4*)(src + i0 + 3072);
    *(uint2*)(dst + i0)        = cvt4(v0);
    *(uint2*)(dst + i0 + 1024) = cvt4(v1);
    *(uint2*)(dst + i0 + 2048) = cvt4(v2);
    *(uint2*)(dst + i0 + 3072) = cvt4(v3);
}

// ===========================================================================
// Kernel 1: QKV projections, fp16 x fp16, BK=64 (unchanged — bit-identical).
// ===========================================================================
#define BK 64
#define NCHUNK (C / BK)                   // 16
#define ASTR 272
#define BSTR 400
#define GBUF (128 * ASTR + 64 * BSTR)     // 60416
#define GA(buf)  ((buf) * GBUF)
#define GB(buf)  ((buf) * GBUF + 128 * ASTR)
#define G_SMEM (3 * GBUF)                 // 181248

__global__ __launch_bounds__(512)
void qkv_fp16_kernel()
{
    extern __shared__ char sm[];
    const uint32_t sbase = smem_u32(sm);

    const int tid  = threadIdx.x;
    const int warp = tid >> 5;            // 0..15
    const int lane = tid & 31;
    const int wm   = warp >> 2;           // 0..3
    const int wn   = warp & 3;            // 0..3

    const int m0 = blockIdx.x * 128;
    const int h  = blockIdx.y;

    float acc[2][6][4];
    #pragma unroll
    for (int i = 0; i < 2; i++)
        #pragma unroll
        for (int j = 0; j < 6; j++)
            #pragma unroll
            for (int k = 0; k < 4; k++)
                acc[i][j][k] = 0.0f;

    auto load_chunk = [&](int ci) {
        const int buf = ci % 3;
        const int k0  = ci * BK;
        #pragma unroll
        for (int i = 0; i < 2; i++) {
            int idx = tid + i * 512;
            int r   = idx >> 3;
            int seg = idx & 7;
            CPA16(sbase + GA(buf) + r * ASTR + seg * 16,
                  g_xf + (size_t)(m0 + r) * C + k0 + seg * 8);
        }
        #pragma unroll
        for (int i = 0; i < 3; i++) {
            int idx = tid + i * 512;
            int k   = idx / 24;
            int rem = idx - k * 24;
            int mat = rem >> 3;
            int seg = rem & 7;
            CPA16(sbase + GB(buf) + k * BSTR + mat * 128 + seg * 16,
                  g_wh + ((size_t)(mat * H + h)) * C * D
                       + (size_t)(k0 + k) * D + seg * 8);
        }
    };

    load_chunk(0); CPC();
    load_chunk(1); CPC();

    for (int ci = 0; ci < NCHUNK; ci++) {
        const int buf = ci % 3;
        if (ci < NCHUNK - 1) { CPW1(); } else { CPW0(); }
        __syncthreads();

        if (ci + 2 < NCHUNK) { load_chunk(ci + 2); CPC(); }

        uint32_t ah[2][4][4];
        {
            const uint32_t ab = sbase + GA(buf);
            #pragma unroll
            for (int mf = 0; mf < 2; mf++) {
                #pragma unroll
                for (int ks = 0; ks < 4; ks++) {
                    int row = wm * 32 + mf * 16 + (lane & 15);
                    int col = ks * 32 + ((lane & 16) ? 16 : 0);
                    LDMX4(ah[mf][ks][0], ah[mf][ks][1], ah[mf][ks][2], ah[mf][ks][3],
                          ab + row * ASTR + col);
                }
            }
        }

        const uint32_t bb = sbase + GB(buf);
        #pragma unroll
        for (int ks = 0; ks < 4; ks++) {
            #pragma unroll
            for (int f = 0; f < 3; f++) {
                uint32_t b0, b1, b2, b3;
                int kk = ks * 16 + (lane & 15);
                int cb = (wn * 48 + f * 16 + ((lane & 16) ? 8 : 0)) * 2;
                LDMX4T(b0, b1, b2, b3, bb + kk * BSTR + cb);
                #pragma unroll
                for (int mf = 0; mf < 2; mf++) {
                    MMA_F16(acc[mf][f * 2],     ah[mf][ks][0], ah[mf][ks][1],
                            ah[mf][ks][2], ah[mf][ks][3], b0, b1);
                    MMA_F16(acc[mf][f * 2 + 1], ah[mf][ks][0], ah[mf][ks][1],
                            ah[mf][ks][2], ah[mf][ks][3], b2, b3);
                }
            }
        }
    }

    // ---- epilogue: all outputs single fp16; Q pre-scaled by D^-0.5 ----
    const int bb = m0 >> 10;
    #pragma unroll
    for (int mf = 0; mf < 2; mf++) {
        #pragma unroll
        for (int f8 = 0; f8 < 6; f8++) {
            int ng   = wn * 48 + f8 * 8;           // warp-uniform
            int mat  = ng >> 6;
            int coln = (ng & 63) + (lane & 3) * 2;
            int row  = wm * 32 + mf * 16 + (lane >> 2);
            int t    = (m0 + row) & 1023;
            size_t base = (((size_t)(bb * H + h) * T + t) * D) + coln;

            const float* c = acc[mf][f8];
            float s = (mat == 0) ? 0.125f : 1.0f;
            __half* g = (mat == 0) ? g_qf : (mat == 1) ? g_kf : g_vf;
            *(uint32_t*)(g + base) =
                pack_h2(__float2half_rn(c[0] * s), __float2half_rn(c[1] * s));
            *(uint32_t*)(g + base + 8 * D) =
                pack_h2(__float2half_rn(c[2] * s), __float2half_rn(c[3] * s));
        }
    }
}

// ===========================================================================
// Kernel 2: causal FlashAttention (bit-identical math to R15/R16).
// Q fp16 in SMEM; S = Q K; O += P V. 2 CTAs/SM. Causal group-skip.
// 3-buffer K/V ring, one barrier per tile. Q stage merged with tile-0 group.
// ===========================================================================
#define BRA 128
#define BCA 64
#define AST 144
#define KVT (64 * AST)            // 9216
#define QF_OFF 0
#define KV_BASE 18432
#define KF_OFF(buf) (KV_BASE + (buf) * 2 * KVT)
#define VF_OFF(buf) (KV_BASE + (buf) * 2 * KVT + KVT)
#define ATT_SMEM (KV_BASE + 6 * KVT)   // 73728

__global__ __launch_bounds__(256, 2)
void flash_attn_mma_kernel(float* __restrict__ out)
{
    extern __shared__ char sm[];
    const uint32_t sbase = smem_u32(sm);

    const int tid  = threadIdx.x;
    const int warp = tid >> 5;
    const int lane = tid & 31;
    const int qt = (int)gridDim.x - 1 - (int)blockIdx.x;   // longest first
    const int h  = blockIdx.y;
    const int b  = blockIdx.z;
    const size_t head_base = ((size_t)(b * H + h) * T) * D;
    const int q0 = qt * BRA;

    auto load_tile = [&](int kt) {
        const int buf = kt % 3;
        const size_t tb = head_base + (size_t)kt * BCA * D;
        #pragma unroll
        for (int i = 0; i < 2; i++) {
            int idx = tid + i * 256;
            int r   = idx >> 3;
            int seg = idx & 7;
            uint32_t dofs = r * AST + seg * 16;
            size_t so = tb + (size_t)r * D + seg * 8;
            CPA16(sbase + KF_OFF(buf) + dofs, g_kf + so);
            CPA16(sbase + VF_OFF(buf) + dofs, g_vf + so);
        }
    };

    // ---- Stage Q (merged into tile-0's commit group) ----
    {
        const __half* qp = g_qf + head_base + (size_t)q0 * D;
        #pragma unroll
        for (int it = 0; it < 4; it++) {
            int idx = tid + it * 256;
            int r   = idx >> 3;
            int seg = idx & 7;
            CPA16(sbase + QF_OFF + r * AST + seg * 16, qp + (size_t)r * D + seg * 8);
        }
    }
    load_tile(0); CPC();
    load_tile(1); CPC();

    float o[8][4];
    #pragma unroll
    for (int nf = 0; nf < 8; nf++)
        #pragma unroll
        for (int e = 0; e < 4; e++) o[nf][e] = 0.0f;
    float m0 = -1e30f, m1 = -1e30f, l0 = 0.0f, l1 = 0.0f;

    const int ntiles = 2 * (qt + 1);
    const int rbase  = q0 + warp * 16 + (lane >> 2);
    const int glim   = 8 * qt + warp;      // allowed: 4*kt + kg <= glim
    const int qrow   = warp * 16 + (lane & 15);

    for (int kt = 0; kt < ntiles; kt++) {
        const int buf = kt % 3;
        if (kt + 1 < ntiles) { CPW1(); } else { CPW0(); }
        __syncthreads();

        if (kt + 2 < ntiles) { load_tile(kt + 2); CPC(); }

        int ng = glim - 4 * kt + 1;
        if (ng > 4) ng = 4;

        float sc[8][4];
        #pragma unroll
        for (int nf = 0; nf < 8; nf++)
            #pragma unroll
            for (int e = 0; e < 4; e++) sc[nf][e] = 0.0f;

        if (ng > 0) {
            const uint32_t kfb = sbase + KF_OFF(buf);
            #pragma unroll
            for (int ks = 0; ks < 4; ks++) {
                uint32_t q0r, q1r, q2r, q3r;
                {
                    int col = ks * 32 + ((lane & 16) ? 16 : 0);
                    LDMX4(q0r, q1r, q2r, q3r, sbase + QF_OFF + qrow * AST + col);
                }
                #pragma unroll
                for (int kg = 0; kg < 4; kg++) {
                    if (kg < ng) {
                        uint32_t kb0, kb1, kb2, kb3;
                        int row = kg * 16 + (lane & 7) + ((lane & 16) ? 8 : 0);
                        int col = ks * 32 + ((lane & 8) ? 16 : 0);
                        LDMX4(kb0, kb1, kb2, kb3, kfb + row * AST + col);
                        MMA_F16(sc[kg * 2],     q0r, q1r, q2r, q3r, kb0, kb1);
                        MMA_F16(sc[kg * 2 + 1], q0r, q1r, q2r, q3r, kb2, kb3);
                    }
                }
            }

            if (kt * BCA + 63 > q0 + warp * 16) {
                #pragma unroll
                for (int nf = 0; nf < 8; nf++) {
                    int col = kt * BCA + nf * 8 + 2 * (lane & 3);
                    if (col     > rbase)     sc[nf][0] = -1e30f;
                    if (col + 1 > rbase)     sc[nf][1] = -1e30f;
                    if (col     > rbase + 8) sc[nf][2] = -1e30f;
                    if (col + 1 > rbase + 8) sc[nf][3] = -1e30f;
                }
            }

            float mt0 = -1e30f, mt1 = -1e30f;
            #pragma unroll
            for (int kg = 0; kg < 4; kg++) {
                if (kg < ng) {
                    #pragma unroll
                    for (int f = 0; f < 2; f++) {
                        mt0 = fmaxf(mt0, fmaxf(sc[kg * 2 + f][0], sc[kg * 2 + f][1]));
                        mt1 = fmaxf(mt1, fmaxf(sc[kg * 2 + f][2], sc[kg * 2 + f][3]));
                    }
                }
            }
            mt0 = fmaxf(mt0, __shfl_xor_sync(0xFFFFFFFFu, mt0, 1));
            mt0 = fmaxf(mt0, __shfl_xor_sync(0xFFFFFFFFu, mt0, 2));
            mt1 = fmaxf(mt1, __shfl_xor_sync(0xFFFFFFFFu, mt1, 1));
            mt1 = fmaxf(mt1, __shfl_xor_sync(0xFFFFFFFFu, mt1, 2));

            float mn0 = fmaxf(m0, mt0), mn1 = fmaxf(m1, mt1);
            float cr0 = __expf(m0 - mn0), cr1 = __expf(m1 - mn1);
            l0 *= cr0; l1 *= cr1;
            #pragma unroll
            for (int nf = 0; nf < 8; nf++) {
                o[nf][0] *= cr0; o[nf][1] *= cr0;
                o[nf][2] *= cr1; o[nf][3] *= cr1;
            }
            #pragma unroll
            for (int kg = 0; kg < 4; kg++) {
                if (kg < ng) {
                    #pragma unroll
                    for (int f = 0; f < 2; f++) {
                        float* s = sc[kg * 2 + f];
                        s[0] = __expf(s[0] - mn0);
                        s[1] = __expf(s[1] - mn0);
                        s[2] = __expf(s[2] - mn1);
                        s[3] = __expf(s[3] - mn1);
                        l0 += s[0] + s[1];
                        l1 += s[2] + s[3];
                    }
                }
            }
            m0 = mn0; m1 = mn1;

            const uint32_t vfb = sbase + VF_OFF(buf);
            #pragma unroll
            for (int ks = 0; ks < 4; ks++) {
                if (ks < ng) {
                    uint32_t ph[4];
                    ph[0] = pack_h2(__float2half_rn(sc[2 * ks][0]),     __float2half_rn(sc[2 * ks][1]));
                    ph[1] = pack_h2(__float2half_rn(sc[2 * ks][2]),     __float2half_rn(sc[2 * ks][3]));
                    ph[2] = pack_h2(__float2half_rn(sc[2 * ks + 1][0]), __float2half_rn(sc[2 * ks + 1][1]));
                    ph[3] = pack_h2(__float2half_rn(sc[2 * ks + 1][2]), __float2half_rn(sc[2 * ks + 1][3]));
                    #pragma unroll
                    for (int nf16 = 0; nf16 < 4; nf16++) {
                        uint32_t vb0, vb1, vb2, vb3;
                        int kk = ks * 16 + ((lane & 8) ? 8 : 0) + (lane & 7);
                        int cb = (nf16 * 16 + ((lane & 16) ? 8 : 0)) * 2;
                        LDMX4T(vb0, vb1, vb2, vb3, vfb + kk * AST + cb);
                        MMA_F16(o[nf16 * 2],     ph[0], ph[1], ph[2], ph[3], vb0, vb1);
                        MMA_F16(o[nf16 * 2 + 1], ph[0], ph[1], ph[2], ph[3], vb2, vb3);
                    }
                }
            }
        }
    }

    l0 += __shfl_xor_sync(0xFFFFFFFFu, l0, 1);
    l0 += __shfl_xor_sync(0xFFFFFFFFu, l0, 2);
    l1 += __shfl_xor_sync(0xFFFFFFFFu, l1, 1);
    l1 += __shfl_xor_sync(0xFFFFFFFFu, l1, 2);
    const float i0 = 1.0f / l0;
    const float i1 = 1.0f / l1;

    float* op = out + ((size_t)(b * T + rbase) * (H * D)) + h * D;
    #pragma unroll
    for (int nf = 0; nf < 8; nf++) {
        int col = nf * 8 + 2 * (lane & 3);
        *(float2*)(op + col) = make_float2(o[nf][0] * i0, o[nf][1] * i0);
        *(float2*)(op + (size_t)8 * (H * D) + col) = make_float2(o[nf][2] * i1, o[nf][3] * i1);
    }
}

// ===========================================================================
extern "C" void kernel_launch(void* const* d_in, const int* in_sizes, int n_in,
                              void* d_out, int out_size)
{
    const float* x  = (const float*)d_in[0];   // [B, T, C]
    const float* Wq = (const float*)d_in[1];   // [H, C, D]
    const float* Wk = (const float*)d_in[2];
    const float* Wv = (const float*)d_in[3];
    float* out = (float*)d_out;                 // [B, T, H*D]

    (void)in_sizes; (void)n_in; (void)out_size;

    static int smem_set = 0;
    if (!smem_set) {
        cudaFuncSetAttribute(qkv_fp16_kernel,
                             cudaFuncAttributeMaxDynamicSharedMemorySize, G_SMEM);
        cudaFuncSetAttribute(flash_attn_mma_kernel,
                             cudaFuncAttributeMaxDynamicSharedMemorySize, ATT_SMEM);
        smem_set = 1;
    }

    conv_all_kernel<<<XB4 + 3 * WB4, 256>>>(x, Wq, Wk, Wv);

    dim3 gemm_grid(T * B / 128, H);             // 64 x 16
    qkv_fp16_kernel<<<gemm_grid, 512, G_SMEM>>>();

    dim3 attn_grid(T / BRA, H, B);              // 8 x 16 x 8
    flash_attn_mma_kernel<<<attn_grid, 256, ATT_SMEM>>>(out);
}